// round 7
// baseline (speedup 1.0000x reference)
#include <cuda_runtime.h>

// Problem constants (fixed: N=2048, B=2)
#define NN   2048
#define BB   2
#define EW   (NN + 1)            // 2049  (== 1 mod 4)
#define HXH  (NN - 1)            // 2047
#define HXW  (NN)                // 2048  (== 0 mod 4)
#define HYH  (NN)                // 2048
#define HYW  (NN - 1)            // 2047  (== 3 mod 4)
#define EN   (EW * EW)
#define HXN  (HXH * HXW)
#define HYN  (HYH * HYW)
#define CFLF 0.35f

#define KF0 (-11.0f / 6.0f)
#define KF1 (3.0f)
#define KF2 (-1.5f)
#define KF3 (1.0f / 3.0f)
#define KB0 (-1.0f / 3.0f)
#define KB1 (1.5f)
#define KB2 (-3.0f)
#define KB3 (11.0f / 6.0f)

struct MCoef {
    float M00, M01, M02, M03, M11, M20, M21, M22, M23;
};

__device__ __forceinline__ MCoef make_M(const float* sb, const float* sd, const float* sg) {
    float beta = *sb, delta = *sd, gamma = *sg;
    MCoef m;
    m.M00 = -0.25f * beta + 0.1f * gamma;
    m.M01 =  0.25f * beta + delta - 0.5f - 0.1f * gamma;
    m.M02 =  0.25f * beta - 0.1f * gamma;
    m.M03 = -0.25f * beta + 0.1f * gamma;
    m.M11 = -2.0f * delta;
    m.M20 =  0.25f * beta - 0.1f * gamma;
    m.M21 = -0.25f * beta + delta + 0.5f + 0.1f * gamma;
    m.M22 = -0.25f * beta - 0.1f * gamma;
    m.M23 =  0.25f * beta + 0.1f * gamma;
    return m;
}

// ---------------------------------------------------------------------------
// Warp-coalesced store of a 128-float row segment (4 floats/lane, stride 4).
// gi & 3 warp-uniform; whole warp participates.
// ---------------------------------------------------------------------------
__device__ __forceinline__ void warp_store128(float* __restrict__ out, int gi,
                                              float v0, float v1, float v2, float v3)
{
    const unsigned FULL = 0xffffffffu;
    const int lane = threadIdx.x & 31;
    const int s = gi & 3;
    if (s == 0) {
        float4 w; w.x = v0; w.y = v1; w.z = v2; w.w = v3;
        *reinterpret_cast<float4*>(out + gi) = w;
        return;
    }
    float n0 = __shfl_down_sync(FULL, v0, 1);
    float n1 = __shfl_down_sync(FULL, v1, 1);
    float n2 = __shfl_down_sync(FULL, v2, 1);
    if (s == 1) {
        if (lane < 31) {
            float4 w; w.x = v3; w.y = n0; w.z = n1; w.w = n2;
            *reinterpret_cast<float4*>(out + gi + 3) = w;
        }
        if (lane == 0)  { out[gi] = v0; out[gi + 1] = v1; out[gi + 2] = v2; }
        else if (lane == 31) { out[gi + 3] = v3; }
    } else if (s == 2) {
        if (lane < 31) {
            float4 w; w.x = v2; w.y = v3; w.z = n0; w.w = n1;
            *reinterpret_cast<float4*>(out + gi + 2) = w;
        }
        if (lane == 0)  { out[gi] = v0; out[gi + 1] = v1; }
        else if (lane == 31) { out[gi + 2] = v2; out[gi + 3] = v3; }
    } else {
        if (lane < 31) {
            float4 w; w.x = v1; w.y = v2; w.z = v3; w.w = n0;
            *reinterpret_cast<float4*>(out + gi + 1) = w;
        }
        if (lane == 0)  { out[gi] = v0; }
        else if (lane == 31) { out[gi + 1] = v1; out[gi + 2] = v2; out[gi + 3] = v3; }
    }
}

// ---------------------------------------------------------------------------
// Compile-time-skew window load: out[t] = buf[idx+t], requires (idx&3)==K.
// ---------------------------------------------------------------------------
template<int W, int K>
__device__ __forceinline__ void load_win_k(const float* __restrict__ buf, int idx,
                                           float* __restrict__ out)
{
    constexpr int NV = (W + K + 3) / 4;
    const float4* p = reinterpret_cast<const float4*>(buf + (idx - K));
    float f[NV * 4];
    #pragma unroll
    for (int t = 0; t < NV; t++)
        *reinterpret_cast<float4*>(f + 4 * t) = p[t];
    #pragma unroll
    for (int t = 0; t < W; t++) out[t] = f[t + K];
}

// ---------------------------------------------------------------------------
// Generic (boundary) amper point.
// ---------------------------------------------------------------------------
__device__ float amper_point(const float* __restrict__ Hxb,
                             const float* __restrict__ Hyb,
                             int i, int j, const MCoef& m)
{
    float s1 = 0.0f, s2 = 0.0f;
    bool irow = (i >= 2 && i <= NN - 2);
    bool jcol = (j >= 2 && j <= NN - 2);

#define HYv(r, c) Hyb[(r) * HYW + (c)]
#define HXv(r, c) Hxb[(r) * HXW + (c)]
    if (irow && jcol) {
        s1 += m.M00 * HYv(i - 2, j - 2) + m.M20 * HYv(i - 2, j);
        s1 += m.M01 * HYv(i - 1, j - 2) + m.M11 * HYv(i - 1, j - 1) + m.M21 * HYv(i - 1, j);
        s1 += m.M02 * HYv(i,     j - 2) + m.M22 * HYv(i,     j);
        s1 += m.M03 * HYv(i + 1, j - 2) + m.M23 * HYv(i + 1, j);
        s2 += m.M00 * HXv(i - 2, j - 2) + m.M01 * HXv(i - 2, j - 1)
            + m.M02 * HXv(i - 2, j)     + m.M03 * HXv(i - 2, j + 1);
        s2 += m.M11 * HXv(i - 1, j - 1);
        s2 += m.M20 * HXv(i,     j - 2) + m.M21 * HXv(i,     j - 1)
            + m.M22 * HXv(i,     j)     + m.M23 * HXv(i,     j + 1);
    }
    if (i >= 1 && j <= NN - 5) {
        s1 += KF0 * HYv(i - 1, j)     + KF1 * HYv(i - 1, j + 1)
            + KF2 * HYv(i - 1, j + 2) + KF3 * HYv(i - 1, j + 3);
    }
    if (i <= NN - 1 && j >= 5) {
        s1 += KB0 * HYv(i, j - 5) + KB1 * HYv(i, j - 4)
            + KB2 * HYv(i, j - 3) + KB3 * HYv(i, j - 2);
    }
    if (irow && j >= 1 && j <= 2) {
        s1 += -HYv(i - 1, j - 1) + 3.0f * HYv(i - 1, j)
              - 3.0f * HYv(i - 1, j + 1) + HYv(i - 1, j + 2);
    }
    if (irow && j >= NN - 2 && j <= NN - 1) {
        s1 += HYv(i, j - 4) - 3.0f * HYv(i, j - 3)
            + 3.0f * HYv(i, j - 2) - HYv(i, j - 1);
    }
    if (j >= 1 && i <= NN - 5) {
        s2 += KF0 * HXv(i, j - 1)     + KF1 * HXv(i + 1, j - 1)
            + KF2 * HXv(i + 2, j - 1) + KF3 * HXv(i + 3, j - 1);
    }
    if (j <= NN - 1 && i >= 5) {
        s2 += KB0 * HXv(i - 5, j) + KB1 * HXv(i - 4, j)
            + KB2 * HXv(i - 3, j) + KB3 * HXv(i - 2, j);
    }
    if (jcol && i >= 1 && i <= 2) {
        s2 += -HXv(i - 1, j - 1) + 3.0f * HXv(i, j - 1)
              - 3.0f * HXv(i + 1, j - 1) + HXv(i + 2, j - 1);
    }
    if (jcol && i >= NN - 2 && i <= NN - 1) {
        s2 += HXv(i - 4, j) - 3.0f * HXv(i - 3, j)
            + 3.0f * HXv(i - 2, j) - HXv(i - 1, j);
    }
#undef HYv
#undef HXv
    return s1 - s2;
}

// ---------------------------------------------------------------------------
// Amper role helpers: P[d] = value at column j+d (callers pass shifted ptr).
// ---------------------------------------------------------------------------
__device__ __forceinline__ void a_im2(const float* P, float* s1, const MCoef& m) {
    #pragma unroll
    for (int q = 0; q < 4; q++) s1[q] += m.M00 * P[q - 2] + m.M20 * P[q];
}
__device__ __forceinline__ void a_im1(const float* P, float* s1, const MCoef& m, float cM21KF0) {
    #pragma unroll
    for (int q = 0; q < 4; q++)
        s1[q] += m.M01 * P[q - 2] + m.M11 * P[q - 1] + cM21KF0 * P[q]
               + KF1 * P[q + 1] + KF2 * P[q + 2] + KF3 * P[q + 3];
}
__device__ __forceinline__ void a_i0(const float* P, float* s1, const MCoef& m, float cM02KB3) {
    #pragma unroll
    for (int q = 0; q < 4; q++)
        s1[q] += KB0 * P[q - 5] + KB1 * P[q - 4] + KB2 * P[q - 3]
               + cM02KB3 * P[q - 2] + m.M22 * P[q];
}
__device__ __forceinline__ void a_ip1(const float* P, float* s1, const MCoef& m) {
    #pragma unroll
    for (int q = 0; q < 4; q++) s1[q] += m.M03 * P[q - 2] + m.M23 * P[q];
}
__device__ __forceinline__ void x_kb(const float* P, float* s2, float c) {
    #pragma unroll
    for (int q = 0; q < 4; q++) s2[q] += c * P[q];
}
__device__ __forceinline__ void x_m2(const float* P, float* s2, const MCoef& m, float cM02KB3) {
    #pragma unroll
    for (int q = 0; q < 4; q++)
        s2[q] += m.M00 * P[q - 2] + m.M01 * P[q - 1] + cM02KB3 * P[q] + m.M03 * P[q + 1];
}
__device__ __forceinline__ void x_m1(const float* P, float* s2, const MCoef& m) {
    #pragma unroll
    for (int q = 0; q < 4; q++) s2[q] += m.M11 * P[q - 1];
}
__device__ __forceinline__ void x_00(const float* P, float* s2, const MCoef& m, float cM21KF0) {
    #pragma unroll
    for (int q = 0; q < 4; q++)
        s2[q] += m.M20 * P[q - 2] + cM21KF0 * P[q - 1] + m.M22 * P[q] + m.M23 * P[q + 1];
}
__device__ __forceinline__ void x_kf(const float* P, float* s2, float c) {
    #pragma unroll
    for (int q = 0; q < 4; q++) s2[q] += c * P[q - 1];
}

// ---------------------------------------------------------------------------
// Amper Hy section, 4 output rows. KY = skew of (row i0-2, col j) index.
// Window k = Hy row i0-2+k; role delta = k-2-r.
// ---------------------------------------------------------------------------
template<int KY>
__device__ __forceinline__ void amper_hy4(const float* __restrict__ hy, int base,
                                          const MCoef& m, float cM21KF0, float cM02KB3,
                                          float s1[4][4])
{
    { float W[6];  load_win_k<6,  (KY + 2) & 3>(hy, base - 2, W);                 // k=0 @ j-2
      a_im2(W + 2, s1[0], m); }
    { float W[9];  load_win_k<9,  (KY + 1) & 3>(hy, base + HYW - 2, W);           // k=1 @ j-2
      a_im1(W + 2, s1[0], m, cM21KF0);
      a_im2(W + 2, s1[1], m); }
    { float W[12]; load_win_k<12, (KY + 1) & 3>(hy, base + 2 * HYW - 5, W);       // k=2 @ j-5
      a_i0 (W + 5, s1[0], m, cM02KB3);
      a_im1(W + 5, s1[1], m, cM21KF0);
      a_im2(W + 5, s1[2], m); }
    { float W[12]; load_win_k<12, (KY + 0) & 3>(hy, base + 3 * HYW - 5, W);       // k=3 @ j-5
      a_ip1(W + 5, s1[0], m);
      a_i0 (W + 5, s1[1], m, cM02KB3);
      a_im1(W + 5, s1[2], m, cM21KF0);
      a_im2(W + 5, s1[3], m); }
    { float W[12]; load_win_k<12, (KY + 3) & 3>(hy, base + 4 * HYW - 5, W);       // k=4 @ j-5
      a_ip1(W + 5, s1[1], m);
      a_i0 (W + 5, s1[2], m, cM02KB3);
      a_im1(W + 5, s1[3], m, cM21KF0); }
    { float W[9];  load_win_k<9,  (KY + 2) & 3>(hy, base + 5 * HYW - 5, W);       // k=5 @ j-5
      a_ip1(W + 5, s1[2], m);
      a_i0 (W + 5, s1[3], m, cM02KB3); }
    { float W[6];  load_win_k<6,  (KY + 0) & 3>(hy, base + 6 * HYW - 2, W);       // k=6 @ j-2
      a_ip1(W + 2, s1[3], m); }
}

// ---------------------------------------------------------------------------
// Amper Hx section, 4 output rows. KX = skew of (row i0-5, col j) index.
// Window k = Hx row i0-5+k; role delta = k-5-r.
// ---------------------------------------------------------------------------
template<int KX>
__device__ __forceinline__ void amper_hx4(const float* __restrict__ hx, int base,
                                          const MCoef& m, float cM21KF0, float cM02KB3,
                                          float s2[4][4])
{
    { float W[4]; load_win_k<4, KX>(hx, base, W);                                 // k=0 @ j
      x_kb(W, s2[0], KB0); }
    { float W[4]; load_win_k<4, KX>(hx, base + HXW, W);                           // k=1
      x_kb(W, s2[1], KB0); x_kb(W, s2[0], KB1); }
    { float W[4]; load_win_k<4, KX>(hx, base + 2 * HXW, W);                       // k=2
      x_kb(W, s2[2], KB0); x_kb(W, s2[1], KB1); x_kb(W, s2[0], KB2); }
    { float W[7]; load_win_k<7, (KX + 2) & 3>(hx, base + 3 * HXW - 2, W);         // k=3 @ j-2
      x_kb(W + 2, s2[3], KB0); x_kb(W + 2, s2[2], KB1); x_kb(W + 2, s2[1], KB2);
      x_m2(W + 2, s2[0], m, cM02KB3); }
    { float W[7]; load_win_k<7, (KX + 2) & 3>(hx, base + 4 * HXW - 2, W);         // k=4
      x_kb(W + 2, s2[3], KB1); x_kb(W + 2, s2[2], KB2);
      x_m2(W + 2, s2[1], m, cM02KB3); x_m1(W + 2, s2[0], m); }
    { float W[7]; load_win_k<7, (KX + 2) & 3>(hx, base + 5 * HXW - 2, W);         // k=5
      x_kb(W + 2, s2[3], KB2); x_m2(W + 2, s2[2], m, cM02KB3);
      x_m1(W + 2, s2[1], m); x_00(W + 2, s2[0], m, cM21KF0); }
    { float W[7]; load_win_k<7, (KX + 2) & 3>(hx, base + 6 * HXW - 2, W);         // k=6
      x_m2(W + 2, s2[3], m, cM02KB3); x_m1(W + 2, s2[2], m);
      x_00(W + 2, s2[1], m, cM21KF0); x_kf(W + 2, s2[0], KF1); }
    { float W[7]; load_win_k<7, (KX + 2) & 3>(hx, base + 7 * HXW - 2, W);         // k=7
      x_m1(W + 2, s2[3], m); x_00(W + 2, s2[2], m, cM21KF0);
      x_kf(W + 2, s2[1], KF1); x_kf(W + 2, s2[0], KF2); }
    { float W[7]; load_win_k<7, (KX + 2) & 3>(hx, base + 8 * HXW - 2, W);         // k=8
      x_00(W + 2, s2[3], m, cM21KF0); x_kf(W + 2, s2[2], KF1);
      x_kf(W + 2, s2[1], KF2); x_kf(W + 2, s2[0], KF3); }
    { float W[4]; load_win_k<4, (KX + 3) & 3>(hx, base + 9 * HXW - 1, W);         // k=9 @ j-1
      x_kf(W + 1, s2[3], KF1); x_kf(W + 1, s2[2], KF2); x_kf(W + 1, s2[1], KF3); }
    { float W[4]; load_win_k<4, (KX + 3) & 3>(hx, base + 10 * HXW - 1, W);        // k=10
      x_kf(W + 1, s2[3], KF2); x_kf(W + 1, s2[2], KF3); }
    { float W[4]; load_win_k<4, (KX + 3) & 3>(hx, base + 11 * HXW - 1, W);        // k=11
      x_kf(W + 1, s2[3], KF3); }
}

// ---------------------------------------------------------------------------
// Amper fast compute: 4 rows x 4 cols -> w[4][4].
// ---------------------------------------------------------------------------
__device__ __forceinline__ void amper_fast4(
    const float* __restrict__ e_base, int eidx,
    const float* __restrict__ hy_base, int ybase,
    const float* __restrict__ hx_base, int xbase,
    const MCoef& m, float w[4][4])
{
    const float cM21KF0 = m.M21 + KF0;
    const float cM02KB3 = m.M02 + KB3;
    float s1[4][4] = {}, s2[4][4] = {};
    float E[4][4];

#define AMP_E_CASE(K)                                                  \
    load_win_k<4, (K) & 3>(e_base, eidx, E[0]);                        \
    load_win_k<4, ((K) + 1) & 3>(e_base, eidx + EW, E[1]);             \
    load_win_k<4, ((K) + 2) & 3>(e_base, eidx + 2 * EW, E[2]);         \
    load_win_k<4, ((K) + 3) & 3>(e_base, eidx + 3 * EW, E[3]);
    switch (eidx & 3) {
        case 0: AMP_E_CASE(0) break;
        case 1: AMP_E_CASE(1) break;
        case 2: AMP_E_CASE(2) break;
        case 3: AMP_E_CASE(3) break;
    }
#undef AMP_E_CASE

    switch (ybase & 3) {
        case 0: amper_hy4<0>(hy_base, ybase, m, cM21KF0, cM02KB3, s1); break;
        case 1: amper_hy4<1>(hy_base, ybase, m, cM21KF0, cM02KB3, s1); break;
        case 2: amper_hy4<2>(hy_base, ybase, m, cM21KF0, cM02KB3, s1); break;
        case 3: amper_hy4<3>(hy_base, ybase, m, cM21KF0, cM02KB3, s1); break;
    }
    switch (xbase & 3) {
        case 0: amper_hx4<0>(hx_base, xbase, m, cM21KF0, cM02KB3, s2); break;
        case 1: amper_hx4<1>(hx_base, xbase, m, cM21KF0, cM02KB3, s2); break;
        case 2: amper_hx4<2>(hx_base, xbase, m, cM21KF0, cM02KB3, s2); break;
        case 3: amper_hx4<3>(hx_base, xbase, m, cM21KF0, cM02KB3, s2); break;
    }
    #pragma unroll
    for (int r = 0; r < 4; r++)
        #pragma unroll
        for (int q = 0; q < 4; q++)
            w[r][q] = E[r][q] + CFLF * (s1[r][q] - s2[r][q]);
}

// ---------------------------------------------------------------------------
// Amper: 4 output rows x 4 cols per thread; 3-tier dispatch.
// ---------------------------------------------------------------------------
__global__ __launch_bounds__(128, 6)
void k_amper(const float* __restrict__ e_base,  int e_off,
             const float* __restrict__ hx_base, int hx_off,
             const float* __restrict__ hy_base, int hy_off,
             float* __restrict__ out_base,      int eo_off,
             const float* __restrict__ sb,
             const float* __restrict__ sd,
             const float* __restrict__ sg)
{
    int t  = blockIdx.x * 32 + threadIdx.x;
    int i0 = (blockIdx.y * blockDim.y + threadIdx.y) * 4;
    if (i0 > NN) return;                      // warp-uniform
    int b = blockIdx.z;

    const int erow0 = eo_off + b * EN + i0 * EW;
    const int s = erow0 & 3;
    const int j = 4 * t - s;
    const bool valid = (j + 3 >= 0) && (j <= NN);

    MCoef m = make_M(sb, sd, sg);
    const int xb = hx_off + b * HXN;
    const int yb = hy_off + b * HYN;

    const bool th_fast = valid && (i0 >= 5) && (i0 <= NN - 8) && (j >= 5) && (j <= NN - 8);
    const unsigned bal = __ballot_sync(0xffffffffu, th_fast);

    if (bal == 0xffffffffu) {
        float w[4][4];
        amper_fast4(e_base, e_off + b * EN + i0 * EW + j,
                    hy_base, yb + (i0 - 2) * HYW + j,
                    hx_base, xb + (i0 - 5) * HXW + j, m, w);
        float4 v; v.x = w[0][0]; v.y = w[0][1]; v.z = w[0][2]; v.w = w[0][3];
        *reinterpret_cast<float4*>(out_base + erow0 + j) = v;     // aligned
        warp_store128(out_base, erow0 + EW + j,     w[1][0], w[1][1], w[1][2], w[1][3]);
        warp_store128(out_base, erow0 + 2 * EW + j, w[2][0], w[2][1], w[2][2], w[2][3]);
        warp_store128(out_base, erow0 + 3 * EW + j, w[3][0], w[3][1], w[3][2], w[3][3]);
    } else if (th_fast) {
        float w[4][4];
        amper_fast4(e_base, e_off + b * EN + i0 * EW + j,
                    hy_base, yb + (i0 - 2) * HYW + j,
                    hx_base, xb + (i0 - 5) * HXW + j, m, w);
        float4 v; v.x = w[0][0]; v.y = w[0][1]; v.z = w[0][2]; v.w = w[0][3];
        *reinterpret_cast<float4*>(out_base + erow0 + j) = v;
        #pragma unroll
        for (int r = 1; r < 4; r++) {
            float* p = out_base + erow0 + r * EW + j;
            #pragma unroll
            for (int q = 0; q < 4; q++) p[q] = w[r][q];
        }
    } else if (valid) {
        const float* Eb  = e_base + e_off + b * EN;
        const float* Hxb = hx_base + xb;
        const float* Hyb = hy_base + yb;
        float* Eob = out_base + eo_off + b * EN;
        #pragma unroll
        for (int r = 0; r < 4; r++) {
            int ii = i0 + r;
            if (ii > NN) continue;
            #pragma unroll
            for (int q = 0; q < 4; q++) {
                int jj = j + q;
                if (jj < 0 || jj > NN) continue;
                float d = amper_point(Hxb, Hyb, ii, jj, m);
                Eob[ii * EW + jj] = Eb[ii * EW + jj] + CFLF * d;
            }
        }
    }
}

// ---------------------------------------------------------------------------
// Generic faraday point helpers
// ---------------------------------------------------------------------------
__device__ float faraday_s3(const float* __restrict__ Eb, int i, int j, const MCoef& m)
{
#define Ev(r, c) Eb[(r) * EW + (c)]
    float s3 = 0.0f;
    if (j >= 1 && j <= NN - 2) {
        s3 += m.M00 * Ev(i,     j - 1) + m.M01 * Ev(i,     j)
            + m.M02 * Ev(i,     j + 1) + m.M03 * Ev(i,     j + 2);
        s3 += m.M11 * Ev(i + 1, j);
        s3 += m.M20 * Ev(i + 2, j - 1) + m.M21 * Ev(i + 2, j)
            + m.M22 * Ev(i + 2, j + 1) + m.M23 * Ev(i + 2, j + 2);
    }
    if (i <= NN - 4)
        s3 += -1.5f * Ev(i + 1, j) + 2.0f * Ev(i + 2, j) - 0.5f * Ev(i + 3, j);
    if (i >= 2)
        s3 += 0.5f * Ev(i - 1, j + 1) - 2.0f * Ev(i, j + 1) + 1.5f * Ev(i + 1, j + 1);
#undef Ev
    return s3;
}

__device__ float faraday_s4(const float* __restrict__ Eb, int i, int j, const MCoef& m)
{
#define Ev(r, c) Eb[(r) * EW + (c)]
    float s4 = 0.0f;
    if (i >= 1 && i <= NN - 2) {
        s4 += m.M00 * Ev(i - 1, j) + m.M20 * Ev(i - 1, j + 2);
        s4 += m.M01 * Ev(i,     j) + m.M11 * Ev(i, j + 1) + m.M21 * Ev(i, j + 2);
        s4 += m.M02 * Ev(i + 1, j) + m.M22 * Ev(i + 1, j + 2);
        s4 += m.M03 * Ev(i + 2, j) + m.M23 * Ev(i + 2, j + 2);
    }
    if (j <= NN - 4)
        s4 += -1.5f * Ev(i, j + 1) + 2.0f * Ev(i, j + 2) - 0.5f * Ev(i, j + 3);
    if (j >= 2)
        s4 += 0.5f * Ev(i + 1, j - 1) - 2.0f * Ev(i + 1, j) + 1.5f * Ev(i + 1, j + 1);
#undef Ev
    return s4;
}

// ---------------------------------------------------------------------------
// Faraday role helpers: P[d] = E at column j+d.
// ---------------------------------------------------------------------------
__device__ __forceinline__ void f_im1(const float* P, float* s3, float* s4, const MCoef& m) {
    #pragma unroll
    for (int q = 0; q < 4; q++) {
        s3[q] += 0.5f * P[q + 1];
        s4[q] += m.M00 * P[q] + m.M20 * P[q + 2];
    }
}
__device__ __forceinline__ void f_i0(const float* P, float* s3, float* s4, const MCoef& m,
                                     float cA, float cB, float cC) {
    #pragma unroll
    for (int q = 0; q < 4; q++) {
        s3[q] += m.M00 * P[q - 1] + m.M01 * P[q] + cA * P[q + 1] + m.M03 * P[q + 2];
        s4[q] += m.M01 * P[q] + cB * P[q + 1] + cC * P[q + 2] - 0.5f * P[q + 3];
    }
}
__device__ __forceinline__ void f_ip1(const float* P, float* s3, float* s4, const MCoef& m,
                                      float cA, float cB) {
    #pragma unroll
    for (int q = 0; q < 4; q++) {
        s3[q] += cB * P[q] + 1.5f * P[q + 1];
        s4[q] += 0.5f * P[q - 1] + cA * P[q] + 1.5f * P[q + 1] + m.M22 * P[q + 2];
    }
}
__device__ __forceinline__ void f_ip2(const float* P, float* s3, float* s4, const MCoef& m,
                                      float cC) {
    #pragma unroll
    for (int q = 0; q < 4; q++) {
        s3[q] += m.M20 * P[q - 1] + cC * P[q] + m.M22 * P[q + 1] + m.M23 * P[q + 2];
        s4[q] += m.M03 * P[q] + m.M23 * P[q + 2];
    }
}
__device__ __forceinline__ void f_ip3(const float* P, float* s3) {
    #pragma unroll
    for (int q = 0; q < 4; q++) s3[q] += -0.5f * P[q];
}

// ---------------------------------------------------------------------------
// Faraday E section, 4 output rows. K0 = skew of idx0 = E[i0-1, j-1].
// Window k = E row i0-1+k; role delta' = k-1-r.
// ---------------------------------------------------------------------------
template<int K0>
__device__ __forceinline__ void faraday_e4(const float* __restrict__ e, int idx0,
                                           const MCoef& m, float cA, float cB, float cC,
                                           float s3[4][4], float s4[4][4])
{
    { float W[6]; load_win_k<6, (K0 + 1) & 3>(e, idx0 + 1, W);                    // k=0 @ j
      f_im1(W, s3[0], s4[0], m); }
    { float W[8]; load_win_k<8, (K0 + 1) & 3>(e, idx0 + EW, W);                   // k=1 @ j-1
      f_i0 (W + 1, s3[0], s4[0], m, cA, cB, cC);
      f_im1(W + 1, s3[1], s4[1], m); }
    { float W[8]; load_win_k<8, (K0 + 2) & 3>(e, idx0 + 2 * EW, W);               // k=2
      f_ip1(W + 1, s3[0], s4[0], m, cA, cB);
      f_i0 (W + 1, s3[1], s4[1], m, cA, cB, cC);
      f_im1(W + 1, s3[2], s4[2], m); }
    { float W[8]; load_win_k<8, (K0 + 3) & 3>(e, idx0 + 3 * EW, W);               // k=3
      f_ip2(W + 1, s3[0], s4[0], m, cC);
      f_ip1(W + 1, s3[1], s4[1], m, cA, cB);
      f_i0 (W + 1, s3[2], s4[2], m, cA, cB, cC);
      f_im1(W + 1, s3[3], s4[3], m); }
    { float W[8]; load_win_k<8, (K0 + 0) & 3>(e, idx0 + 4 * EW, W);               // k=4
      f_ip3(W + 1, s3[0]);
      f_ip2(W + 1, s3[1], s4[1], m, cC);
      f_ip1(W + 1, s3[2], s4[2], m, cA, cB);
      f_i0 (W + 1, s3[3], s4[3], m, cA, cB, cC); }
    { float W[7]; load_win_k<7, (K0 + 1) & 3>(e, idx0 + 5 * EW, W);               // k=5
      f_ip3(W + 1, s3[1]);
      f_ip2(W + 1, s3[2], s4[2], m, cC);
      f_ip1(W + 1, s3[3], s4[3], m, cA, cB); }
    { float W[7]; load_win_k<7, (K0 + 2) & 3>(e, idx0 + 6 * EW, W);               // k=6
      f_ip3(W + 1, s3[2]);
      f_ip2(W + 1, s3[3], s4[3], m, cC); }
    { float W[4]; load_win_k<4, (K0 + 0) & 3>(e, idx0 + 7 * EW + 1, W);           // k=7 @ j
      f_ip3(W, s3[3]); }
}

// ---------------------------------------------------------------------------
// Faraday fast compute: 4 rows x 4 cols -> wx[4][4], wy[4][4].
// ---------------------------------------------------------------------------
__device__ __forceinline__ void faraday_fast4(
    const float* __restrict__ e_base, int ebase,
    const float* __restrict__ hx_base, int hxidx,
    const float* __restrict__ hy_base, int hyidx,
    const MCoef& m, float wx[4][4], float wy[4][4])
{
    const float cA = m.M02 - 2.0f;
    const float cB = m.M11 - 1.5f;
    const float cC = m.M21 + 2.0f;
    float s3[4][4] = {}, s4[4][4] = {};
    float hx[4][4], hy[4][4];

#define F_HX_CASE(K)                                                   \
    load_win_k<4, (K) & 3>(hx_base, hxidx, hx[0]);                     \
    load_win_k<4, (K) & 3>(hx_base, hxidx + HXW, hx[1]);               \
    load_win_k<4, (K) & 3>(hx_base, hxidx + 2 * HXW, hx[2]);           \
    load_win_k<4, (K) & 3>(hx_base, hxidx + 3 * HXW, hx[3]);
    switch (hxidx & 3) {
        case 0: F_HX_CASE(0) break;
        case 1: F_HX_CASE(1) break;
        case 2: F_HX_CASE(2) break;
        case 3: F_HX_CASE(3) break;
    }
#undef F_HX_CASE
#define F_HY_CASE(K)                                                   \
    load_win_k<4, (K) & 3>(hy_base, hyidx, hy[0]);                     \
    load_win_k<4, ((K) + 3) & 3>(hy_base, hyidx + HYW, hy[1]);         \
    load_win_k<4, ((K) + 2) & 3>(hy_base, hyidx + 2 * HYW, hy[2]);     \
    load_win_k<4, ((K) + 1) & 3>(hy_base, hyidx + 3 * HYW, hy[3]);
    switch (hyidx & 3) {
        case 0: F_HY_CASE(0) break;
        case 1: F_HY_CASE(1) break;
        case 2: F_HY_CASE(2) break;
        case 3: F_HY_CASE(3) break;
    }
#undef F_HY_CASE

    switch (ebase & 3) {
        case 0: faraday_e4<0>(e_base, ebase, m, cA, cB, cC, s3, s4); break;
        case 1: faraday_e4<1>(e_base, ebase, m, cA, cB, cC, s3, s4); break;
        case 2: faraday_e4<2>(e_base, ebase, m, cA, cB, cC, s3, s4); break;
        case 3: faraday_e4<3>(e_base, ebase, m, cA, cB, cC, s3, s4); break;
    }
    #pragma unroll
    for (int r = 0; r < 4; r++)
        #pragma unroll
        for (int q = 0; q < 4; q++) {
            wx[r][q] = hx[r][q] - CFLF * s3[r][q];
            wy[r][q] = hy[r][q] + CFLF * s4[r][q];
        }
}

// ---------------------------------------------------------------------------
// Fused faraday: 4 output rows x 4 cols per thread; 3-tier dispatch.
// ---------------------------------------------------------------------------
__global__ __launch_bounds__(128, 6)
void k_faraday(const float* __restrict__ e_base,  int e_off,
               const float* __restrict__ hx_base, int hx_off,
               const float* __restrict__ hy_base, int hy_off,
               float* __restrict__ out_base,      int hxo_off, int hyo_off,
               const float* __restrict__ sb,
               const float* __restrict__ sd,
               const float* __restrict__ sg)
{
    int t  = blockIdx.x * 32 + threadIdx.x;
    int i0 = (blockIdx.y * blockDim.y + threadIdx.y) * 4;
    if (i0 >= NN) return;                     // warp-uniform
    int b = blockIdx.z;

    const int sF = hxo_off & 3;
    const int j = 4 * t - sF;
    const bool valid = (j + 3 >= 0) && (j < NN);

    MCoef m = make_M(sb, sd, sg);
    const int eb = e_off + b * EN;
    const int xb = hx_off + b * HXN;
    const int yb = hy_off + b * HYN;

    const bool th_fast = valid && (i0 >= 2) && (i0 <= NN - 7) && (j >= 2) && (j <= NN - 7);
    const unsigned bal = __ballot_sync(0xffffffffu, th_fast);

    if (bal == 0xffffffffu) {
        float wx[4][4], wy[4][4];
        faraday_fast4(e_base, eb + (i0 - 1) * EW + (j - 1),
                      hx_base, xb + i0 * HXW + j,
                      hy_base, yb + i0 * HYW + j, m, wx, wy);
        #pragma unroll
        for (int r = 0; r < 4; r++) {
            float4 v; v.x = wx[r][0]; v.y = wx[r][1]; v.z = wx[r][2]; v.w = wx[r][3];
            *reinterpret_cast<float4*>(out_base + hxo_off + b * HXN + (i0 + r) * HXW + j) = v;
        }
        #pragma unroll
        for (int r = 0; r < 4; r++)
            warp_store128(out_base, hyo_off + b * HYN + (i0 + r) * HYW + j,
                          wy[r][0], wy[r][1], wy[r][2], wy[r][3]);
    } else if (th_fast) {
        float wx[4][4], wy[4][4];
        faraday_fast4(e_base, eb + (i0 - 1) * EW + (j - 1),
                      hx_base, xb + i0 * HXW + j,
                      hy_base, yb + i0 * HYW + j, m, wx, wy);
        #pragma unroll
        for (int r = 0; r < 4; r++) {
            float4 v; v.x = wx[r][0]; v.y = wx[r][1]; v.z = wx[r][2]; v.w = wx[r][3];
            *reinterpret_cast<float4*>(out_base + hxo_off + b * HXN + (i0 + r) * HXW + j) = v;
            float* p = out_base + hyo_off + b * HYN + (i0 + r) * HYW + j;
            #pragma unroll
            for (int q = 0; q < 4; q++) p[q] = wy[r][q];
        }
    } else if (valid) {
        const float* Eb  = e_base + eb;
        const float* Hxb = hx_base + xb;
        const float* Hyb = hy_base + yb;
        float* Hxob = out_base + hxo_off + b * HXN;
        float* Hyob = out_base + hyo_off + b * HYN;
        #pragma unroll
        for (int r = 0; r < 4; r++) {
            int ii = i0 + r;
            if (ii >= NN) continue;
            #pragma unroll
            for (int q = 0; q < 4; q++) {
                int jj = j + q;
                if (jj < 0 || jj >= NN) continue;
                if (ii < HXH && jj < HXW) {
                    float s3 = faraday_s3(Eb, ii, jj, m);
                    Hxob[ii * HXW + jj] = Hxb[ii * HXW + jj] - CFLF * s3;
                }
                if (ii < HYH && jj < HYW) {
                    float s4 = faraday_s4(Eb, ii, jj, m);
                    Hyob[ii * HYW + jj] = Hyb[ii * HYW + jj] + CFLF * s4;
                }
            }
        }
    }
}

// ---------------------------------------------------------------------------
extern "C" void kernel_launch(void* const* d_in, const int* in_sizes, int n_in,
                              void* d_out, int out_size)
{
    const float* sb = (const float*)d_in[3];
    const float* sd = (const float*)d_in[4];
    const float* sg = (const float*)d_in[5];
    float* out = (float*)d_out;

    const float* e_base  = (const float*)d_in[0]; int e_off  = 0;
    const float* hx_base = (const float*)d_in[1]; int hx_off = 0;
    const float* hy_base = (const float*)d_in[2]; int hy_off = 0;

    const int STEP = BB * (EN + HXN + HYN);

    dim3 blk(32, 4, 1);
    // amper: 513 row-strips of 4 cover 2052 >= 2049; faraday: 512 strips.
    dim3 gE(17, (513 + 3) / 4, BB);
    dim3 gF(17, 512 / 4, BB);

    for (int k = 0; k < 3; k++) {
        int eo_off  = k * STEP;
        int hxo_off = eo_off + BB * EN;
        int hyo_off = hxo_off + BB * HXN;

        k_amper<<<gE, blk>>>(e_base, e_off, hx_base, hx_off, hy_base, hy_off,
                             out, eo_off, sb, sd, sg);
        k_faraday<<<gF, blk>>>(out, eo_off, hx_base, hx_off, hy_base, hy_off,
                               out, hxo_off, hyo_off, sb, sd, sg);

        e_base = out;  e_off  = eo_off;
        hx_base = out; hx_off = hxo_off;
        hy_base = out; hy_off = hyo_off;
    }
}

// round 8
// speedup vs baseline: 1.1001x; 1.1001x over previous
#include <cuda_runtime.h>

// Problem constants (fixed: N=2048, B=2)
#define NN   2048
#define BB   2
#define EW   (NN + 1)            // 2049  (== 1 mod 4)
#define HXH  (NN - 1)            // 2047
#define HXW  (NN)                // 2048  (== 0 mod 4)
#define HYH  (NN)                // 2048
#define HYW  (NN - 1)            // 2047  (== 3 mod 4)
#define EN   (EW * EW)
#define HXN  (HXH * HXW)
#define HYN  (HYH * HYW)
#define CFLF 0.35f

#define KF0 (-11.0f / 6.0f)
#define KF1 (3.0f)
#define KF2 (-1.5f)
#define KF3 (1.0f / 3.0f)
#define KB0 (-1.0f / 3.0f)
#define KB1 (1.5f)
#define KB2 (-3.0f)
#define KB3 (11.0f / 6.0f)

struct MCoef {
    float M00, M01, M02, M03, M11, M20, M21, M22, M23;
};

// Precomputed coefficients, filled once by k_setup:
// [0..8]  M00,M01,M02,M03,M11,M20,M21,M22,M23
// [9]  cM21KF0  [10] cM02KB3  [11] cA  [12] cB  [13] cC
__device__ float g_coef[16];

__global__ void k_setup(const float* __restrict__ sb,
                        const float* __restrict__ sd,
                        const float* __restrict__ sg)
{
    float beta = *sb, delta = *sd, gamma = *sg;
    float M00 = -0.25f * beta + 0.1f * gamma;
    float M01 =  0.25f * beta + delta - 0.5f - 0.1f * gamma;
    float M02 =  0.25f * beta - 0.1f * gamma;
    float M03 = -0.25f * beta + 0.1f * gamma;
    float M11 = -2.0f * delta;
    float M20 =  0.25f * beta - 0.1f * gamma;
    float M21 = -0.25f * beta + delta + 0.5f + 0.1f * gamma;
    float M22 = -0.25f * beta - 0.1f * gamma;
    float M23 =  0.25f * beta + 0.1f * gamma;
    g_coef[0] = M00;  g_coef[1] = M01;  g_coef[2] = M02;  g_coef[3] = M03;
    g_coef[4] = M11;  g_coef[5] = M20;  g_coef[6] = M21;  g_coef[7] = M22;
    g_coef[8] = M23;
    g_coef[9]  = M21 + KF0;        // cM21KF0
    g_coef[10] = M02 + KB3;        // cM02KB3
    g_coef[11] = M02 - 2.0f;       // cA
    g_coef[12] = M11 - 1.5f;       // cB
    g_coef[13] = M21 + 2.0f;       // cC
    g_coef[14] = 0.0f; g_coef[15] = 0.0f;
}

__device__ __forceinline__ MCoef load_M() {
    const float4* cp = reinterpret_cast<const float4*>(g_coef);
    float4 c0 = cp[0], c1 = cp[1], c2 = cp[2];
    MCoef m;
    m.M00 = c0.x; m.M01 = c0.y; m.M02 = c0.z; m.M03 = c0.w;
    m.M11 = c1.x; m.M20 = c1.y; m.M21 = c1.z; m.M22 = c1.w;
    m.M23 = c2.x;
    return m;
}

// ---------------------------------------------------------------------------
// Warp-coalesced store of a 128-float row segment (4 floats/lane, stride 4).
// gi & 3 warp-uniform; whole warp participates.
// ---------------------------------------------------------------------------
__device__ __forceinline__ void warp_store128(float* __restrict__ out, int gi,
                                              float v0, float v1, float v2, float v3)
{
    const unsigned FULL = 0xffffffffu;
    const int lane = threadIdx.x & 31;
    const int s = gi & 3;
    if (s == 0) {
        float4 w; w.x = v0; w.y = v1; w.z = v2; w.w = v3;
        *reinterpret_cast<float4*>(out + gi) = w;
        return;
    }
    float n0 = __shfl_down_sync(FULL, v0, 1);
    float n1 = __shfl_down_sync(FULL, v1, 1);
    float n2 = __shfl_down_sync(FULL, v2, 1);
    if (s == 1) {
        if (lane < 31) {
            float4 w; w.x = v3; w.y = n0; w.z = n1; w.w = n2;
            *reinterpret_cast<float4*>(out + gi + 3) = w;
        }
        if (lane == 0)  { out[gi] = v0; out[gi + 1] = v1; out[gi + 2] = v2; }
        else if (lane == 31) { out[gi + 3] = v3; }
    } else if (s == 2) {
        if (lane < 31) {
            float4 w; w.x = v2; w.y = v3; w.z = n0; w.w = n1;
            *reinterpret_cast<float4*>(out + gi + 2) = w;
        }
        if (lane == 0)  { out[gi] = v0; out[gi + 1] = v1; }
        else if (lane == 31) { out[gi + 2] = v2; out[gi + 3] = v3; }
    } else {
        if (lane < 31) {
            float4 w; w.x = v1; w.y = v2; w.z = v3; w.w = n0;
            *reinterpret_cast<float4*>(out + gi + 1) = w;
        }
        if (lane == 0)  { out[gi] = v0; }
        else if (lane == 31) { out[gi + 1] = v1; out[gi + 2] = v2; out[gi + 3] = v3; }
    }
}

// ---------------------------------------------------------------------------
// Compile-time-skew window load: out[t] = buf[idx+t], requires (idx&3)==K.
// ---------------------------------------------------------------------------
template<int W, int K>
__device__ __forceinline__ void load_win_k(const float* __restrict__ buf, int idx,
                                           float* __restrict__ out)
{
    constexpr int NV = (W + K + 3) / 4;
    const float4* p = reinterpret_cast<const float4*>(buf + (idx - K));
    float f[NV * 4];
    #pragma unroll
    for (int t = 0; t < NV; t++)
        *reinterpret_cast<float4*>(f + 4 * t) = p[t];
    #pragma unroll
    for (int t = 0; t < W; t++) out[t] = f[t + K];
}

// ---------------------------------------------------------------------------
// Generic (boundary) amper point.
// ---------------------------------------------------------------------------
__device__ float amper_point(const float* __restrict__ Hxb,
                             const float* __restrict__ Hyb,
                             int i, int j, const MCoef& m)
{
    float s1 = 0.0f, s2 = 0.0f;
    bool irow = (i >= 2 && i <= NN - 2);
    bool jcol = (j >= 2 && j <= NN - 2);

#define HYv(r, c) Hyb[(r) * HYW + (c)]
#define HXv(r, c) Hxb[(r) * HXW + (c)]
    if (irow && jcol) {
        s1 += m.M00 * HYv(i - 2, j - 2) + m.M20 * HYv(i - 2, j);
        s1 += m.M01 * HYv(i - 1, j - 2) + m.M11 * HYv(i - 1, j - 1) + m.M21 * HYv(i - 1, j);
        s1 += m.M02 * HYv(i,     j - 2) + m.M22 * HYv(i,     j);
        s1 += m.M03 * HYv(i + 1, j - 2) + m.M23 * HYv(i + 1, j);
        s2 += m.M00 * HXv(i - 2, j - 2) + m.M01 * HXv(i - 2, j - 1)
            + m.M02 * HXv(i - 2, j)     + m.M03 * HXv(i - 2, j + 1);
        s2 += m.M11 * HXv(i - 1, j - 1);
        s2 += m.M20 * HXv(i,     j - 2) + m.M21 * HXv(i,     j - 1)
            + m.M22 * HXv(i,     j)     + m.M23 * HXv(i,     j + 1);
    }
    if (i >= 1 && j <= NN - 5) {
        s1 += KF0 * HYv(i - 1, j)     + KF1 * HYv(i - 1, j + 1)
            + KF2 * HYv(i - 1, j + 2) + KF3 * HYv(i - 1, j + 3);
    }
    if (i <= NN - 1 && j >= 5) {
        s1 += KB0 * HYv(i, j - 5) + KB1 * HYv(i, j - 4)
            + KB2 * HYv(i, j - 3) + KB3 * HYv(i, j - 2);
    }
    if (irow && j >= 1 && j <= 2) {
        s1 += -HYv(i - 1, j - 1) + 3.0f * HYv(i - 1, j)
              - 3.0f * HYv(i - 1, j + 1) + HYv(i - 1, j + 2);
    }
    if (irow && j >= NN - 2 && j <= NN - 1) {
        s1 += HYv(i, j - 4) - 3.0f * HYv(i, j - 3)
            + 3.0f * HYv(i, j - 2) - HYv(i, j - 1);
    }
    if (j >= 1 && i <= NN - 5) {
        s2 += KF0 * HXv(i, j - 1)     + KF1 * HXv(i + 1, j - 1)
            + KF2 * HXv(i + 2, j - 1) + KF3 * HXv(i + 3, j - 1);
    }
    if (j <= NN - 1 && i >= 5) {
        s2 += KB0 * HXv(i - 5, j) + KB1 * HXv(i - 4, j)
            + KB2 * HXv(i - 3, j) + KB3 * HXv(i - 2, j);
    }
    if (jcol && i >= 1 && i <= 2) {
        s2 += -HXv(i - 1, j - 1) + 3.0f * HXv(i, j - 1)
              - 3.0f * HXv(i + 1, j - 1) + HXv(i + 2, j - 1);
    }
    if (jcol && i >= NN - 2 && i <= NN - 1) {
        s2 += HXv(i - 4, j) - 3.0f * HXv(i - 3, j)
            + 3.0f * HXv(i - 2, j) - HXv(i - 1, j);
    }
#undef HYv
#undef HXv
    return s1 - s2;
}

// ---------------------------------------------------------------------------
// Amper Hy section (rows i0-2 .. i0+2), 2 output rows. KY = skew of base.
// ---------------------------------------------------------------------------
template<int KY>
__device__ __forceinline__ void amper_hy_sec(const float* __restrict__ hy, int base,
                                             const MCoef& m, float cM21KF0, float cM02KB3,
                                             float* __restrict__ s1a, float* __restrict__ s1b)
{
    float Y0[6], Y1[9], Y2[12], Y3[9], Y4[6];
    load_win_k<6,  KY          >(hy, base, Y0);
    load_win_k<9,  (KY + 3) & 3>(hy, base + HYW, Y1);
    load_win_k<12, (KY + 3) & 3>(hy, base + 2 * HYW - 3, Y2);
    load_win_k<9,  (KY + 2) & 3>(hy, base + 3 * HYW - 3, Y3);
    load_win_k<6,  KY          >(hy, base + 4 * HYW, Y4);

    #pragma unroll
    for (int q = 0; q < 4; q++) {
        s1a[q] += m.M00 * Y0[q] + m.M20 * Y0[q + 2];
        s1a[q] += m.M01 * Y1[q] + m.M11 * Y1[q + 1] + cM21KF0 * Y1[q + 2]
                + KF1 * Y1[q + 3] + KF2 * Y1[q + 4] + KF3 * Y1[q + 5];
        s1b[q] += m.M00 * Y1[q] + m.M20 * Y1[q + 2];
        s1a[q] += KB0 * Y2[q] + KB1 * Y2[q + 1] + KB2 * Y2[q + 2]
                + cM02KB3 * Y2[q + 3] + m.M22 * Y2[q + 5];
        s1b[q] += m.M01 * Y2[q + 3] + m.M11 * Y2[q + 4] + cM21KF0 * Y2[q + 5]
                + KF1 * Y2[q + 6] + KF2 * Y2[q + 7] + KF3 * Y2[q + 8];
        s1a[q] += m.M03 * Y3[q + 3] + m.M23 * Y3[q + 5];
        s1b[q] += KB0 * Y3[q] + KB1 * Y3[q + 1] + KB2 * Y3[q + 2]
                + cM02KB3 * Y3[q + 3] + m.M22 * Y3[q + 5];
        s1b[q] += m.M03 * Y4[q] + m.M23 * Y4[q + 2];
    }
}

// ---------------------------------------------------------------------------
// Amper Hx section (rows i0-5 .. i0+4), 2 output rows. KX = skew of base.
// ---------------------------------------------------------------------------
template<int KX>
__device__ __forceinline__ void amper_hx_sec(const float* __restrict__ hx, int base,
                                             const MCoef& m, float cM21KF0, float cM02KB3,
                                             float* __restrict__ s2a, float* __restrict__ s2b)
{
    float X0[4], X1[4], X2[4], X3[7], X4[7], X5[7], X6[7], X7[4], X8[4], X9[4];
    load_win_k<4, KX          >(hx, base, X0);
    load_win_k<4, KX          >(hx, base + HXW, X1);
    load_win_k<4, KX          >(hx, base + 2 * HXW, X2);
    load_win_k<7, (KX + 2) & 3>(hx, base + 3 * HXW - 2, X3);
    load_win_k<7, (KX + 2) & 3>(hx, base + 4 * HXW - 2, X4);
    load_win_k<7, (KX + 2) & 3>(hx, base + 5 * HXW - 2, X5);
    load_win_k<7, (KX + 2) & 3>(hx, base + 6 * HXW - 2, X6);
    load_win_k<4, (KX + 3) & 3>(hx, base + 7 * HXW - 1, X7);
    load_win_k<4, (KX + 3) & 3>(hx, base + 8 * HXW - 1, X8);
    load_win_k<4, (KX + 3) & 3>(hx, base + 9 * HXW - 1, X9);

    #pragma unroll
    for (int q = 0; q < 4; q++) {
        s2a[q] += KB0 * X0[q] + KB1 * X1[q] + KB2 * X2[q];
        s2b[q] += KB0 * X1[q] + KB1 * X2[q];
        s2a[q] += m.M00 * X3[q] + m.M01 * X3[q + 1] + cM02KB3 * X3[q + 2] + m.M03 * X3[q + 3];
        s2b[q] += KB2 * X3[q + 2];
        s2a[q] += m.M11 * X4[q + 1];
        s2b[q] += m.M00 * X4[q] + m.M01 * X4[q + 1] + cM02KB3 * X4[q + 2] + m.M03 * X4[q + 3];
        s2a[q] += m.M20 * X5[q] + cM21KF0 * X5[q + 1] + m.M22 * X5[q + 2] + m.M23 * X5[q + 3];
        s2b[q] += m.M11 * X5[q + 1];
        s2a[q] += KF1 * X6[q + 1];
        s2b[q] += m.M20 * X6[q] + cM21KF0 * X6[q + 1] + m.M22 * X6[q + 2] + m.M23 * X6[q + 3];
        s2a[q] += KF2 * X7[q] + KF3 * X8[q];
        s2b[q] += KF1 * X7[q] + KF2 * X8[q] + KF3 * X9[q];
    }
}

// ---------------------------------------------------------------------------
// Amper: 2 output rows x 4 cols per thread.
// ---------------------------------------------------------------------------
__global__ __launch_bounds__(128)
void k_amper(const float* __restrict__ e_base,  int e_off,
             const float* __restrict__ hx_base, int hx_off,
             const float* __restrict__ hy_base, int hy_off,
             float* __restrict__ out_base,      int eo_off)
{
    int t  = blockIdx.x * 32 + threadIdx.x;
    int i0 = (blockIdx.y * blockDim.y + threadIdx.y) * 2;
    if (i0 > NN) return;
    int b = blockIdx.z;

    const int erow0 = eo_off + b * EN + i0 * EW;
    const int s = erow0 & 3;
    const int j = 4 * t - s;
    if (j + 3 < 0 || j > NN) return;

    MCoef m = load_M();
    const float cM21KF0 = g_coef[9];
    const float cM02KB3 = g_coef[10];

    const int xb = hx_off + b * HXN;
    const int yb = hy_off + b * HYN;

    bool fast = (i0 >= 5) && (i0 <= NN - 6) && (j >= 5) && (j + 3 <= NN - 5);
    if (fast) {
        float s1a[4] = {0, 0, 0, 0}, s1b[4] = {0, 0, 0, 0};
        float s2a[4] = {0, 0, 0, 0}, s2b[4] = {0, 0, 0, 0};

        float E0[4], E1[4];
        const int eidx = e_off + b * EN + i0 * EW + j;
        switch (eidx & 3) {
            case 0: load_win_k<4, 0>(e_base, eidx, E0); load_win_k<4, 1>(e_base, eidx + EW, E1); break;
            case 1: load_win_k<4, 1>(e_base, eidx, E0); load_win_k<4, 2>(e_base, eidx + EW, E1); break;
            case 2: load_win_k<4, 2>(e_base, eidx, E0); load_win_k<4, 3>(e_base, eidx + EW, E1); break;
            case 3: load_win_k<4, 3>(e_base, eidx, E0); load_win_k<4, 0>(e_base, eidx + EW, E1); break;
        }

        const int ybase = yb + (i0 - 2) * HYW + (j - 2);
        switch (ybase & 3) {
            case 0: amper_hy_sec<0>(hy_base, ybase, m, cM21KF0, cM02KB3, s1a, s1b); break;
            case 1: amper_hy_sec<1>(hy_base, ybase, m, cM21KF0, cM02KB3, s1a, s1b); break;
            case 2: amper_hy_sec<2>(hy_base, ybase, m, cM21KF0, cM02KB3, s1a, s1b); break;
            case 3: amper_hy_sec<3>(hy_base, ybase, m, cM21KF0, cM02KB3, s1a, s1b); break;
        }

        const int xbase = xb + (i0 - 5) * HXW + j;
        switch (xbase & 3) {
            case 0: amper_hx_sec<0>(hx_base, xbase, m, cM21KF0, cM02KB3, s2a, s2b); break;
            case 1: amper_hx_sec<1>(hx_base, xbase, m, cM21KF0, cM02KB3, s2a, s2b); break;
            case 2: amper_hx_sec<2>(hx_base, xbase, m, cM21KF0, cM02KB3, s2a, s2b); break;
            case 3: amper_hx_sec<3>(hx_base, xbase, m, cM21KF0, cM02KB3, s2a, s2b); break;
        }

        float4 w;
        w.x = E0[0] + CFLF * (s1a[0] - s2a[0]);
        w.y = E0[1] + CFLF * (s1a[1] - s2a[1]);
        w.z = E0[2] + CFLF * (s1a[2] - s2a[2]);
        w.w = E0[3] + CFLF * (s1a[3] - s2a[3]);
        *reinterpret_cast<float4*>(out_base + erow0 + j) = w;   // aligned

        float* w1 = out_base + erow0 + EW + j;                  // odd stride: scalar
        #pragma unroll
        for (int q = 0; q < 4; q++)
            w1[q] = E1[q] + CFLF * (s1b[q] - s2b[q]);
    } else {
        const float* Eb  = e_base + e_off + b * EN;
        const float* Hxb = hx_base + xb;
        const float* Hyb = hy_base + yb;
        float* Eob = out_base + eo_off + b * EN;
        #pragma unroll
        for (int r = 0; r < 2; r++) {
            int ii = i0 + r;
            if (ii > NN) continue;
            #pragma unroll
            for (int q = 0; q < 4; q++) {
                int jj = j + q;
                if (jj < 0 || jj > NN) continue;
                float d = amper_point(Hxb, Hyb, ii, jj, m);
                Eob[ii * EW + jj] = Eb[ii * EW + jj] + CFLF * d;
            }
        }
    }
}

// ---------------------------------------------------------------------------
// Generic faraday point helpers
// ---------------------------------------------------------------------------
__device__ float faraday_s3(const float* __restrict__ Eb, int i, int j, const MCoef& m)
{
#define Ev(r, c) Eb[(r) * EW + (c)]
    float s3 = 0.0f;
    if (j >= 1 && j <= NN - 2) {
        s3 += m.M00 * Ev(i,     j - 1) + m.M01 * Ev(i,     j)
            + m.M02 * Ev(i,     j + 1) + m.M03 * Ev(i,     j + 2);
        s3 += m.M11 * Ev(i + 1, j);
        s3 += m.M20 * Ev(i + 2, j - 1) + m.M21 * Ev(i + 2, j)
            + m.M22 * Ev(i + 2, j + 1) + m.M23 * Ev(i + 2, j + 2);
    }
    if (i <= NN - 4)
        s3 += -1.5f * Ev(i + 1, j) + 2.0f * Ev(i + 2, j) - 0.5f * Ev(i + 3, j);
    if (i >= 2)
        s3 += 0.5f * Ev(i - 1, j + 1) - 2.0f * Ev(i, j + 1) + 1.5f * Ev(i + 1, j + 1);
#undef Ev
    return s3;
}

__device__ float faraday_s4(const float* __restrict__ Eb, int i, int j, const MCoef& m)
{
#define Ev(r, c) Eb[(r) * EW + (c)]
    float s4 = 0.0f;
    if (i >= 1 && i <= NN - 2) {
        s4 += m.M00 * Ev(i - 1, j) + m.M20 * Ev(i - 1, j + 2);
        s4 += m.M01 * Ev(i,     j) + m.M11 * Ev(i, j + 1) + m.M21 * Ev(i, j + 2);
        s4 += m.M02 * Ev(i + 1, j) + m.M22 * Ev(i + 1, j + 2);
        s4 += m.M03 * Ev(i + 2, j) + m.M23 * Ev(i + 2, j + 2);
    }
    if (j <= NN - 4)
        s4 += -1.5f * Ev(i, j + 1) + 2.0f * Ev(i, j + 2) - 0.5f * Ev(i, j + 3);
    if (j >= 2)
        s4 += 0.5f * Ev(i + 1, j - 1) - 2.0f * Ev(i + 1, j) + 1.5f * Ev(i + 1, j + 1);
#undef Ev
    return s4;
}

// ---------------------------------------------------------------------------
// Faraday E section (rows i0-1 .. i0+4), 2 output rows. KE = skew of base.
// ---------------------------------------------------------------------------
template<int KE>
__device__ __forceinline__ void faraday_e_sec(const float* __restrict__ e, int base,
                                              const MCoef& m, float cA, float cB, float cC,
                                              float* __restrict__ s3a, float* __restrict__ s3b,
                                              float* __restrict__ s4a, float* __restrict__ s4b)
{
    float W0[6], W1[8], W2[8], W3[7], W4[7], W5[4];
    load_win_k<6, KE          >(e, base, W0);
    load_win_k<8, KE          >(e, base + EW - 1, W1);
    load_win_k<8, (KE + 1) & 3>(e, base + 2 * EW - 1, W2);
    load_win_k<7, (KE + 2) & 3>(e, base + 3 * EW - 1, W3);
    load_win_k<7, (KE + 3) & 3>(e, base + 4 * EW - 1, W4);
    load_win_k<4, (KE + 1) & 3>(e, base + 5 * EW, W5);

    #pragma unroll
    for (int q = 0; q < 4; q++) {
        s3a[q] += 0.5f * W0[q + 1];
        s4a[q] += m.M00 * W0[q] + m.M20 * W0[q + 2];
        s3a[q] += m.M00 * W1[q] + m.M01 * W1[q + 1] + cA * W1[q + 2] + m.M03 * W1[q + 3];
        s4a[q] += m.M01 * W1[q + 1] + cB * W1[q + 2] + cC * W1[q + 3] - 0.5f * W1[q + 4];
        s3b[q] += 0.5f * W1[q + 2];
        s4b[q] += m.M00 * W1[q + 1] + m.M20 * W1[q + 3];
        s3a[q] += cB * W2[q + 1] + 1.5f * W2[q + 2];
        s4a[q] += 0.5f * W2[q] + cA * W2[q + 1] + 1.5f * W2[q + 2] + m.M22 * W2[q + 3];
        s3b[q] += m.M00 * W2[q] + m.M01 * W2[q + 1] + cA * W2[q + 2] + m.M03 * W2[q + 3];
        s4b[q] += m.M01 * W2[q + 1] + cB * W2[q + 2] + cC * W2[q + 3] - 0.5f * W2[q + 4];
        s3a[q] += m.M20 * W3[q] + cC * W3[q + 1] + m.M22 * W3[q + 2] + m.M23 * W3[q + 3];
        s4a[q] += m.M03 * W3[q + 1] + m.M23 * W3[q + 3];
        s3b[q] += cB * W3[q + 1] + 1.5f * W3[q + 2];
        s4b[q] += 0.5f * W3[q] + cA * W3[q + 1] + 1.5f * W3[q + 2] + m.M22 * W3[q + 3];
        s3a[q] += -0.5f * W4[q + 1];
        s3b[q] += m.M20 * W4[q] + cC * W4[q + 1] + m.M22 * W4[q + 2] + m.M23 * W4[q + 3];
        s4b[q] += m.M03 * W4[q + 1] + m.M23 * W4[q + 3];
        s3b[q] += -0.5f * W5[q];
    }
}

// ---------------------------------------------------------------------------
// Faraday fast-path compute.
// ---------------------------------------------------------------------------
__device__ __forceinline__ void faraday_fast_compute(
    const float* __restrict__ e_base, int ebase,
    const float* __restrict__ hx_base, int hxidx,
    const float* __restrict__ hy_base, int hyidx,
    const MCoef& m, float cA, float cB, float cC,
    float* __restrict__ wx0, float* __restrict__ wx1,
    float* __restrict__ wy0, float* __restrict__ wy1)
{
    float s3a[4] = {0, 0, 0, 0}, s3b[4] = {0, 0, 0, 0};
    float s4a[4] = {0, 0, 0, 0}, s4b[4] = {0, 0, 0, 0};

    float hx0[4], hx1[4], hy0[4], hy1[4];
    switch (hxidx & 3) {         // HXW == 0 mod 4
        case 0: load_win_k<4, 0>(hx_base, hxidx, hx0); load_win_k<4, 0>(hx_base, hxidx + HXW, hx1); break;
        case 1: load_win_k<4, 1>(hx_base, hxidx, hx0); load_win_k<4, 1>(hx_base, hxidx + HXW, hx1); break;
        case 2: load_win_k<4, 2>(hx_base, hxidx, hx0); load_win_k<4, 2>(hx_base, hxidx + HXW, hx1); break;
        case 3: load_win_k<4, 3>(hx_base, hxidx, hx0); load_win_k<4, 3>(hx_base, hxidx + HXW, hx1); break;
    }
    switch (hyidx & 3) {         // HYW == 3 mod 4
        case 0: load_win_k<4, 0>(hy_base, hyidx, hy0); load_win_k<4, 3>(hy_base, hyidx + HYW, hy1); break;
        case 1: load_win_k<4, 1>(hy_base, hyidx, hy0); load_win_k<4, 0>(hy_base, hyidx + HYW, hy1); break;
        case 2: load_win_k<4, 2>(hy_base, hyidx, hy0); load_win_k<4, 1>(hy_base, hyidx + HYW, hy1); break;
        case 3: load_win_k<4, 3>(hy_base, hyidx, hy0); load_win_k<4, 2>(hy_base, hyidx + HYW, hy1); break;
    }
    switch (ebase & 3) {
        case 0: faraday_e_sec<0>(e_base, ebase, m, cA, cB, cC, s3a, s3b, s4a, s4b); break;
        case 1: faraday_e_sec<1>(e_base, ebase, m, cA, cB, cC, s3a, s3b, s4a, s4b); break;
        case 2: faraday_e_sec<2>(e_base, ebase, m, cA, cB, cC, s3a, s3b, s4a, s4b); break;
        case 3: faraday_e_sec<3>(e_base, ebase, m, cA, cB, cC, s3a, s3b, s4a, s4b); break;
    }
    #pragma unroll
    for (int q = 0; q < 4; q++) {
        wx0[q] = hx0[q] - CFLF * s3a[q];
        wx1[q] = hx1[q] - CFLF * s3b[q];
        wy0[q] = hy0[q] + CFLF * s4a[q];
        wy1[q] = hy1[q] + CFLF * s4b[q];
    }
}

// ---------------------------------------------------------------------------
// Fused faraday: 2 output rows x 4 cols per thread; 3-tier dispatch.
// ---------------------------------------------------------------------------
__global__ __launch_bounds__(128, 9)
void k_faraday(const float* __restrict__ e_base,  int e_off,
               const float* __restrict__ hx_base, int hx_off,
               const float* __restrict__ hy_base, int hy_off,
               float* __restrict__ out_base,      int hxo_off, int hyo_off)
{
    int t  = blockIdx.x * 32 + threadIdx.x;
    int i0 = (blockIdx.y * blockDim.y + threadIdx.y) * 2;
    if (i0 >= NN) return;                     // warp-uniform
    int b = blockIdx.z;

    const int sF = hxo_off & 3;
    const int j = 4 * t - sF;
    const bool valid = (j + 3 >= 0) && (j < NN);

    MCoef m = load_M();
    const float cA = g_coef[11];
    const float cB = g_coef[12];
    const float cC = g_coef[13];

    const int eb = e_off + b * EN;
    const int xb = hx_off + b * HXN;
    const int yb = hy_off + b * HYN;

    const bool th_fast = valid && (i0 >= 2) && (i0 <= NN - 5) && (j >= 2) && (j <= NN - 7);
    const unsigned bal = __ballot_sync(0xffffffffu, th_fast);

    if (bal == 0xffffffffu) {
        float wx0[4], wx1[4], wy0[4], wy1[4];
        faraday_fast_compute(e_base, eb + (i0 - 1) * EW + j,
                             hx_base, xb + i0 * HXW + j,
                             hy_base, yb + i0 * HYW + j,
                             m, cA, cB, cC, wx0, wx1, wy0, wy1);
        float4 w;
        w.x = wx0[0]; w.y = wx0[1]; w.z = wx0[2]; w.w = wx0[3];
        *reinterpret_cast<float4*>(out_base + hxo_off + b * HXN + i0 * HXW + j) = w;
        w.x = wx1[0]; w.y = wx1[1]; w.z = wx1[2]; w.w = wx1[3];
        *reinterpret_cast<float4*>(out_base + hxo_off + b * HXN + (i0 + 1) * HXW + j) = w;
        warp_store128(out_base, hyo_off + b * HYN + i0 * HYW + j,
                      wy0[0], wy0[1], wy0[2], wy0[3]);
        warp_store128(out_base, hyo_off + b * HYN + (i0 + 1) * HYW + j,
                      wy1[0], wy1[1], wy1[2], wy1[3]);
    } else if (th_fast) {
        float wx0[4], wx1[4], wy0[4], wy1[4];
        faraday_fast_compute(e_base, eb + (i0 - 1) * EW + j,
                             hx_base, xb + i0 * HXW + j,
                             hy_base, yb + i0 * HYW + j,
                             m, cA, cB, cC, wx0, wx1, wy0, wy1);
        float4 w;
        w.x = wx0[0]; w.y = wx0[1]; w.z = wx0[2]; w.w = wx0[3];
        *reinterpret_cast<float4*>(out_base + hxo_off + b * HXN + i0 * HXW + j) = w;
        w.x = wx1[0]; w.y = wx1[1]; w.z = wx1[2]; w.w = wx1[3];
        *reinterpret_cast<float4*>(out_base + hxo_off + b * HXN + (i0 + 1) * HXW + j) = w;
        float* hyw0 = out_base + hyo_off + b * HYN + i0 * HYW + j;
        float* hyw1 = hyw0 + HYW;
        #pragma unroll
        for (int q = 0; q < 4; q++) {
            hyw0[q] = wy0[q];
            hyw1[q] = wy1[q];
        }
    } else if (valid) {
        const float* Eb  = e_base + eb;
        const float* Hxb = hx_base + xb;
        const float* Hyb = hy_base + yb;
        float* Hxob = out_base + hxo_off + b * HXN;
        float* Hyob = out_base + hyo_off + b * HYN;
        #pragma unroll
        for (int r = 0; r < 2; r++) {
            int ii = i0 + r;
            if (ii >= NN) continue;
            #pragma unroll
            for (int q = 0; q < 4; q++) {
                int jj = j + q;
                if (jj < 0 || jj >= NN) continue;
                if (ii < HXH && jj < HXW) {
                    float s3 = faraday_s3(Eb, ii, jj, m);
                    Hxob[ii * HXW + jj] = Hxb[ii * HXW + jj] - CFLF * s3;
                }
                if (ii < HYH && jj < HYW) {
                    float s4 = faraday_s4(Eb, ii, jj, m);
                    Hyob[ii * HYW + jj] = Hyb[ii * HYW + jj] + CFLF * s4;
                }
            }
        }
    }
}

// ---------------------------------------------------------------------------
extern "C" void kernel_launch(void* const* d_in, const int* in_sizes, int n_in,
                              void* d_out, int out_size)
{
    const float* sb = (const float*)d_in[3];
    const float* sd = (const float*)d_in[4];
    const float* sg = (const float*)d_in[5];
    float* out = (float*)d_out;

    const float* e_base  = (const float*)d_in[0]; int e_off  = 0;
    const float* hx_base = (const float*)d_in[1]; int hx_off = 0;
    const float* hy_base = (const float*)d_in[2]; int hy_off = 0;

    const int STEP = BB * (EN + HXN + HYN);

    k_setup<<<1, 1>>>(sb, sd, sg);

    dim3 blk(32, 4, 1);
    dim3 gE(17, (1025 + 3) / 4, BB);   // 1025 row-pairs cover 2049 rows
    dim3 gF(17, 1024 / 4, BB);         // 1024 row-pairs cover 2048 rows

    for (int k = 0; k < 3; k++) {
        int eo_off  = k * STEP;
        int hxo_off = eo_off + BB * EN;
        int hyo_off = hxo_off + BB * HXN;

        k_amper<<<gE, blk>>>(e_base, e_off, hx_base, hx_off, hy_base, hy_off,
                             out, eo_off);
        k_faraday<<<gF, blk>>>(out, eo_off, hx_base, hx_off, hy_base, hy_off,
                               out, hxo_off, hyo_off);

        e_base = out;  e_off  = eo_off;
        hx_base = out; hx_off = hxo_off;
        hy_base = out; hy_off = hyo_off;
    }
}

// round 9
// speedup vs baseline: 1.2172x; 1.1064x over previous
#include <cuda_runtime.h>

// Problem constants (fixed: N=2048, B=2)
#define NN   2048
#define BB   2
#define EW   (NN + 1)            // 2049  (== 1 mod 4)
#define HXH  (NN - 1)            // 2047
#define HXW  (NN)                // 2048  (== 0 mod 4)
#define HYH  (NN)                // 2048
#define HYW  (NN - 1)            // 2047  (== 3 mod 4)
#define EN   (EW * EW)
#define HXN  (HXH * HXW)
#define HYN  (HYH * HYW)
#define CFLF 0.35f

#define KF0 (-11.0f / 6.0f)
#define KF1 (3.0f)
#define KF2 (-1.5f)
#define KF3 (1.0f / 3.0f)
#define KB0 (-1.0f / 3.0f)
#define KB1 (1.5f)
#define KB2 (-3.0f)
#define KB3 (11.0f / 6.0f)

struct MCoef {
    float M00, M01, M02, M03, M11, M20, M21, M22, M23;
};

// Precomputed coefficients, filled once by k_setup:
// [0..8]  M00..M23  [9] cM21KF0  [10] cM02KB3  [11] cA  [12] cB  [13] cC
__device__ float g_coef[16];

__global__ void k_setup(const float* __restrict__ sb,
                        const float* __restrict__ sd,
                        const float* __restrict__ sg)
{
    float beta = *sb, delta = *sd, gamma = *sg;
    float M00 = -0.25f * beta + 0.1f * gamma;
    float M01 =  0.25f * beta + delta - 0.5f - 0.1f * gamma;
    float M02 =  0.25f * beta - 0.1f * gamma;
    float M03 = -0.25f * beta + 0.1f * gamma;
    float M11 = -2.0f * delta;
    float M20 =  0.25f * beta - 0.1f * gamma;
    float M21 = -0.25f * beta + delta + 0.5f + 0.1f * gamma;
    float M22 = -0.25f * beta - 0.1f * gamma;
    float M23 =  0.25f * beta + 0.1f * gamma;
    g_coef[0] = M00;  g_coef[1] = M01;  g_coef[2] = M02;  g_coef[3] = M03;
    g_coef[4] = M11;  g_coef[5] = M20;  g_coef[6] = M21;  g_coef[7] = M22;
    g_coef[8] = M23;
    g_coef[9]  = M21 + KF0;
    g_coef[10] = M02 + KB3;
    g_coef[11] = M02 - 2.0f;
    g_coef[12] = M11 - 1.5f;
    g_coef[13] = M21 + 2.0f;
    g_coef[14] = 0.0f; g_coef[15] = 0.0f;
}

__device__ __forceinline__ MCoef load_M() {
    const float4* cp = reinterpret_cast<const float4*>(g_coef);
    float4 c0 = cp[0], c1 = cp[1], c2 = cp[2];
    MCoef m;
    m.M00 = c0.x; m.M01 = c0.y; m.M02 = c0.z; m.M03 = c0.w;
    m.M11 = c1.x; m.M20 = c1.y; m.M21 = c1.z; m.M22 = c1.w;
    m.M23 = c2.x;
    return m;
}

// ---------------------------------------------------------------------------
// Warp-coalesced store (whole warp must participate).
// ---------------------------------------------------------------------------
__device__ __forceinline__ void warp_store128(float* __restrict__ out, int gi,
                                              float v0, float v1, float v2, float v3)
{
    const unsigned FULL = 0xffffffffu;
    const int lane = threadIdx.x & 31;
    const int s = gi & 3;
    if (s == 0) {
        float4 w; w.x = v0; w.y = v1; w.z = v2; w.w = v3;
        *reinterpret_cast<float4*>(out + gi) = w;
        return;
    }
    float n0 = __shfl_down_sync(FULL, v0, 1);
    float n1 = __shfl_down_sync(FULL, v1, 1);
    float n2 = __shfl_down_sync(FULL, v2, 1);
    if (s == 1) {
        if (lane < 31) {
            float4 w; w.x = v3; w.y = n0; w.z = n1; w.w = n2;
            *reinterpret_cast<float4*>(out + gi + 3) = w;
        }
        if (lane == 0)  { out[gi] = v0; out[gi + 1] = v1; out[gi + 2] = v2; }
        else if (lane == 31) { out[gi + 3] = v3; }
    } else if (s == 2) {
        if (lane < 31) {
            float4 w; w.x = v2; w.y = v3; w.z = n0; w.w = n1;
            *reinterpret_cast<float4*>(out + gi + 2) = w;
        }
        if (lane == 0)  { out[gi] = v0; out[gi + 1] = v1; }
        else if (lane == 31) { out[gi + 2] = v2; out[gi + 3] = v3; }
    } else {
        if (lane < 31) {
            float4 w; w.x = v1; w.y = v2; w.z = v3; w.w = n0;
            *reinterpret_cast<float4*>(out + gi + 1) = w;
        }
        if (lane == 0)  { out[gi] = v0; }
        else if (lane == 31) { out[gi + 1] = v1; out[gi + 2] = v2; out[gi + 3] = v3; }
    }
}

// ---------------------------------------------------------------------------
// Compile-time-skew window load: out[t] = buf[idx+t], requires (idx&3)==K.
// ---------------------------------------------------------------------------
template<int W, int K>
__device__ __forceinline__ void load_win_k(const float* __restrict__ buf, int idx,
                                           float* __restrict__ out)
{
    constexpr int NV = (W + K + 3) / 4;
    const float4* p = reinterpret_cast<const float4*>(buf + (idx - K));
    float f[NV * 4];
    #pragma unroll
    for (int t = 0; t < NV; t++)
        *reinterpret_cast<float4*>(f + 4 * t) = p[t];
    #pragma unroll
    for (int t = 0; t < W; t++) out[t] = f[t + K];
}

// ---------------------------------------------------------------------------
// Generic (boundary) amper point.
// ---------------------------------------------------------------------------
__device__ float amper_point(const float* __restrict__ Hxb,
                             const float* __restrict__ Hyb,
                             int i, int j, const MCoef& m)
{
    float s1 = 0.0f, s2 = 0.0f;
    bool irow = (i >= 2 && i <= NN - 2);
    bool jcol = (j >= 2 && j <= NN - 2);

#define HYv(r, c) Hyb[(r) * HYW + (c)]
#define HXv(r, c) Hxb[(r) * HXW + (c)]
    if (irow && jcol) {
        s1 += m.M00 * HYv(i - 2, j - 2) + m.M20 * HYv(i - 2, j);
        s1 += m.M01 * HYv(i - 1, j - 2) + m.M11 * HYv(i - 1, j - 1) + m.M21 * HYv(i - 1, j);
        s1 += m.M02 * HYv(i,     j - 2) + m.M22 * HYv(i,     j);
        s1 += m.M03 * HYv(i + 1, j - 2) + m.M23 * HYv(i + 1, j);
        s2 += m.M00 * HXv(i - 2, j - 2) + m.M01 * HXv(i - 2, j - 1)
            + m.M02 * HXv(i - 2, j)     + m.M03 * HXv(i - 2, j + 1);
        s2 += m.M11 * HXv(i - 1, j - 1);
        s2 += m.M20 * HXv(i,     j - 2) + m.M21 * HXv(i,     j - 1)
            + m.M22 * HXv(i,     j)     + m.M23 * HXv(i,     j + 1);
    }
    if (i >= 1 && j <= NN - 5) {
        s1 += KF0 * HYv(i - 1, j)     + KF1 * HYv(i - 1, j + 1)
            + KF2 * HYv(i - 1, j + 2) + KF3 * HYv(i - 1, j + 3);
    }
    if (i <= NN - 1 && j >= 5) {
        s1 += KB0 * HYv(i, j - 5) + KB1 * HYv(i, j - 4)
            + KB2 * HYv(i, j - 3) + KB3 * HYv(i, j - 2);
    }
    if (irow && j >= 1 && j <= 2) {
        s1 += -HYv(i - 1, j - 1) + 3.0f * HYv(i - 1, j)
              - 3.0f * HYv(i - 1, j + 1) + HYv(i - 1, j + 2);
    }
    if (irow && j >= NN - 2 && j <= NN - 1) {
        s1 += HYv(i, j - 4) - 3.0f * HYv(i, j - 3)
            + 3.0f * HYv(i, j - 2) - HYv(i, j - 1);
    }
    if (j >= 1 && i <= NN - 5) {
        s2 += KF0 * HXv(i, j - 1)     + KF1 * HXv(i + 1, j - 1)
            + KF2 * HXv(i + 2, j - 1) + KF3 * HXv(i + 3, j - 1);
    }
    if (j <= NN - 1 && i >= 5) {
        s2 += KB0 * HXv(i - 5, j) + KB1 * HXv(i - 4, j)
            + KB2 * HXv(i - 3, j) + KB3 * HXv(i - 2, j);
    }
    if (jcol && i >= 1 && i <= 2) {
        s2 += -HXv(i - 1, j - 1) + 3.0f * HXv(i, j - 1)
              - 3.0f * HXv(i + 1, j - 1) + HXv(i + 2, j - 1);
    }
    if (jcol && i >= NN - 2 && i <= NN - 1) {
        s2 += HXv(i - 4, j) - 3.0f * HXv(i - 3, j)
            + 3.0f * HXv(i - 2, j) - HXv(i - 1, j);
    }
#undef HYv
#undef HXv
    return s1 - s2;
}

// ---------------------------------------------------------------------------
// Amper Hy section (rows i0-2 .. i0+2), 2 output rows. KY = skew of base.
// ---------------------------------------------------------------------------
template<int KY>
__device__ __forceinline__ void amper_hy_sec(const float* __restrict__ hy, int base,
                                             const MCoef& m, float cM21KF0, float cM02KB3,
                                             float* __restrict__ s1a, float* __restrict__ s1b)
{
    float Y0[6], Y1[9], Y2[12], Y3[9], Y4[6];
    load_win_k<6,  KY          >(hy, base, Y0);
    load_win_k<9,  (KY + 3) & 3>(hy, base + HYW, Y1);
    load_win_k<12, (KY + 3) & 3>(hy, base + 2 * HYW - 3, Y2);
    load_win_k<9,  (KY + 2) & 3>(hy, base + 3 * HYW - 3, Y3);
    load_win_k<6,  KY          >(hy, base + 4 * HYW, Y4);

    #pragma unroll
    for (int q = 0; q < 4; q++) {
        s1a[q] += m.M00 * Y0[q] + m.M20 * Y0[q + 2];
        s1a[q] += m.M01 * Y1[q] + m.M11 * Y1[q + 1] + cM21KF0 * Y1[q + 2]
                + KF1 * Y1[q + 3] + KF2 * Y1[q + 4] + KF3 * Y1[q + 5];
        s1b[q] += m.M00 * Y1[q] + m.M20 * Y1[q + 2];
        s1a[q] += KB0 * Y2[q] + KB1 * Y2[q + 1] + KB2 * Y2[q + 2]
                + cM02KB3 * Y2[q + 3] + m.M22 * Y2[q + 5];
        s1b[q] += m.M01 * Y2[q + 3] + m.M11 * Y2[q + 4] + cM21KF0 * Y2[q + 5]
                + KF1 * Y2[q + 6] + KF2 * Y2[q + 7] + KF3 * Y2[q + 8];
        s1a[q] += m.M03 * Y3[q + 3] + m.M23 * Y3[q + 5];
        s1b[q] += KB0 * Y3[q] + KB1 * Y3[q + 1] + KB2 * Y3[q + 2]
                + cM02KB3 * Y3[q + 3] + m.M22 * Y3[q + 5];
        s1b[q] += m.M03 * Y4[q] + m.M23 * Y4[q + 2];
    }
}

// ---------------------------------------------------------------------------
// Amper Hx section (rows i0-5 .. i0+4), 2 output rows. KX = skew of base.
// ---------------------------------------------------------------------------
template<int KX>
__device__ __forceinline__ void amper_hx_sec(const float* __restrict__ hx, int base,
                                             const MCoef& m, float cM21KF0, float cM02KB3,
                                             float* __restrict__ s2a, float* __restrict__ s2b)
{
    float X0[4], X1[4], X2[4], X3[7], X4[7], X5[7], X6[7], X7[4], X8[4], X9[4];
    load_win_k<4, KX          >(hx, base, X0);
    load_win_k<4, KX          >(hx, base + HXW, X1);
    load_win_k<4, KX          >(hx, base + 2 * HXW, X2);
    load_win_k<7, (KX + 2) & 3>(hx, base + 3 * HXW - 2, X3);
    load_win_k<7, (KX + 2) & 3>(hx, base + 4 * HXW - 2, X4);
    load_win_k<7, (KX + 2) & 3>(hx, base + 5 * HXW - 2, X5);
    load_win_k<7, (KX + 2) & 3>(hx, base + 6 * HXW - 2, X6);
    load_win_k<4, (KX + 3) & 3>(hx, base + 7 * HXW - 1, X7);
    load_win_k<4, (KX + 3) & 3>(hx, base + 8 * HXW - 1, X8);
    load_win_k<4, (KX + 3) & 3>(hx, base + 9 * HXW - 1, X9);

    #pragma unroll
    for (int q = 0; q < 4; q++) {
        s2a[q] += KB0 * X0[q] + KB1 * X1[q] + KB2 * X2[q];
        s2b[q] += KB0 * X1[q] + KB1 * X2[q];
        s2a[q] += m.M00 * X3[q] + m.M01 * X3[q + 1] + cM02KB3 * X3[q + 2] + m.M03 * X3[q + 3];
        s2b[q] += KB2 * X3[q + 2];
        s2a[q] += m.M11 * X4[q + 1];
        s2b[q] += m.M00 * X4[q] + m.M01 * X4[q + 1] + cM02KB3 * X4[q + 2] + m.M03 * X4[q + 3];
        s2a[q] += m.M20 * X5[q] + cM21KF0 * X5[q + 1] + m.M22 * X5[q + 2] + m.M23 * X5[q + 3];
        s2b[q] += m.M11 * X5[q + 1];
        s2a[q] += KF1 * X6[q + 1];
        s2b[q] += m.M20 * X6[q] + cM21KF0 * X6[q + 1] + m.M22 * X6[q + 2] + m.M23 * X6[q + 3];
        s2a[q] += KF2 * X7[q] + KF3 * X8[q];
        s2b[q] += KF1 * X7[q] + KF2 * X8[q] + KF3 * X9[q];
    }
}

// ---------------------------------------------------------------------------
// Amper MAIN: interior-only, 2 output rows x 4 cols per thread.
// ---------------------------------------------------------------------------
__global__ __launch_bounds__(128, 9)
void k_amper(const float* __restrict__ e_base,  int e_off,
             const float* __restrict__ hx_base, int hx_off,
             const float* __restrict__ hy_base, int hy_off,
             float* __restrict__ out_base,      int eo_off)
{
    int t  = blockIdx.x * 32 + threadIdx.x;
    int i0 = (blockIdx.y * 4 + threadIdx.y) * 2;
    if (i0 < 5 || i0 > NN - 6) return;        // warp-uniform
    int b = blockIdx.z;

    const int erow0 = eo_off + b * EN + i0 * EW;
    const int s = erow0 & 3;
    const int j = 4 * t - s;
    const bool fast = (j >= 5) && (j <= NN - 8);
    const unsigned bal = __ballot_sync(0xffffffffu, fast);
    if (!fast) return;

    MCoef m = load_M();
    const float cM21KF0 = g_coef[9];
    const float cM02KB3 = g_coef[10];

    const int xb = hx_off + b * HXN;
    const int yb = hy_off + b * HYN;

    float s1a[4] = {0, 0, 0, 0}, s1b[4] = {0, 0, 0, 0};
    float s2a[4] = {0, 0, 0, 0}, s2b[4] = {0, 0, 0, 0};

    float E0[4], E1[4];
    const int eidx = e_off + b * EN + i0 * EW + j;
    switch (eidx & 3) {
        case 0: load_win_k<4, 0>(e_base, eidx, E0); load_win_k<4, 1>(e_base, eidx + EW, E1); break;
        case 1: load_win_k<4, 1>(e_base, eidx, E0); load_win_k<4, 2>(e_base, eidx + EW, E1); break;
        case 2: load_win_k<4, 2>(e_base, eidx, E0); load_win_k<4, 3>(e_base, eidx + EW, E1); break;
        case 3: load_win_k<4, 3>(e_base, eidx, E0); load_win_k<4, 0>(e_base, eidx + EW, E1); break;
    }

    const int ybase = yb + (i0 - 2) * HYW + (j - 2);
    switch (ybase & 3) {
        case 0: amper_hy_sec<0>(hy_base, ybase, m, cM21KF0, cM02KB3, s1a, s1b); break;
        case 1: amper_hy_sec<1>(hy_base, ybase, m, cM21KF0, cM02KB3, s1a, s1b); break;
        case 2: amper_hy_sec<2>(hy_base, ybase, m, cM21KF0, cM02KB3, s1a, s1b); break;
        case 3: amper_hy_sec<3>(hy_base, ybase, m, cM21KF0, cM02KB3, s1a, s1b); break;
    }

    const int xbase = xb + (i0 - 5) * HXW + j;
    switch (xbase & 3) {
        case 0: amper_hx_sec<0>(hx_base, xbase, m, cM21KF0, cM02KB3, s2a, s2b); break;
        case 1: amper_hx_sec<1>(hx_base, xbase, m, cM21KF0, cM02KB3, s2a, s2b); break;
        case 2: amper_hx_sec<2>(hx_base, xbase, m, cM21KF0, cM02KB3, s2a, s2b); break;
        case 3: amper_hx_sec<3>(hx_base, xbase, m, cM21KF0, cM02KB3, s2a, s2b); break;
    }

    float4 w;
    w.x = E0[0] + CFLF * (s1a[0] - s2a[0]);
    w.y = E0[1] + CFLF * (s1a[1] - s2a[1]);
    w.z = E0[2] + CFLF * (s1a[2] - s2a[2]);
    w.w = E0[3] + CFLF * (s1a[3] - s2a[3]);
    *reinterpret_cast<float4*>(out_base + erow0 + j) = w;   // aligned by construction

    float r1_0 = E1[0] + CFLF * (s1b[0] - s2b[0]);
    float r1_1 = E1[1] + CFLF * (s1b[1] - s2b[1]);
    float r1_2 = E1[2] + CFLF * (s1b[2] - s2b[2]);
    float r1_3 = E1[3] + CFLF * (s1b[3] - s2b[3]);
    if (bal == 0xffffffffu) {
        warp_store128(out_base, erow0 + EW + j, r1_0, r1_1, r1_2, r1_3);
    } else {
        float* p1 = out_base + erow0 + EW + j;
        p1[0] = r1_0; p1[1] = r1_1; p1[2] = r1_2; p1[3] = r1_3;
    }
}

// ---------------------------------------------------------------------------
// Amper BORDER: per-point generic, complement of main's coverage.
// Regions: R0 rows[0,5]x2049, R1 rows[2044,2048]x2049,
//          R2 rows[6,2043]xcols[0,7], R3 rows[6,2043]xcols[2038,2048]
// ---------------------------------------------------------------------------
#define AB_R0 12294               // 6*2049
#define AB_R1 10245               // 5*2049
#define AB_R2 16304               // 2038*8
#define AB_R3 22418               // 2038*11
#define AB_N  (AB_R0 + AB_R1 + AB_R2 + AB_R3)   // 61261

__global__ void k_amper_border(const float* __restrict__ e_base,  int e_off,
                               const float* __restrict__ hx_base, int hx_off,
                               const float* __restrict__ hy_base, int hy_off,
                               float* __restrict__ out_base,      int eo_off)
{
    int idx = blockIdx.x * blockDim.x + threadIdx.x;
    int b = blockIdx.y;
    if (idx >= AB_N) return;
    int i, j;
    if (idx < AB_R0) { i = idx / EW; j = idx % EW; }
    else if (idx < AB_R0 + AB_R1) { int r = idx - AB_R0; i = 2044 + r / EW; j = r % EW; }
    else if (idx < AB_R0 + AB_R1 + AB_R2) { int r = idx - (AB_R0 + AB_R1); i = 6 + r / 8; j = r % 8; }
    else { int r = idx - (AB_R0 + AB_R1 + AB_R2); i = 6 + r / 11; j = 2038 + r % 11; }

    int i0 = i & ~1;
    int s = (eo_off + b * EN + i0 * EW) & 3;
    int js = j - ((j + s) & 3);
    if (i0 >= 5 && i0 <= NN - 6 && js >= 5 && js <= NN - 8) return;  // main covered it

    MCoef m = load_M();
    const float* Hxb = hx_base + hx_off + b * HXN;
    const float* Hyb = hy_base + hy_off + b * HYN;
    float d = amper_point(Hxb, Hyb, i, j, m);
    out_base[eo_off + b * EN + i * EW + j] =
        e_base[e_off + b * EN + i * EW + j] + CFLF * d;
}

// ---------------------------------------------------------------------------
// Generic faraday point helpers
// ---------------------------------------------------------------------------
__device__ float faraday_s3(const float* __restrict__ Eb, int i, int j, const MCoef& m)
{
#define Ev(r, c) Eb[(r) * EW + (c)]
    float s3 = 0.0f;
    if (j >= 1 && j <= NN - 2) {
        s3 += m.M00 * Ev(i,     j - 1) + m.M01 * Ev(i,     j)
            + m.M02 * Ev(i,     j + 1) + m.M03 * Ev(i,     j + 2);
        s3 += m.M11 * Ev(i + 1, j);
        s3 += m.M20 * Ev(i + 2, j - 1) + m.M21 * Ev(i + 2, j)
            + m.M22 * Ev(i + 2, j + 1) + m.M23 * Ev(i + 2, j + 2);
    }
    if (i <= NN - 4)
        s3 += -1.5f * Ev(i + 1, j) + 2.0f * Ev(i + 2, j) - 0.5f * Ev(i + 3, j);
    if (i >= 2)
        s3 += 0.5f * Ev(i - 1, j + 1) - 2.0f * Ev(i, j + 1) + 1.5f * Ev(i + 1, j + 1);
#undef Ev
    return s3;
}

__device__ float faraday_s4(const float* __restrict__ Eb, int i, int j, const MCoef& m)
{
#define Ev(r, c) Eb[(r) * EW + (c)]
    float s4 = 0.0f;
    if (i >= 1 && i <= NN - 2) {
        s4 += m.M00 * Ev(i - 1, j) + m.M20 * Ev(i - 1, j + 2);
        s4 += m.M01 * Ev(i,     j) + m.M11 * Ev(i, j + 1) + m.M21 * Ev(i, j + 2);
        s4 += m.M02 * Ev(i + 1, j) + m.M22 * Ev(i + 1, j + 2);
        s4 += m.M03 * Ev(i + 2, j) + m.M23 * Ev(i + 2, j + 2);
    }
    if (j <= NN - 4)
        s4 += -1.5f * Ev(i, j + 1) + 2.0f * Ev(i, j + 2) - 0.5f * Ev(i, j + 3);
    if (j >= 2)
        s4 += 0.5f * Ev(i + 1, j - 1) - 2.0f * Ev(i + 1, j) + 1.5f * Ev(i + 1, j + 1);
#undef Ev
    return s4;
}

// ---------------------------------------------------------------------------
// Faraday E section (rows i0-1 .. i0+4), 2 output rows. KE = skew of base.
// ---------------------------------------------------------------------------
template<int KE>
__device__ __forceinline__ void faraday_e_sec(const float* __restrict__ e, int base,
                                              const MCoef& m, float cA, float cB, float cC,
                                              float* __restrict__ s3a, float* __restrict__ s3b,
                                              float* __restrict__ s4a, float* __restrict__ s4b)
{
    float W0[6], W1[8], W2[8], W3[7], W4[7], W5[4];
    load_win_k<6, KE          >(e, base, W0);
    load_win_k<8, KE          >(e, base + EW - 1, W1);
    load_win_k<8, (KE + 1) & 3>(e, base + 2 * EW - 1, W2);
    load_win_k<7, (KE + 2) & 3>(e, base + 3 * EW - 1, W3);
    load_win_k<7, (KE + 3) & 3>(e, base + 4 * EW - 1, W4);
    load_win_k<4, (KE + 1) & 3>(e, base + 5 * EW, W5);

    #pragma unroll
    for (int q = 0; q < 4; q++) {
        s3a[q] += 0.5f * W0[q + 1];
        s4a[q] += m.M00 * W0[q] + m.M20 * W0[q + 2];
        s3a[q] += m.M00 * W1[q] + m.M01 * W1[q + 1] + cA * W1[q + 2] + m.M03 * W1[q + 3];
        s4a[q] += m.M01 * W1[q + 1] + cB * W1[q + 2] + cC * W1[q + 3] - 0.5f * W1[q + 4];
        s3b[q] += 0.5f * W1[q + 2];
        s4b[q] += m.M00 * W1[q + 1] + m.M20 * W1[q + 3];
        s3a[q] += cB * W2[q + 1] + 1.5f * W2[q + 2];
        s4a[q] += 0.5f * W2[q] + cA * W2[q + 1] + 1.5f * W2[q + 2] + m.M22 * W2[q + 3];
        s3b[q] += m.M00 * W2[q] + m.M01 * W2[q + 1] + cA * W2[q + 2] + m.M03 * W2[q + 3];
        s4b[q] += m.M01 * W2[q + 1] + cB * W2[q + 2] + cC * W2[q + 3] - 0.5f * W2[q + 4];
        s3a[q] += m.M20 * W3[q] + cC * W3[q + 1] + m.M22 * W3[q + 2] + m.M23 * W3[q + 3];
        s4a[q] += m.M03 * W3[q + 1] + m.M23 * W3[q + 3];
        s3b[q] += cB * W3[q + 1] + 1.5f * W3[q + 2];
        s4b[q] += 0.5f * W3[q] + cA * W3[q + 1] + 1.5f * W3[q + 2] + m.M22 * W3[q + 3];
        s3a[q] += -0.5f * W4[q + 1];
        s3b[q] += m.M20 * W4[q] + cC * W4[q + 1] + m.M22 * W4[q + 2] + m.M23 * W4[q + 3];
        s4b[q] += m.M03 * W4[q + 1] + m.M23 * W4[q + 3];
        s3b[q] += -0.5f * W5[q];
    }
}

// ---------------------------------------------------------------------------
// Faraday MAIN: interior-only, 2 output rows x 4 cols per thread.
// ---------------------------------------------------------------------------
__global__ __launch_bounds__(128, 9)
void k_faraday(const float* __restrict__ e_base,  int e_off,
               const float* __restrict__ hx_base, int hx_off,
               const float* __restrict__ hy_base, int hy_off,
               float* __restrict__ out_base,      int hxo_off, int hyo_off)
{
    int t  = blockIdx.x * 32 + threadIdx.x;
    int i0 = (blockIdx.y * 4 + threadIdx.y) * 2;
    if (i0 < 2 || i0 > NN - 5) return;        // warp-uniform
    int b = blockIdx.z;

    const int sF = hxo_off & 3;
    const int j = 4 * t - sF;
    const bool fast = (j >= 2) && (j <= NN - 7);
    const unsigned bal = __ballot_sync(0xffffffffu, fast);
    if (!fast) return;

    MCoef m = load_M();
    const float cA = g_coef[11];
    const float cB = g_coef[12];
    const float cC = g_coef[13];

    const int eb = e_off + b * EN;
    const int xb = hx_off + b * HXN;
    const int yb = hy_off + b * HYN;

    float s3a[4] = {0, 0, 0, 0}, s3b[4] = {0, 0, 0, 0};
    float s4a[4] = {0, 0, 0, 0}, s4b[4] = {0, 0, 0, 0};

    float hx0[4], hx1[4], hy0[4], hy1[4];
    const int hxidx = xb + i0 * HXW + j;      // HXW == 0 mod 4
    switch (hxidx & 3) {
        case 0: load_win_k<4, 0>(hx_base, hxidx, hx0); load_win_k<4, 0>(hx_base, hxidx + HXW, hx1); break;
        case 1: load_win_k<4, 1>(hx_base, hxidx, hx0); load_win_k<4, 1>(hx_base, hxidx + HXW, hx1); break;
        case 2: load_win_k<4, 2>(hx_base, hxidx, hx0); load_win_k<4, 2>(hx_base, hxidx + HXW, hx1); break;
        case 3: load_win_k<4, 3>(hx_base, hxidx, hx0); load_win_k<4, 3>(hx_base, hxidx + HXW, hx1); break;
    }
    const int hyidx = yb + i0 * HYW + j;      // HYW == 3 mod 4
    switch (hyidx & 3) {
        case 0: load_win_k<4, 0>(hy_base, hyidx, hy0); load_win_k<4, 3>(hy_base, hyidx + HYW, hy1); break;
        case 1: load_win_k<4, 1>(hy_base, hyidx, hy0); load_win_k<4, 0>(hy_base, hyidx + HYW, hy1); break;
        case 2: load_win_k<4, 2>(hy_base, hyidx, hy0); load_win_k<4, 1>(hy_base, hyidx + HYW, hy1); break;
        case 3: load_win_k<4, 3>(hy_base, hyidx, hy0); load_win_k<4, 2>(hy_base, hyidx + HYW, hy1); break;
    }
    const int ebase = eb + (i0 - 1) * EW + j;
    switch (ebase & 3) {
        case 0: faraday_e_sec<0>(e_base, ebase, m, cA, cB, cC, s3a, s3b, s4a, s4b); break;
        case 1: faraday_e_sec<1>(e_base, ebase, m, cA, cB, cC, s3a, s3b, s4a, s4b); break;
        case 2: faraday_e_sec<2>(e_base, ebase, m, cA, cB, cC, s3a, s3b, s4a, s4b); break;
        case 3: faraday_e_sec<3>(e_base, ebase, m, cA, cB, cC, s3a, s3b, s4a, s4b); break;
    }

    float4 w;
    w.x = hx0[0] - CFLF * s3a[0];
    w.y = hx0[1] - CFLF * s3a[1];
    w.z = hx0[2] - CFLF * s3a[2];
    w.w = hx0[3] - CFLF * s3a[3];
    *reinterpret_cast<float4*>(out_base + hxo_off + b * HXN + i0 * HXW + j) = w;
    w.x = hx1[0] - CFLF * s3b[0];
    w.y = hx1[1] - CFLF * s3b[1];
    w.z = hx1[2] - CFLF * s3b[2];
    w.w = hx1[3] - CFLF * s3b[3];
    *reinterpret_cast<float4*>(out_base + hxo_off + b * HXN + (i0 + 1) * HXW + j) = w;

    float wy00 = hy0[0] + CFLF * s4a[0];
    float wy01 = hy0[1] + CFLF * s4a[1];
    float wy02 = hy0[2] + CFLF * s4a[2];
    float wy03 = hy0[3] + CFLF * s4a[3];
    float wy10 = hy1[0] + CFLF * s4b[0];
    float wy11 = hy1[1] + CFLF * s4b[1];
    float wy12 = hy1[2] + CFLF * s4b[2];
    float wy13 = hy1[3] + CFLF * s4b[3];
    if (bal == 0xffffffffu) {
        warp_store128(out_base, hyo_off + b * HYN + i0 * HYW + j, wy00, wy01, wy02, wy03);
        warp_store128(out_base, hyo_off + b * HYN + (i0 + 1) * HYW + j, wy10, wy11, wy12, wy13);
    } else {
        float* p0 = out_base + hyo_off + b * HYN + i0 * HYW + j;
        float* p1 = p0 + HYW;
        p0[0] = wy00; p0[1] = wy01; p0[2] = wy02; p0[3] = wy03;
        p1[0] = wy10; p1[1] = wy11; p1[2] = wy12; p1[3] = wy13;
    }
}

// ---------------------------------------------------------------------------
// Faraday BORDER: per-point generic, complement of main's coverage.
// Regions: R0 rows[0,1]x2048, R1 rows[2044,2047]x2048,
//          R2 rows[2,2043]xcols[0,4], R3 rows[2,2043]xcols[2039,2047]
// ---------------------------------------------------------------------------
#define FB_R0 4096                // 2*2048
#define FB_R1 8192                // 4*2048
#define FB_R2 10210               // 2042*5
#define FB_R3 18378               // 2042*9
#define FB_N  (FB_R0 + FB_R1 + FB_R2 + FB_R3)   // 40876

__global__ void k_faraday_border(const float* __restrict__ e_base,  int e_off,
                                 const float* __restrict__ hx_base, int hx_off,
                                 const float* __restrict__ hy_base, int hy_off,
                                 float* __restrict__ out_base,      int hxo_off, int hyo_off)
{
    int idx = blockIdx.x * blockDim.x + threadIdx.x;
    int b = blockIdx.y;
    if (idx >= FB_N) return;
    int i, j;
    if (idx < FB_R0) { i = idx / NN; j = idx % NN; }
    else if (idx < FB_R0 + FB_R1) { int r = idx - FB_R0; i = 2044 + r / NN; j = r % NN; }
    else if (idx < FB_R0 + FB_R1 + FB_R2) { int r = idx - (FB_R0 + FB_R1); i = 2 + r / 5; j = r % 5; }
    else { int r = idx - (FB_R0 + FB_R1 + FB_R2); i = 2 + r / 9; j = 2039 + r % 9; }

    int i0 = i & ~1;
    int sF = hxo_off & 3;
    int js = j - ((j + sF) & 3);
    if (i0 >= 2 && i0 <= NN - 5 && js >= 2 && js <= NN - 7) return;  // main covered it

    MCoef m = load_M();
    const float* Eb  = e_base + e_off + b * EN;
    const float* Hxb = hx_base + hx_off + b * HXN;
    const float* Hyb = hy_base + hy_off + b * HYN;
    float* Hxob = out_base + hxo_off + b * HXN;
    float* Hyob = out_base + hyo_off + b * HYN;

    if (i < HXH && j < HXW) {
        float s3 = faraday_s3(Eb, i, j, m);
        Hxob[i * HXW + j] = Hxb[i * HXW + j] - CFLF * s3;
    }
    if (i < HYH && j < HYW) {
        float s4 = faraday_s4(Eb, i, j, m);
        Hyob[i * HYW + j] = Hyb[i * HYW + j] + CFLF * s4;
    }
}

// ---------------------------------------------------------------------------
extern "C" void kernel_launch(void* const* d_in, const int* in_sizes, int n_in,
                              void* d_out, int out_size)
{
    const float* sb = (const float*)d_in[3];
    const float* sd = (const float*)d_in[4];
    const float* sg = (const float*)d_in[5];
    float* out = (float*)d_out;

    const float* e_base  = (const float*)d_in[0]; int e_off  = 0;
    const float* hx_base = (const float*)d_in[1]; int hx_off = 0;
    const float* hy_base = (const float*)d_in[2]; int hy_off = 0;

    const int STEP = BB * (EN + HXN + HYN);

    k_setup<<<1, 1>>>(sb, sd, sg);

    dim3 blk(32, 4, 1);
    dim3 gMain(16, 256, BB);                  // strips t<512, row-pairs <2048
    dim3 gAB((AB_N + 255) / 256, BB, 1);
    dim3 gFB((FB_N + 255) / 256, BB, 1);

    for (int k = 0; k < 3; k++) {
        int eo_off  = k * STEP;
        int hxo_off = eo_off + BB * EN;
        int hyo_off = hxo_off + BB * HXN;

        k_amper<<<gMain, blk>>>(e_base, e_off, hx_base, hx_off, hy_base, hy_off,
                                out, eo_off);
        k_amper_border<<<gAB, 256>>>(e_base, e_off, hx_base, hx_off, hy_base, hy_off,
                                     out, eo_off);
        k_faraday<<<gMain, blk>>>(out, eo_off, hx_base, hx_off, hy_base, hy_off,
                                  out, hxo_off, hyo_off);
        k_faraday_border<<<gFB, 256>>>(out, eo_off, hx_base, hx_off, hy_base, hy_off,
                                       out, hxo_off, hyo_off);

        e_base = out;  e_off  = eo_off;
        hx_base = out; hx_off = hxo_off;
        hy_base = out; hy_off = hyo_off;
    }
}

// round 11
// speedup vs baseline: 1.3517x; 1.1104x over previous
#include <cuda_runtime.h>

// Problem constants (fixed: N=2048, B=2)
#define NN   2048
#define BB   2
#define EW   (NN + 1)            // 2049  (== 1 mod 4)
#define HXH  (NN - 1)            // 2047
#define HXW  (NN)                // 2048  (== 0 mod 4)
#define HYH  (NN)                // 2048
#define HYW  (NN - 1)            // 2047  (== 3 mod 4)
#define EN   (EW * EW)
#define HXN  (HXH * HXW)
#define HYN  (HYH * HYW)
#define CFLF 0.35f

#define KF0 (-11.0f / 6.0f)
#define KF1 (3.0f)
#define KF2 (-1.5f)
#define KF3 (1.0f / 3.0f)
#define KB0 (-1.0f / 3.0f)
#define KB1 (1.5f)
#define KB2 (-3.0f)
#define KB3 (11.0f / 6.0f)

struct MCoef {
    float M00, M01, M02, M03, M11, M20, M21, M22, M23;
};

// Precomputed coefficients, filled once by k_setup:
// [0..8]  M00..M23  [9] cM21KF0  [10] cM02KB3  [11] cA  [12] cB  [13] cC
__device__ float g_coef[16];

__global__ void k_setup(const float* __restrict__ sb,
                        const float* __restrict__ sd,
                        const float* __restrict__ sg)
{
    float beta = *sb, delta = *sd, gamma = *sg;
    float M00 = -0.25f * beta + 0.1f * gamma;
    float M01 =  0.25f * beta + delta - 0.5f - 0.1f * gamma;
    float M02 =  0.25f * beta - 0.1f * gamma;
    float M03 = -0.25f * beta + 0.1f * gamma;
    float M11 = -2.0f * delta;
    float M20 =  0.25f * beta - 0.1f * gamma;
    float M21 = -0.25f * beta + delta + 0.5f + 0.1f * gamma;
    float M22 = -0.25f * beta - 0.1f * gamma;
    float M23 =  0.25f * beta + 0.1f * gamma;
    g_coef[0] = M00;  g_coef[1] = M01;  g_coef[2] = M02;  g_coef[3] = M03;
    g_coef[4] = M11;  g_coef[5] = M20;  g_coef[6] = M21;  g_coef[7] = M22;
    g_coef[8] = M23;
    g_coef[9]  = M21 + KF0;
    g_coef[10] = M02 + KB3;
    g_coef[11] = M02 - 2.0f;
    g_coef[12] = M11 - 1.5f;
    g_coef[13] = M21 + 2.0f;
    g_coef[14] = 0.0f; g_coef[15] = 0.0f;
}

__device__ __forceinline__ MCoef load_M() {
    const float4* cp = reinterpret_cast<const float4*>(g_coef);
    float4 c0 = cp[0], c1 = cp[1], c2 = cp[2];
    MCoef m;
    m.M00 = c0.x; m.M01 = c0.y; m.M02 = c0.z; m.M03 = c0.w;
    m.M11 = c1.x; m.M20 = c1.y; m.M21 = c1.z; m.M22 = c1.w;
    m.M23 = c2.x;
    return m;
}

// ---------------------------------------------------------------------------
// Warp-coalesced store (whole warp must participate).
// ---------------------------------------------------------------------------
__device__ __forceinline__ void warp_store128(float* __restrict__ out, int gi,
                                              float v0, float v1, float v2, float v3)
{
    const unsigned FULL = 0xffffffffu;
    const int lane = threadIdx.x & 31;
    const int s = gi & 3;
    if (s == 0) {
        float4 w; w.x = v0; w.y = v1; w.z = v2; w.w = v3;
        *reinterpret_cast<float4*>(out + gi) = w;
        return;
    }
    float n0 = __shfl_down_sync(FULL, v0, 1);
    float n1 = __shfl_down_sync(FULL, v1, 1);
    float n2 = __shfl_down_sync(FULL, v2, 1);
    if (s == 1) {
        if (lane < 31) {
            float4 w; w.x = v3; w.y = n0; w.z = n1; w.w = n2;
            *reinterpret_cast<float4*>(out + gi + 3) = w;
        }
        if (lane == 0)  { out[gi] = v0; out[gi + 1] = v1; out[gi + 2] = v2; }
        else if (lane == 31) { out[gi + 3] = v3; }
    } else if (s == 2) {
        if (lane < 31) {
            float4 w; w.x = v2; w.y = v3; w.z = n0; w.w = n1;
            *reinterpret_cast<float4*>(out + gi + 2) = w;
        }
        if (lane == 0)  { out[gi] = v0; out[gi + 1] = v1; }
        else if (lane == 31) { out[gi + 2] = v2; out[gi + 3] = v3; }
    } else {
        if (lane < 31) {
            float4 w; w.x = v1; w.y = v2; w.z = v3; w.w = n0;
            *reinterpret_cast<float4*>(out + gi + 1) = w;
        }
        if (lane == 0)  { out[gi] = v0; }
        else if (lane == 31) { out[gi + 1] = v1; out[gi + 2] = v2; out[gi + 3] = v3; }
    }
}

// ---------------------------------------------------------------------------
// Compile-time-skew window load: out[t] = buf[idx+t], requires (idx&3)==K.
// ---------------------------------------------------------------------------
template<int W, int K>
__device__ __forceinline__ void load_win_k(const float* __restrict__ buf, int idx,
                                           float* __restrict__ out)
{
    constexpr int NV = (W + K + 3) / 4;
    const float4* p = reinterpret_cast<const float4*>(buf + (idx - K));
    float f[NV * 4];
    #pragma unroll
    for (int t = 0; t < NV; t++)
        *reinterpret_cast<float4*>(f + 4 * t) = p[t];
    #pragma unroll
    for (int t = 0; t < W; t++) out[t] = f[t + K];
}

// ---------------------------------------------------------------------------
// Generic (boundary) amper point.
// ---------------------------------------------------------------------------
__device__ float amper_point(const float* __restrict__ Hxb,
                             const float* __restrict__ Hyb,
                             int i, int j, const MCoef& m)
{
    float s1 = 0.0f, s2 = 0.0f;
    bool irow = (i >= 2 && i <= NN - 2);
    bool jcol = (j >= 2 && j <= NN - 2);

#define HYv(r, c) Hyb[(r) * HYW + (c)]
#define HXv(r, c) Hxb[(r) * HXW + (c)]
    if (irow && jcol) {
        s1 += m.M00 * HYv(i - 2, j - 2) + m.M20 * HYv(i - 2, j);
        s1 += m.M01 * HYv(i - 1, j - 2) + m.M11 * HYv(i - 1, j - 1) + m.M21 * HYv(i - 1, j);
        s1 += m.M02 * HYv(i,     j - 2) + m.M22 * HYv(i,     j);
        s1 += m.M03 * HYv(i + 1, j - 2) + m.M23 * HYv(i + 1, j);
        s2 += m.M00 * HXv(i - 2, j - 2) + m.M01 * HXv(i - 2, j - 1)
            + m.M02 * HXv(i - 2, j)     + m.M03 * HXv(i - 2, j + 1);
        s2 += m.M11 * HXv(i - 1, j - 1);
        s2 += m.M20 * HXv(i,     j - 2) + m.M21 * HXv(i,     j - 1)
            + m.M22 * HXv(i,     j)     + m.M23 * HXv(i,     j + 1);
    }
    if (i >= 1 && j <= NN - 5) {
        s1 += KF0 * HYv(i - 1, j)     + KF1 * HYv(i - 1, j + 1)
            + KF2 * HYv(i - 1, j + 2) + KF3 * HYv(i - 1, j + 3);
    }
    if (i <= NN - 1 && j >= 5) {
        s1 += KB0 * HYv(i, j - 5) + KB1 * HYv(i, j - 4)
            + KB2 * HYv(i, j - 3) + KB3 * HYv(i, j - 2);
    }
    if (irow && j >= 1 && j <= 2) {
        s1 += -HYv(i - 1, j - 1) + 3.0f * HYv(i - 1, j)
              - 3.0f * HYv(i - 1, j + 1) + HYv(i - 1, j + 2);
    }
    if (irow && j >= NN - 2 && j <= NN - 1) {
        s1 += HYv(i, j - 4) - 3.0f * HYv(i, j - 3)
            + 3.0f * HYv(i, j - 2) - HYv(i, j - 1);
    }
    if (j >= 1 && i <= NN - 5) {
        s2 += KF0 * HXv(i, j - 1)     + KF1 * HXv(i + 1, j - 1)
            + KF2 * HXv(i + 2, j - 1) + KF3 * HXv(i + 3, j - 1);
    }
    if (j <= NN - 1 && i >= 5) {
        s2 += KB0 * HXv(i - 5, j) + KB1 * HXv(i - 4, j)
            + KB2 * HXv(i - 3, j) + KB3 * HXv(i - 2, j);
    }
    if (jcol && i >= 1 && i <= 2) {
        s2 += -HXv(i - 1, j - 1) + 3.0f * HXv(i, j - 1)
              - 3.0f * HXv(i + 1, j - 1) + HXv(i + 2, j - 1);
    }
    if (jcol && i >= NN - 2 && i <= NN - 1) {
        s2 += HXv(i - 4, j) - 3.0f * HXv(i - 3, j)
            + 3.0f * HXv(i - 2, j) - HXv(i - 1, j);
    }
#undef HYv
#undef HXv
    return s1 - s2;
}

// ---------------------------------------------------------------------------
// Amper Hy section (rows i0-2 .. i0+2), 2 output rows. KY = skew of base.
// ---------------------------------------------------------------------------
template<int KY>
__device__ __forceinline__ void amper_hy_sec(const float* __restrict__ hy, int base,
                                             const MCoef& m, float cM21KF0, float cM02KB3,
                                             float* __restrict__ s1a, float* __restrict__ s1b)
{
    float Y0[6], Y1[9], Y2[12], Y3[9], Y4[6];
    load_win_k<6,  KY          >(hy, base, Y0);
    load_win_k<9,  (KY + 3) & 3>(hy, base + HYW, Y1);
    load_win_k<12, (KY + 3) & 3>(hy, base + 2 * HYW - 3, Y2);
    load_win_k<9,  (KY + 2) & 3>(hy, base + 3 * HYW - 3, Y3);
    load_win_k<6,  KY          >(hy, base + 4 * HYW, Y4);

    #pragma unroll
    for (int q = 0; q < 4; q++) {
        s1a[q] += m.M00 * Y0[q] + m.M20 * Y0[q + 2];
        s1a[q] += m.M01 * Y1[q] + m.M11 * Y1[q + 1] + cM21KF0 * Y1[q + 2]
                + KF1 * Y1[q + 3] + KF2 * Y1[q + 4] + KF3 * Y1[q + 5];
        s1b[q] += m.M00 * Y1[q] + m.M20 * Y1[q + 2];
        s1a[q] += KB0 * Y2[q] + KB1 * Y2[q + 1] + KB2 * Y2[q + 2]
                + cM02KB3 * Y2[q + 3] + m.M22 * Y2[q + 5];
        s1b[q] += m.M01 * Y2[q + 3] + m.M11 * Y2[q + 4] + cM21KF0 * Y2[q + 5]
                + KF1 * Y2[q + 6] + KF2 * Y2[q + 7] + KF3 * Y2[q + 8];
        s1a[q] += m.M03 * Y3[q + 3] + m.M23 * Y3[q + 5];
        s1b[q] += KB0 * Y3[q] + KB1 * Y3[q + 1] + KB2 * Y3[q + 2]
                + cM02KB3 * Y3[q + 3] + m.M22 * Y3[q + 5];
        s1b[q] += m.M03 * Y4[q] + m.M23 * Y4[q + 2];
    }
}

// ---------------------------------------------------------------------------
// Amper Hx section (rows i0-5 .. i0+4), 2 output rows. KX = skew of base.
// ---------------------------------------------------------------------------
template<int KX>
__device__ __forceinline__ void amper_hx_sec(const float* __restrict__ hx, int base,
                                             const MCoef& m, float cM21KF0, float cM02KB3,
                                             float* __restrict__ s2a, float* __restrict__ s2b)
{
    float X0[4], X1[4], X2[4], X3[7], X4[7], X5[7], X6[7], X7[4], X8[4], X9[4];
    load_win_k<4, KX          >(hx, base, X0);
    load_win_k<4, KX          >(hx, base + HXW, X1);
    load_win_k<4, KX          >(hx, base + 2 * HXW, X2);
    load_win_k<7, (KX + 2) & 3>(hx, base + 3 * HXW - 2, X3);
    load_win_k<7, (KX + 2) & 3>(hx, base + 4 * HXW - 2, X4);
    load_win_k<7, (KX + 2) & 3>(hx, base + 5 * HXW - 2, X5);
    load_win_k<7, (KX + 2) & 3>(hx, base + 6 * HXW - 2, X6);
    load_win_k<4, (KX + 3) & 3>(hx, base + 7 * HXW - 1, X7);
    load_win_k<4, (KX + 3) & 3>(hx, base + 8 * HXW - 1, X8);
    load_win_k<4, (KX + 3) & 3>(hx, base + 9 * HXW - 1, X9);

    #pragma unroll
    for (int q = 0; q < 4; q++) {
        s2a[q] += KB0 * X0[q] + KB1 * X1[q] + KB2 * X2[q];
        s2b[q] += KB0 * X1[q] + KB1 * X2[q];
        s2a[q] += m.M00 * X3[q] + m.M01 * X3[q + 1] + cM02KB3 * X3[q + 2] + m.M03 * X3[q + 3];
        s2b[q] += KB2 * X3[q + 2];
        s2a[q] += m.M11 * X4[q + 1];
        s2b[q] += m.M00 * X4[q] + m.M01 * X4[q + 1] + cM02KB3 * X4[q + 2] + m.M03 * X4[q + 3];
        s2a[q] += m.M20 * X5[q] + cM21KF0 * X5[q + 1] + m.M22 * X5[q + 2] + m.M23 * X5[q + 3];
        s2b[q] += m.M11 * X5[q + 1];
        s2a[q] += KF1 * X6[q + 1];
        s2b[q] += m.M20 * X6[q] + cM21KF0 * X6[q + 1] + m.M22 * X6[q + 2] + m.M23 * X6[q + 3];
        s2a[q] += KF2 * X7[q] + KF3 * X8[q];
        s2b[q] += KF1 * X7[q] + KF2 * X8[q] + KF3 * X9[q];
    }
}

// ---------------------------------------------------------------------------
// Amper border body (cold path, noinline; spills are fine).
// Regions: R0 rows[0,5]x2049, R1 rows[2044,2048]x2049,
//          R2 rows[6,2043]xcols[0,7], R3 rows[6,2043]xcols[2038,2048]
// ---------------------------------------------------------------------------
#define AB_R0 12294               // 6*2049
#define AB_R1 10245               // 5*2049
#define AB_R2 16304               // 2038*8
#define AB_R3 22418               // 2038*11
#define AB_N  (AB_R0 + AB_R1 + AB_R2 + AB_R3)   // 61261
#define AB_YBLKS ((AB_N + 2047) / 2048)         // 30 (16 xblks * 128 thr)

__device__ __noinline__ void amper_border_body(
    int idx, int b,
    const float* __restrict__ e_base,  int e_off,
    const float* __restrict__ hx_base, int hx_off,
    const float* __restrict__ hy_base, int hy_off,
    float* __restrict__ out_base,      int eo_off)
{
    if (idx >= AB_N) return;
    int i, j;
    if (idx < AB_R0) { i = idx / EW; j = idx % EW; }
    else if (idx < AB_R0 + AB_R1) { int r = idx - AB_R0; i = 2044 + r / EW; j = r % EW; }
    else if (idx < AB_R0 + AB_R1 + AB_R2) { int r = idx - (AB_R0 + AB_R1); i = 6 + r / 8; j = r % 8; }
    else { int r = idx - (AB_R0 + AB_R1 + AB_R2); i = 6 + r / 11; j = 2038 + r % 11; }

    int i0 = i & ~1;
    int s = (eo_off + b * EN + i0 * EW) & 3;
    int js = j - ((j + s) & 3);
    if (i0 >= 5 && i0 <= NN - 6 && js >= 5 && js <= NN - 8) return;  // main covered it

    MCoef m = load_M();
    const float* Hxb = hx_base + hx_off + b * HXN;
    const float* Hyb = hy_base + hy_off + b * HYN;
    float d = amper_point(Hxb, Hyb, i, j, m);
    out_base[eo_off + b * EN + i * EW + j] =
        e_base[e_off + b * EN + i * EW + j] + CFLF * d;
}

// ---------------------------------------------------------------------------
// Amper: main interior blocks (y < 256) + border blocks (y >= 256).
// ---------------------------------------------------------------------------
__global__ __launch_bounds__(128, 9)
void k_amper(const float* __restrict__ e_base,  int e_off,
             const float* __restrict__ hx_base, int hx_off,
             const float* __restrict__ hy_base, int hy_off,
             float* __restrict__ out_base,      int eo_off)
{
    int b = blockIdx.z;
    if (blockIdx.y >= 256) {
        int idx = ((blockIdx.y - 256) * 16 + blockIdx.x) * 128
                + threadIdx.y * 32 + threadIdx.x;
        amper_border_body(idx, b, e_base, e_off, hx_base, hx_off,
                          hy_base, hy_off, out_base, eo_off);
        return;
    }

    int t  = blockIdx.x * 32 + threadIdx.x;
    int i0 = (blockIdx.y * 4 + threadIdx.y) * 2;
    if (i0 < 5 || i0 > NN - 6) return;        // warp-uniform

    const int erow0 = eo_off + b * EN + i0 * EW;
    const int s = erow0 & 3;
    const int j = 4 * t - s;
    const bool fast = (j >= 5) && (j <= NN - 8);
    const unsigned bal = __ballot_sync(0xffffffffu, fast);
    if (!fast) return;

    MCoef m = load_M();
    const float cM21KF0 = g_coef[9];
    const float cM02KB3 = g_coef[10];

    const int xb = hx_off + b * HXN;
    const int yb = hy_off + b * HYN;

    float s1a[4] = {0, 0, 0, 0}, s1b[4] = {0, 0, 0, 0};
    float s2a[4] = {0, 0, 0, 0}, s2b[4] = {0, 0, 0, 0};

    float E0[4], E1[4];
    const int eidx = e_off + b * EN + i0 * EW + j;
    switch (eidx & 3) {
        case 0: load_win_k<4, 0>(e_base, eidx, E0); load_win_k<4, 1>(e_base, eidx + EW, E1); break;
        case 1: load_win_k<4, 1>(e_base, eidx, E0); load_win_k<4, 2>(e_base, eidx + EW, E1); break;
        case 2: load_win_k<4, 2>(e_base, eidx, E0); load_win_k<4, 3>(e_base, eidx + EW, E1); break;
        case 3: load_win_k<4, 3>(e_base, eidx, E0); load_win_k<4, 0>(e_base, eidx + EW, E1); break;
    }

    const int ybase = yb + (i0 - 2) * HYW + (j - 2);
    switch (ybase & 3) {
        case 0: amper_hy_sec<0>(hy_base, ybase, m, cM21KF0, cM02KB3, s1a, s1b); break;
        case 1: amper_hy_sec<1>(hy_base, ybase, m, cM21KF0, cM02KB3, s1a, s1b); break;
        case 2: amper_hy_sec<2>(hy_base, ybase, m, cM21KF0, cM02KB3, s1a, s1b); break;
        case 3: amper_hy_sec<3>(hy_base, ybase, m, cM21KF0, cM02KB3, s1a, s1b); break;
    }

    const int xbase = xb + (i0 - 5) * HXW + j;
    switch (xbase & 3) {
        case 0: amper_hx_sec<0>(hx_base, xbase, m, cM21KF0, cM02KB3, s2a, s2b); break;
        case 1: amper_hx_sec<1>(hx_base, xbase, m, cM21KF0, cM02KB3, s2a, s2b); break;
        case 2: amper_hx_sec<2>(hx_base, xbase, m, cM21KF0, cM02KB3, s2a, s2b); break;
        case 3: amper_hx_sec<3>(hx_base, xbase, m, cM21KF0, cM02KB3, s2a, s2b); break;
    }

    float4 w;
    w.x = E0[0] + CFLF * (s1a[0] - s2a[0]);
    w.y = E0[1] + CFLF * (s1a[1] - s2a[1]);
    w.z = E0[2] + CFLF * (s1a[2] - s2a[2]);
    w.w = E0[3] + CFLF * (s1a[3] - s2a[3]);
    *reinterpret_cast<float4*>(out_base + erow0 + j) = w;   // aligned by construction

    float r1_0 = E1[0] + CFLF * (s1b[0] - s2b[0]);
    float r1_1 = E1[1] + CFLF * (s1b[1] - s2b[1]);
    float r1_2 = E1[2] + CFLF * (s1b[2] - s2b[2]);
    float r1_3 = E1[3] + CFLF * (s1b[3] - s2b[3]);
    if (bal == 0xffffffffu) {
        warp_store128(out_base, erow0 + EW + j, r1_0, r1_1, r1_2, r1_3);
    } else {
        float* p1 = out_base + erow0 + EW + j;
        p1[0] = r1_0; p1[1] = r1_1; p1[2] = r1_2; p1[3] = r1_3;
    }
}

// ---------------------------------------------------------------------------
// Generic faraday point helpers
// ---------------------------------------------------------------------------
__device__ float faraday_s3(const float* __restrict__ Eb, int i, int j, const MCoef& m)
{
#define Ev(r, c) Eb[(r) * EW + (c)]
    float s3 = 0.0f;
    if (j >= 1 && j <= NN - 2) {
        s3 += m.M00 * Ev(i,     j - 1) + m.M01 * Ev(i,     j)
            + m.M02 * Ev(i,     j + 1) + m.M03 * Ev(i,     j + 2);
        s3 += m.M11 * Ev(i + 1, j);
        s3 += m.M20 * Ev(i + 2, j - 1) + m.M21 * Ev(i + 2, j)
            + m.M22 * Ev(i + 2, j + 1) + m.M23 * Ev(i + 2, j + 2);
    }
    if (i <= NN - 4)
        s3 += -1.5f * Ev(i + 1, j) + 2.0f * Ev(i + 2, j) - 0.5f * Ev(i + 3, j);
    if (i >= 2)
        s3 += 0.5f * Ev(i - 1, j + 1) - 2.0f * Ev(i, j + 1) + 1.5f * Ev(i + 1, j + 1);
#undef Ev
    return s3;
}

__device__ float faraday_s4(const float* __restrict__ Eb, int i, int j, const MCoef& m)
{
#define Ev(r, c) Eb[(r) * EW + (c)]
    float s4 = 0.0f;
    if (i >= 1 && i <= NN - 2) {
        s4 += m.M00 * Ev(i - 1, j) + m.M20 * Ev(i - 1, j + 2);
        s4 += m.M01 * Ev(i,     j) + m.M11 * Ev(i, j + 1) + m.M21 * Ev(i, j + 2);
        s4 += m.M02 * Ev(i + 1, j) + m.M22 * Ev(i + 1, j + 2);
        s4 += m.M03 * Ev(i + 2, j) + m.M23 * Ev(i + 2, j + 2);
    }
    if (j <= NN - 4)
        s4 += -1.5f * Ev(i, j + 1) + 2.0f * Ev(i, j + 2) - 0.5f * Ev(i, j + 3);
    if (j >= 2)
        s4 += 0.5f * Ev(i + 1, j - 1) - 2.0f * Ev(i + 1, j) + 1.5f * Ev(i + 1, j + 1);
#undef Ev
    return s4;
}

// ---------------------------------------------------------------------------
// Faraday E section (rows i0-1 .. i0+4), 2 output rows. KE = skew of base.
// ---------------------------------------------------------------------------
template<int KE>
__device__ __forceinline__ void faraday_e_sec(const float* __restrict__ e, int base,
                                              const MCoef& m, float cA, float cB, float cC,
                                              float* __restrict__ s3a, float* __restrict__ s3b,
                                              float* __restrict__ s4a, float* __restrict__ s4b)
{
    float W0[6], W1[8], W2[8], W3[7], W4[7], W5[4];
    load_win_k<6, KE          >(e, base, W0);
    load_win_k<8, KE          >(e, base + EW - 1, W1);
    load_win_k<8, (KE + 1) & 3>(e, base + 2 * EW - 1, W2);
    load_win_k<7, (KE + 2) & 3>(e, base + 3 * EW - 1, W3);
    load_win_k<7, (KE + 3) & 3>(e, base + 4 * EW - 1, W4);
    load_win_k<4, (KE + 1) & 3>(e, base + 5 * EW, W5);

    #pragma unroll
    for (int q = 0; q < 4; q++) {
        s3a[q] += 0.5f * W0[q + 1];
        s4a[q] += m.M00 * W0[q] + m.M20 * W0[q + 2];
        s3a[q] += m.M00 * W1[q] + m.M01 * W1[q + 1] + cA * W1[q + 2] + m.M03 * W1[q + 3];
        s4a[q] += m.M01 * W1[q + 1] + cB * W1[q + 2] + cC * W1[q + 3] - 0.5f * W1[q + 4];
        s3b[q] += 0.5f * W1[q + 2];
        s4b[q] += m.M00 * W1[q + 1] + m.M20 * W1[q + 3];
        s3a[q] += cB * W2[q + 1] + 1.5f * W2[q + 2];
        s4a[q] += 0.5f * W2[q] + cA * W2[q + 1] + 1.5f * W2[q + 2] + m.M22 * W2[q + 3];
        s3b[q] += m.M00 * W2[q] + m.M01 * W2[q + 1] + cA * W2[q + 2] + m.M03 * W2[q + 3];
        s4b[q] += m.M01 * W2[q + 1] + cB * W2[q + 2] + cC * W2[q + 3] - 0.5f * W2[q + 4];
        s3a[q] += m.M20 * W3[q] + cC * W3[q + 1] + m.M22 * W3[q + 2] + m.M23 * W3[q + 3];
        s4a[q] += m.M03 * W3[q + 1] + m.M23 * W3[q + 3];
        s3b[q] += cB * W3[q + 1] + 1.5f * W3[q + 2];
        s4b[q] += 0.5f * W3[q] + cA * W3[q + 1] + 1.5f * W3[q + 2] + m.M22 * W3[q + 3];
        s3a[q] += -0.5f * W4[q + 1];
        s3b[q] += m.M20 * W4[q] + cC * W4[q + 1] + m.M22 * W4[q + 2] + m.M23 * W4[q + 3];
        s4b[q] += m.M03 * W4[q + 1] + m.M23 * W4[q + 3];
        s3b[q] += -0.5f * W5[q];
    }
}

// ---------------------------------------------------------------------------
// Faraday border body (cold path, noinline).
// Regions: R0 rows[0,1]x2048, R1 rows[2044,2047]x2048,
//          R2 rows[2,2043]xcols[0,4], R3 rows[2,2043]xcols[2039,2047]
// ---------------------------------------------------------------------------
#define FB_R0 4096                // 2*2048
#define FB_R1 8192                // 4*2048
#define FB_R2 10210               // 2042*5
#define FB_R3 18378               // 2042*9
#define FB_N  (FB_R0 + FB_R1 + FB_R2 + FB_R3)   // 40876
#define FB_YBLKS ((FB_N + 2047) / 2048)         // 20

__device__ __noinline__ void faraday_border_body(
    int idx, int b,
    const float* __restrict__ e_base,  int e_off,
    const float* __restrict__ hx_base, int hx_off,
    const float* __restrict__ hy_base, int hy_off,
    float* __restrict__ out_base,      int hxo_off, int hyo_off)
{
    if (idx >= FB_N) return;
    int i, j;
    if (idx < FB_R0) { i = idx / NN; j = idx % NN; }
    else if (idx < FB_R0 + FB_R1) { int r = idx - FB_R0; i = 2044 + r / NN; j = r % NN; }
    else if (idx < FB_R0 + FB_R1 + FB_R2) { int r = idx - (FB_R0 + FB_R1); i = 2 + r / 5; j = r % 5; }
    else { int r = idx - (FB_R0 + FB_R1 + FB_R2); i = 2 + r / 9; j = 2039 + r % 9; }

    int i0 = i & ~1;
    int sF = hxo_off & 3;
    int js = j - ((j + sF) & 3);
    if (i0 >= 2 && i0 <= NN - 5 && js >= 2 && js <= NN - 7) return;  // main covered it

    MCoef m = load_M();
    const float* Eb  = e_base + e_off + b * EN;
    const float* Hxb = hx_base + hx_off + b * HXN;
    const float* Hyb = hy_base + hy_off + b * HYN;
    float* Hxob = out_base + hxo_off + b * HXN;
    float* Hyob = out_base + hyo_off + b * HYN;

    if (i < HXH && j < HXW) {
        float s3 = faraday_s3(Eb, i, j, m);
        Hxob[i * HXW + j] = Hxb[i * HXW + j] - CFLF * s3;
    }
    if (i < HYH && j < HYW) {
        float s4 = faraday_s4(Eb, i, j, m);
        Hyob[i * HYW + j] = Hyb[i * HYW + j] + CFLF * s4;
    }
}

// ---------------------------------------------------------------------------
// Faraday: main interior blocks (y < 256) + border blocks (y >= 256).
// ---------------------------------------------------------------------------
__global__ __launch_bounds__(128, 9)
void k_faraday(const float* __restrict__ e_base,  int e_off,
               const float* __restrict__ hx_base, int hx_off,
               const float* __restrict__ hy_base, int hy_off,
               float* __restrict__ out_base,      int hxo_off, int hyo_off)
{
    int b = blockIdx.z;
    if (blockIdx.y >= 256) {
        int idx = ((blockIdx.y - 256) * 16 + blockIdx.x) * 128
                + threadIdx.y * 32 + threadIdx.x;
        faraday_border_body(idx, b, e_base, e_off, hx_base, hx_off,
                            hy_base, hy_off, out_base, hxo_off, hyo_off);
        return;
    }

    int t  = blockIdx.x * 32 + threadIdx.x;
    int i0 = (blockIdx.y * 4 + threadIdx.y) * 2;
    if (i0 < 2 || i0 > NN - 5) return;        // warp-uniform

    const int sF = hxo_off & 3;
    const int j = 4 * t - sF;
    const bool fast = (j >= 2) && (j <= NN - 7);
    const unsigned bal = __ballot_sync(0xffffffffu, fast);
    if (!fast) return;

    MCoef m = load_M();
    const float cA = g_coef[11];
    const float cB = g_coef[12];
    const float cC = g_coef[13];

    const int eb = e_off + b * EN;
    const int xb = hx_off + b * HXN;
    const int yb = hy_off + b * HYN;

    float s3a[4] = {0, 0, 0, 0}, s3b[4] = {0, 0, 0, 0};
    float s4a[4] = {0, 0, 0, 0}, s4b[4] = {0, 0, 0, 0};

    float hx0[4], hx1[4], hy0[4], hy1[4];
    const int hxidx = xb + i0 * HXW + j;      // HXW == 0 mod 4
    switch (hxidx & 3) {
        case 0: load_win_k<4, 0>(hx_base, hxidx, hx0); load_win_k<4, 0>(hx_base, hxidx + HXW, hx1); break;
        case 1: load_win_k<4, 1>(hx_base, hxidx, hx0); load_win_k<4, 1>(hx_base, hxidx + HXW, hx1); break;
        case 2: load_win_k<4, 2>(hx_base, hxidx, hx0); load_win_k<4, 2>(hx_base, hxidx + HXW, hx1); break;
        case 3: load_win_k<4, 3>(hx_base, hxidx, hx0); load_win_k<4, 3>(hx_base, hxidx + HXW, hx1); break;
    }
    const int hyidx = yb + i0 * HYW + j;      // HYW == 3 mod 4
    switch (hyidx & 3) {
        case 0: load_win_k<4, 0>(hy_base, hyidx, hy0); load_win_k<4, 3>(hy_base, hyidx + HYW, hy1); break;
        case 1: load_win_k<4, 1>(hy_base, hyidx, hy0); load_win_k<4, 0>(hy_base, hyidx + HYW, hy1); break;
        case 2: load_win_k<4, 2>(hy_base, hyidx, hy0); load_win_k<4, 1>(hy_base, hyidx + HYW, hy1); break;
        case 3: load_win_k<4, 3>(hy_base, hyidx, hy0); load_win_k<4, 2>(hy_base, hyidx + HYW, hy1); break;
    }
    const int ebase = eb + (i0 - 1) * EW + j;
    switch (ebase & 3) {
        case 0: faraday_e_sec<0>(e_base, ebase, m, cA, cB, cC, s3a, s3b, s4a, s4b); break;
        case 1: faraday_e_sec<1>(e_base, ebase, m, cA, cB, cC, s3a, s3b, s4a, s4b); break;
        case 2: faraday_e_sec<2>(e_base, ebase, m, cA, cB, cC, s3a, s3b, s4a, s4b); break;
        case 3: faraday_e_sec<3>(e_base, ebase, m, cA, cB, cC, s3a, s3b, s4a, s4b); break;
    }

    float4 w;
    w.x = hx0[0] - CFLF * s3a[0];
    w.y = hx0[1] - CFLF * s3a[1];
    w.z = hx0[2] - CFLF * s3a[2];
    w.w = hx0[3] - CFLF * s3a[3];
    *reinterpret_cast<float4*>(out_base + hxo_off + b * HXN + i0 * HXW + j) = w;
    w.x = hx1[0] - CFLF * s3b[0];
    w.y = hx1[1] - CFLF * s3b[1];
    w.z = hx1[2] - CFLF * s3b[2];
    w.w = hx1[3] - CFLF * s3b[3];
    *reinterpret_cast<float4*>(out_base + hxo_off + b * HXN + (i0 + 1) * HXW + j) = w;

    float wy00 = hy0[0] + CFLF * s4a[0];
    float wy01 = hy0[1] + CFLF * s4a[1];
    float wy02 = hy0[2] + CFLF * s4a[2];
    float wy03 = hy0[3] + CFLF * s4a[3];
    float wy10 = hy1[0] + CFLF * s4b[0];
    float wy11 = hy1[1] + CFLF * s4b[1];
    float wy12 = hy1[2] + CFLF * s4b[2];
    float wy13 = hy1[3] + CFLF * s4b[3];
    if (bal == 0xffffffffu) {
        warp_store128(out_base, hyo_off + b * HYN + i0 * HYW + j, wy00, wy01, wy02, wy03);
        warp_store128(out_base, hyo_off + b * HYN + (i0 + 1) * HYW + j, wy10, wy11, wy12, wy13);
    } else {
        float* p0 = out_base + hyo_off + b * HYN + i0 * HYW + j;
        float* p1 = p0 + HYW;
        p0[0] = wy00; p0[1] = wy01; p0[2] = wy02; p0[3] = wy03;
        p1[0] = wy10; p1[1] = wy11; p1[2] = wy12; p1[3] = wy13;
    }
}

// ---------------------------------------------------------------------------
extern "C" void kernel_launch(void* const* d_in, const int* in_sizes, int n_in,
                              void* d_out, int out_size)
{
    const float* sb = (const float*)d_in[3];
    const float* sd = (const float*)d_in[4];
    const float* sg = (const float*)d_in[5];
    float* out = (float*)d_out;

    const float* e_base  = (const float*)d_in[0]; int e_off  = 0;
    const float* hx_base = (const float*)d_in[1]; int hx_off = 0;
    const float* hy_base = (const float*)d_in[2]; int hy_off = 0;

    const int STEP = BB * (EN + HXN + HYN);

    k_setup<<<1, 1>>>(sb, sd, sg);

    dim3 blk(32, 4, 1);
    dim3 gA(16, 256 + AB_YBLKS, BB);          // main rows + amper border band
    dim3 gF(16, 256 + FB_YBLKS, BB);          // main rows + faraday border band

    for (int k = 0; k < 3; k++) {
        int eo_off  = k * STEP;
        int hxo_off = eo_off + BB * EN;
        int hyo_off = hxo_off + BB * HXN;

        k_amper<<<gA, blk>>>(e_base, e_off, hx_base, hx_off, hy_base, hy_off,
                             out, eo_off);
        k_faraday<<<gF, blk>>>(out, eo_off, hx_base, hx_off, hy_base, hy_off,
                               out, hxo_off, hyo_off);

        e_base = out;  e_off  = eo_off;
        hx_base = out; hx_off = hxo_off;
        hy_base = out; hy_off = hyo_off;
    }
}

// round 14
// speedup vs baseline: 1.4606x; 1.0806x over previous
#include <cuda_runtime.h>

// Problem constants (fixed: N=2048, B=2)
#define NN   2048
#define BB   2
#define EW   (NN + 1)            // 2049  (== 1 mod 4)
#define HXH  (NN - 1)            // 2047
#define HXW  (NN)                // 2048  (== 0 mod 4)
#define HYH  (NN)                // 2048
#define HYW  (NN - 1)            // 2047  (== 3 mod 4)
#define EN   (EW * EW)
#define HXN  (HXH * HXW)
#define HYN  (HYH * HYW)
#define CFLF 0.35f

#define KF0 (-11.0f / 6.0f)
#define KF1 (3.0f)
#define KF2 (-1.5f)
#define KF3 (1.0f / 3.0f)
#define KB0 (-1.0f / 3.0f)
#define KB1 (1.5f)
#define KB2 (-3.0f)
#define KB3 (11.0f / 6.0f)

struct MCoef {
    float M00, M01, M02, M03, M11, M20, M21, M22, M23;
};

// Precomputed coefficients, filled once by k_setup:
// [0..8]  M00..M23  [9] cM21KF0  [10] cM02KB3  [11] cA  [12] cB  [13] cC
__device__ float g_coef[16];

__global__ void k_setup(const float* __restrict__ sb,
                        const float* __restrict__ sd,
                        const float* __restrict__ sg)
{
    float beta = *sb, delta = *sd, gamma = *sg;
    float M00 = -0.25f * beta + 0.1f * gamma;
    float M01 =  0.25f * beta + delta - 0.5f - 0.1f * gamma;
    float M02 =  0.25f * beta - 0.1f * gamma;
    float M03 = -0.25f * beta + 0.1f * gamma;
    float M11 = -2.0f * delta;
    float M20 =  0.25f * beta - 0.1f * gamma;
    float M21 = -0.25f * beta + delta + 0.5f + 0.1f * gamma;
    float M22 = -0.25f * beta - 0.1f * gamma;
    float M23 =  0.25f * beta + 0.1f * gamma;
    g_coef[0] = M00;  g_coef[1] = M01;  g_coef[2] = M02;  g_coef[3] = M03;
    g_coef[4] = M11;  g_coef[5] = M20;  g_coef[6] = M21;  g_coef[7] = M22;
    g_coef[8] = M23;
    g_coef[9]  = M21 + KF0;
    g_coef[10] = M02 + KB3;
    g_coef[11] = M02 - 2.0f;
    g_coef[12] = M11 - 1.5f;
    g_coef[13] = M21 + 2.0f;
    g_coef[14] = 0.0f; g_coef[15] = 0.0f;
}

__device__ __forceinline__ MCoef load_M() {
    const float4* cp = reinterpret_cast<const float4*>(g_coef);
    float4 c0 = cp[0], c1 = cp[1], c2 = cp[2];
    MCoef m;
    m.M00 = c0.x; m.M01 = c0.y; m.M02 = c0.z; m.M03 = c0.w;
    m.M11 = c1.x; m.M20 = c1.y; m.M21 = c1.z; m.M22 = c1.w;
    m.M23 = c2.x;
    return m;
}

// ---------------------------------------------------------------------------
// Warp-coalesced store (whole warp must participate).
// ---------------------------------------------------------------------------
__device__ __forceinline__ void warp_store128(float* __restrict__ out, int gi,
                                              float v0, float v1, float v2, float v3)
{
    const unsigned FULL = 0xffffffffu;
    const int lane = threadIdx.x & 31;
    const int s = gi & 3;
    if (s == 0) {
        float4 w; w.x = v0; w.y = v1; w.z = v2; w.w = v3;
        *reinterpret_cast<float4*>(out + gi) = w;
        return;
    }
    float n0 = __shfl_down_sync(FULL, v0, 1);
    float n1 = __shfl_down_sync(FULL, v1, 1);
    float n2 = __shfl_down_sync(FULL, v2, 1);
    if (s == 1) {
        if (lane < 31) {
            float4 w; w.x = v3; w.y = n0; w.z = n1; w.w = n2;
            *reinterpret_cast<float4*>(out + gi + 3) = w;
        }
        if (lane == 0)  { out[gi] = v0; out[gi + 1] = v1; out[gi + 2] = v2; }
        else if (lane == 31) { out[gi + 3] = v3; }
    } else if (s == 2) {
        if (lane < 31) {
            float4 w; w.x = v2; w.y = v3; w.z = n0; w.w = n1;
            *reinterpret_cast<float4*>(out + gi + 2) = w;
        }
        if (lane == 0)  { out[gi] = v0; out[gi + 1] = v1; }
        else if (lane == 31) { out[gi + 2] = v2; out[gi + 3] = v3; }
    } else {
        if (lane < 31) {
            float4 w; w.x = v1; w.y = v2; w.z = v3; w.w = n0;
            *reinterpret_cast<float4*>(out + gi + 1) = w;
        }
        if (lane == 0)  { out[gi] = v0; }
        else if (lane == 31) { out[gi + 1] = v1; out[gi + 2] = v2; out[gi + 3] = v3; }
    }
}

// ---------------------------------------------------------------------------
// Compile-time-skew window load: out[t] = buf[idx+t], requires (idx&3)==K.
// ---------------------------------------------------------------------------
template<int W, int K>
__device__ __forceinline__ void load_win_k(const float* __restrict__ buf, int idx,
                                           float* __restrict__ out)
{
    constexpr int NV = (W + K + 3) / 4;
    const float4* p = reinterpret_cast<const float4*>(buf + (idx - K));
    float f[NV * 4];
    #pragma unroll
    for (int t = 0; t < NV; t++)
        *reinterpret_cast<float4*>(f + 4 * t) = p[t];
    #pragma unroll
    for (int t = 0; t < W; t++) out[t] = f[t + K];
}

// ---------------------------------------------------------------------------
// Generic (boundary) amper point.
// ---------------------------------------------------------------------------
__device__ float amper_point(const float* __restrict__ Hxb,
                             const float* __restrict__ Hyb,
                             int i, int j, const MCoef& m)
{
    float s1 = 0.0f, s2 = 0.0f;
    bool irow = (i >= 2 && i <= NN - 2);
    bool jcol = (j >= 2 && j <= NN - 2);

#define HYv(r, c) Hyb[(r) * HYW + (c)]
#define HXv(r, c) Hxb[(r) * HXW + (c)]
    if (irow && jcol) {
        s1 += m.M00 * HYv(i - 2, j - 2) + m.M20 * HYv(i - 2, j);
        s1 += m.M01 * HYv(i - 1, j - 2) + m.M11 * HYv(i - 1, j - 1) + m.M21 * HYv(i - 1, j);
        s1 += m.M02 * HYv(i,     j - 2) + m.M22 * HYv(i,     j);
        s1 += m.M03 * HYv(i + 1, j - 2) + m.M23 * HYv(i + 1, j);
        s2 += m.M00 * HXv(i - 2, j - 2) + m.M01 * HXv(i - 2, j - 1)
            + m.M02 * HXv(i - 2, j)     + m.M03 * HXv(i - 2, j + 1);
        s2 += m.M11 * HXv(i - 1, j - 1);
        s2 += m.M20 * HXv(i,     j - 2) + m.M21 * HXv(i,     j - 1)
            + m.M22 * HXv(i,     j)     + m.M23 * HXv(i,     j + 1);
    }
    if (i >= 1 && j <= NN - 5) {
        s1 += KF0 * HYv(i - 1, j)     + KF1 * HYv(i - 1, j + 1)
            + KF2 * HYv(i - 1, j + 2) + KF3 * HYv(i - 1, j + 3);
    }
    if (i <= NN - 1 && j >= 5) {
        s1 += KB0 * HYv(i, j - 5) + KB1 * HYv(i, j - 4)
            + KB2 * HYv(i, j - 3) + KB3 * HYv(i, j - 2);
    }
    if (irow && j >= 1 && j <= 2) {
        s1 += -HYv(i - 1, j - 1) + 3.0f * HYv(i - 1, j)
              - 3.0f * HYv(i - 1, j + 1) + HYv(i - 1, j + 2);
    }
    if (irow && j >= NN - 2 && j <= NN - 1) {
        s1 += HYv(i, j - 4) - 3.0f * HYv(i, j - 3)
            + 3.0f * HYv(i, j - 2) - HYv(i, j - 1);
    }
    if (j >= 1 && i <= NN - 5) {
        s2 += KF0 * HXv(i, j - 1)     + KF1 * HXv(i + 1, j - 1)
            + KF2 * HXv(i + 2, j - 1) + KF3 * HXv(i + 3, j - 1);
    }
    if (j <= NN - 1 && i >= 5) {
        s2 += KB0 * HXv(i - 5, j) + KB1 * HXv(i - 4, j)
            + KB2 * HXv(i - 3, j) + KB3 * HXv(i - 2, j);
    }
    if (jcol && i >= 1 && i <= 2) {
        s2 += -HXv(i - 1, j - 1) + 3.0f * HXv(i, j - 1)
              - 3.0f * HXv(i + 1, j - 1) + HXv(i + 2, j - 1);
    }
    if (jcol && i >= NN - 2 && i <= NN - 1) {
        s2 += HXv(i - 4, j) - 3.0f * HXv(i - 3, j)
            + 3.0f * HXv(i - 2, j) - HXv(i - 1, j);
    }
#undef HYv
#undef HXv
    return s1 - s2;
}

// ---------------------------------------------------------------------------
// Amper Hy section (rows i0-2 .. i0+2), 2 output rows. KY = skew of base.
// ---------------------------------------------------------------------------
template<int KY>
__device__ __forceinline__ void amper_hy_sec(const float* __restrict__ hy, int base,
                                             const MCoef& m, float cM21KF0, float cM02KB3,
                                             float* __restrict__ s1a, float* __restrict__ s1b)
{
    float Y0[6], Y1[9], Y2[12], Y3[9], Y4[6];
    load_win_k<6,  KY          >(hy, base, Y0);
    load_win_k<9,  (KY + 3) & 3>(hy, base + HYW, Y1);
    load_win_k<12, (KY + 3) & 3>(hy, base + 2 * HYW - 3, Y2);
    load_win_k<9,  (KY + 2) & 3>(hy, base + 3 * HYW - 3, Y3);
    load_win_k<6,  KY          >(hy, base + 4 * HYW, Y4);

    #pragma unroll
    for (int q = 0; q < 4; q++) {
        s1a[q] += m.M00 * Y0[q] + m.M20 * Y0[q + 2];
        s1a[q] += m.M01 * Y1[q] + m.M11 * Y1[q + 1] + cM21KF0 * Y1[q + 2]
                + KF1 * Y1[q + 3] + KF2 * Y1[q + 4] + KF3 * Y1[q + 5];
        s1b[q] += m.M00 * Y1[q] + m.M20 * Y1[q + 2];
        s1a[q] += KB0 * Y2[q] + KB1 * Y2[q + 1] + KB2 * Y2[q + 2]
                + cM02KB3 * Y2[q + 3] + m.M22 * Y2[q + 5];
        s1b[q] += m.M01 * Y2[q + 3] + m.M11 * Y2[q + 4] + cM21KF0 * Y2[q + 5]
                + KF1 * Y2[q + 6] + KF2 * Y2[q + 7] + KF3 * Y2[q + 8];
        s1a[q] += m.M03 * Y3[q + 3] + m.M23 * Y3[q + 5];
        s1b[q] += KB0 * Y3[q] + KB1 * Y3[q + 1] + KB2 * Y3[q + 2]
                + cM02KB3 * Y3[q + 3] + m.M22 * Y3[q + 5];
        s1b[q] += m.M03 * Y4[q] + m.M23 * Y4[q + 2];
    }
}

// ---------------------------------------------------------------------------
// Amper Hx section (rows i0-5 .. i0+4), 2 output rows. KX = skew of base.
// ---------------------------------------------------------------------------
template<int KX>
__device__ __forceinline__ void amper_hx_sec(const float* __restrict__ hx, int base,
                                             const MCoef& m, float cM21KF0, float cM02KB3,
                                             float* __restrict__ s2a, float* __restrict__ s2b)
{
    float X0[4], X1[4], X2[4], X3[7], X4[7], X5[7], X6[7], X7[4], X8[4], X9[4];
    load_win_k<4, KX          >(hx, base, X0);
    load_win_k<4, KX          >(hx, base + HXW, X1);
    load_win_k<4, KX          >(hx, base + 2 * HXW, X2);
    load_win_k<7, (KX + 2) & 3>(hx, base + 3 * HXW - 2, X3);
    load_win_k<7, (KX + 2) & 3>(hx, base + 4 * HXW - 2, X4);
    load_win_k<7, (KX + 2) & 3>(hx, base + 5 * HXW - 2, X5);
    load_win_k<7, (KX + 2) & 3>(hx, base + 6 * HXW - 2, X6);
    load_win_k<4, (KX + 3) & 3>(hx, base + 7 * HXW - 1, X7);
    load_win_k<4, (KX + 3) & 3>(hx, base + 8 * HXW - 1, X8);
    load_win_k<4, (KX + 3) & 3>(hx, base + 9 * HXW - 1, X9);

    #pragma unroll
    for (int q = 0; q < 4; q++) {
        s2a[q] += KB0 * X0[q] + KB1 * X1[q] + KB2 * X2[q];
        s2b[q] += KB0 * X1[q] + KB1 * X2[q];
        s2a[q] += m.M00 * X3[q] + m.M01 * X3[q + 1] + cM02KB3 * X3[q + 2] + m.M03 * X3[q + 3];
        s2b[q] += KB2 * X3[q + 2];
        s2a[q] += m.M11 * X4[q + 1];
        s2b[q] += m.M00 * X4[q] + m.M01 * X4[q + 1] + cM02KB3 * X4[q + 2] + m.M03 * X4[q + 3];
        s2a[q] += m.M20 * X5[q] + cM21KF0 * X5[q + 1] + m.M22 * X5[q + 2] + m.M23 * X5[q + 3];
        s2b[q] += m.M11 * X5[q + 1];
        s2a[q] += KF1 * X6[q + 1];
        s2b[q] += m.M20 * X6[q] + cM21KF0 * X6[q + 1] + m.M22 * X6[q + 2] + m.M23 * X6[q + 3];
        s2a[q] += KF2 * X7[q] + KF3 * X8[q];
        s2b[q] += KF1 * X7[q] + KF2 * X8[q] + KF3 * X9[q];
    }
}

// ---------------------------------------------------------------------------
// Amper border body (cold path, noinline; spills are fine).
// ---------------------------------------------------------------------------
#define AB_R0 12294               // 6*2049
#define AB_R1 10245               // 5*2049
#define AB_R2 16304               // 2038*8
#define AB_R3 22418               // 2038*11
#define AB_N  (AB_R0 + AB_R1 + AB_R2 + AB_R3)   // 61261
#define AB_YBLKS ((AB_N + 2047) / 2048)         // 30

__device__ __noinline__ void amper_border_body(
    int idx, int b,
    const float* __restrict__ e_base,  int e_off,
    const float* __restrict__ hx_base, int hx_off,
    const float* __restrict__ hy_base, int hy_off,
    float* __restrict__ out_base,      int eo_off)
{
    if (idx >= AB_N) return;
    int i, j;
    if (idx < AB_R0) { i = idx / EW; j = idx % EW; }
    else if (idx < AB_R0 + AB_R1) { int r = idx - AB_R0; i = 2044 + r / EW; j = r % EW; }
    else if (idx < AB_R0 + AB_R1 + AB_R2) { int r = idx - (AB_R0 + AB_R1); i = 6 + r / 8; j = r % 8; }
    else { int r = idx - (AB_R0 + AB_R1 + AB_R2); i = 6 + r / 11; j = 2038 + r % 11; }

    int i0 = i & ~1;
    int s = (eo_off + b * EN + i0 * EW) & 3;
    int js = j - ((j + s) & 3);
    if (i0 >= 5 && i0 <= NN - 6 && js >= 5 && js <= NN - 8) return;  // main covered it

    MCoef m = load_M();
    const float* Hxb = hx_base + hx_off + b * HXN;
    const float* Hyb = hy_base + hy_off + b * HYN;
    float d = amper_point(Hxb, Hyb, i, j, m);
    out_base[eo_off + b * EN + i * EW + j] =
        e_base[e_off + b * EN + i * EW + j] + CFLF * d;
}

// ---------------------------------------------------------------------------
// Amper: main interior blocks (y < 256) + border blocks (y >= 256).
// ---------------------------------------------------------------------------
__global__ __launch_bounds__(128, 10)
void k_amper(const float* __restrict__ e_base,  int e_off,
             const float* __restrict__ hx_base, int hx_off,
             const float* __restrict__ hy_base, int hy_off,
             float* __restrict__ out_base,      int eo_off)
{
    int b = blockIdx.z;
    if (blockIdx.y >= 256) {
        int idx = ((blockIdx.y - 256) * 16 + blockIdx.x) * 128
                + threadIdx.y * 32 + threadIdx.x;
        amper_border_body(idx, b, e_base, e_off, hx_base, hx_off,
                          hy_base, hy_off, out_base, eo_off);
        return;
    }

    int t  = blockIdx.x * 32 + threadIdx.x;
    int i0 = (blockIdx.y * 4 + threadIdx.y) * 2;
    if (i0 < 5 || i0 > NN - 6) return;        // warp-uniform

    const int erow0 = eo_off + b * EN + i0 * EW;
    const int s = erow0 & 3;
    const int j = 4 * t - s;
    const bool fast = (j >= 5) && (j <= NN - 8);
    const unsigned bal = __ballot_sync(0xffffffffu, fast);
    if (!fast) return;

    MCoef m = load_M();
    const float cM21KF0 = g_coef[9];
    const float cM02KB3 = g_coef[10];

    const int xb = hx_off + b * HXN;
    const int yb = hy_off + b * HYN;

    float s1a[4] = {0, 0, 0, 0}, s1b[4] = {0, 0, 0, 0};
    float s2a[4] = {0, 0, 0, 0}, s2b[4] = {0, 0, 0, 0};

    const int ybase = yb + (i0 - 2) * HYW + (j - 2);
    switch (ybase & 3) {
        case 0: amper_hy_sec<0>(hy_base, ybase, m, cM21KF0, cM02KB3, s1a, s1b); break;
        case 1: amper_hy_sec<1>(hy_base, ybase, m, cM21KF0, cM02KB3, s1a, s1b); break;
        case 2: amper_hy_sec<2>(hy_base, ybase, m, cM21KF0, cM02KB3, s1a, s1b); break;
        case 3: amper_hy_sec<3>(hy_base, ybase, m, cM21KF0, cM02KB3, s1a, s1b); break;
    }

    const int xbase = xb + (i0 - 5) * HXW + j;
    switch (xbase & 3) {
        case 0: amper_hx_sec<0>(hx_base, xbase, m, cM21KF0, cM02KB3, s2a, s2b); break;
        case 1: amper_hx_sec<1>(hx_base, xbase, m, cM21KF0, cM02KB3, s2a, s2b); break;
        case 2: amper_hx_sec<2>(hx_base, xbase, m, cM21KF0, cM02KB3, s2a, s2b); break;
        case 3: amper_hx_sec<3>(hx_base, xbase, m, cM21KF0, cM02KB3, s2a, s2b); break;
    }

    // E input loaded LATE to minimize live registers through the stencil body.
    float E0[4], E1[4];
    const int eidx = e_off + b * EN + i0 * EW + j;
    switch (eidx & 3) {
        case 0: load_win_k<4, 0>(e_base, eidx, E0); load_win_k<4, 1>(e_base, eidx + EW, E1); break;
        case 1: load_win_k<4, 1>(e_base, eidx, E0); load_win_k<4, 2>(e_base, eidx + EW, E1); break;
        case 2: load_win_k<4, 2>(e_base, eidx, E0); load_win_k<4, 3>(e_base, eidx + EW, E1); break;
        case 3: load_win_k<4, 3>(e_base, eidx, E0); load_win_k<4, 0>(e_base, eidx + EW, E1); break;
    }

    float4 w;
    w.x = E0[0] + CFLF * (s1a[0] - s2a[0]);
    w.y = E0[1] + CFLF * (s1a[1] - s2a[1]);
    w.z = E0[2] + CFLF * (s1a[2] - s2a[2]);
    w.w = E0[3] + CFLF * (s1a[3] - s2a[3]);
    *reinterpret_cast<float4*>(out_base + erow0 + j) = w;   // aligned by construction

    float r1_0 = E1[0] + CFLF * (s1b[0] - s2b[0]);
    float r1_1 = E1[1] + CFLF * (s1b[1] - s2b[1]);
    float r1_2 = E1[2] + CFLF * (s1b[2] - s2b[2]);
    float r1_3 = E1[3] + CFLF * (s1b[3] - s2b[3]);
    if (bal == 0xffffffffu) {
        warp_store128(out_base, erow0 + EW + j, r1_0, r1_1, r1_2, r1_3);
    } else {
        float* p1 = out_base + erow0 + EW + j;
        p1[0] = r1_0; p1[1] = r1_1; p1[2] = r1_2; p1[3] = r1_3;
    }
}

// ---------------------------------------------------------------------------
// Generic faraday point helpers
// ---------------------------------------------------------------------------
__device__ float faraday_s3(const float* __restrict__ Eb, int i, int j, const MCoef& m)
{
#define Ev(r, c) Eb[(r) * EW + (c)]
    float s3 = 0.0f;
    if (j >= 1 && j <= NN - 2) {
        s3 += m.M00 * Ev(i,     j - 1) + m.M01 * Ev(i,     j)
            + m.M02 * Ev(i,     j + 1) + m.M03 * Ev(i,     j + 2);
        s3 += m.M11 * Ev(i + 1, j);
        s3 += m.M20 * Ev(i + 2, j - 1) + m.M21 * Ev(i + 2, j)
            + m.M22 * Ev(i + 2, j + 1) + m.M23 * Ev(i + 2, j + 2);
    }
    if (i <= NN - 4)
        s3 += -1.5f * Ev(i + 1, j) + 2.0f * Ev(i + 2, j) - 0.5f * Ev(i + 3, j);
    if (i >= 2)
        s3 += 0.5f * Ev(i - 1, j + 1) - 2.0f * Ev(i, j + 1) + 1.5f * Ev(i + 1, j + 1);
#undef Ev
    return s3;
}

__device__ float faraday_s4(const float* __restrict__ Eb, int i, int j, const MCoef& m)
{
#define Ev(r, c) Eb[(r) * EW + (c)]
    float s4 = 0.0f;
    if (i >= 1 && i <= NN - 2) {
        s4 += m.M00 * Ev(i - 1, j) + m.M20 * Ev(i - 1, j + 2);
        s4 += m.M01 * Ev(i,     j) + m.M11 * Ev(i, j + 1) + m.M21 * Ev(i, j + 2);
        s4 += m.M02 * Ev(i + 1, j) + m.M22 * Ev(i + 1, j + 2);
        s4 += m.M03 * Ev(i + 2, j) + m.M23 * Ev(i + 2, j + 2);
    }
    if (j <= NN - 4)
        s4 += -1.5f * Ev(i, j + 1) + 2.0f * Ev(i, j + 2) - 0.5f * Ev(i, j + 3);
    if (j >= 2)
        s4 += 0.5f * Ev(i + 1, j - 1) - 2.0f * Ev(i + 1, j) + 1.5f * Ev(i + 1, j + 1);
#undef Ev
    return s4;
}

// ---------------------------------------------------------------------------
// Faraday E section (rows i0-1 .. i0+4), 2 output rows. KE = skew of base.
// ---------------------------------------------------------------------------
template<int KE>
__device__ __forceinline__ void faraday_e_sec(const float* __restrict__ e, int base,
                                              const MCoef& m, float cA, float cB, float cC,
                                              float* __restrict__ s3a, float* __restrict__ s3b,
                                              float* __restrict__ s4a, float* __restrict__ s4b)
{
    float W0[6], W1[8], W2[8], W3[7], W4[7], W5[4];
    load_win_k<6, KE          >(e, base, W0);
    load_win_k<8, KE          >(e, base + EW - 1, W1);
    load_win_k<8, (KE + 1) & 3>(e, base + 2 * EW - 1, W2);
    load_win_k<7, (KE + 2) & 3>(e, base + 3 * EW - 1, W3);
    load_win_k<7, (KE + 3) & 3>(e, base + 4 * EW - 1, W4);
    load_win_k<4, (KE + 1) & 3>(e, base + 5 * EW, W5);

    #pragma unroll
    for (int q = 0; q < 4; q++) {
        s3a[q] += 0.5f * W0[q + 1];
        s4a[q] += m.M00 * W0[q] + m.M20 * W0[q + 2];
        s3a[q] += m.M00 * W1[q] + m.M01 * W1[q + 1] + cA * W1[q + 2] + m.M03 * W1[q + 3];
        s4a[q] += m.M01 * W1[q + 1] + cB * W1[q + 2] + cC * W1[q + 3] - 0.5f * W1[q + 4];
        s3b[q] += 0.5f * W1[q + 2];
        s4b[q] += m.M00 * W1[q + 1] + m.M20 * W1[q + 3];
        s3a[q] += cB * W2[q + 1] + 1.5f * W2[q + 2];
        s4a[q] += 0.5f * W2[q] + cA * W2[q + 1] + 1.5f * W2[q + 2] + m.M22 * W2[q + 3];
        s3b[q] += m.M00 * W2[q] + m.M01 * W2[q + 1] + cA * W2[q + 2] + m.M03 * W2[q + 3];
        s4b[q] += m.M01 * W2[q + 1] + cB * W2[q + 2] + cC * W2[q + 3] - 0.5f * W2[q + 4];
        s3a[q] += m.M20 * W3[q] + cC * W3[q + 1] + m.M22 * W3[q + 2] + m.M23 * W3[q + 3];
        s4a[q] += m.M03 * W3[q + 1] + m.M23 * W3[q + 3];
        s3b[q] += cB * W3[q + 1] + 1.5f * W3[q + 2];
        s4b[q] += 0.5f * W3[q] + cA * W3[q + 1] + 1.5f * W3[q + 2] + m.M22 * W3[q + 3];
        s3a[q] += -0.5f * W4[q + 1];
        s3b[q] += m.M20 * W4[q] + cC * W4[q + 1] + m.M22 * W4[q + 2] + m.M23 * W4[q + 3];
        s4b[q] += m.M03 * W4[q + 1] + m.M23 * W4[q + 3];
        s3b[q] += -0.5f * W5[q];
    }
}

// ---------------------------------------------------------------------------
// Faraday border body (cold path, noinline).
// ---------------------------------------------------------------------------
#define FB_R0 4096                // 2*2048
#define FB_R1 8192                // 4*2048
#define FB_R2 10210               // 2042*5
#define FB_R3 18378               // 2042*9
#define FB_N  (FB_R0 + FB_R1 + FB_R2 + FB_R3)   // 40876
#define FB_YBLKS ((FB_N + 2047) / 2048)         // 20

__device__ __noinline__ void faraday_border_body(
    int idx, int b,
    const float* __restrict__ e_base,  int e_off,
    const float* __restrict__ hx_base, int hx_off,
    const float* __restrict__ hy_base, int hy_off,
    float* __restrict__ out_base,      int hxo_off, int hyo_off)
{
    if (idx >= FB_N) return;
    int i, j;
    if (idx < FB_R0) { i = idx / NN; j = idx % NN; }
    else if (idx < FB_R0 + FB_R1) { int r = idx - FB_R0; i = 2044 + r / NN; j = r % NN; }
    else if (idx < FB_R0 + FB_R1 + FB_R2) { int r = idx - (FB_R0 + FB_R1); i = 2 + r / 5; j = r % 5; }
    else { int r = idx - (FB_R0 + FB_R1 + FB_R2); i = 2 + r / 9; j = 2039 + r % 9; }

    int i0 = i & ~1;
    int sF = hxo_off & 3;
    int js = j - ((j + sF) & 3);
    if (i0 >= 2 && i0 <= NN - 5 && js >= 2 && js <= NN - 7) return;  // main covered it

    MCoef m = load_M();
    const float* Eb  = e_base + e_off + b * EN;
    const float* Hxb = hx_base + hx_off + b * HXN;
    const float* Hyb = hy_base + hy_off + b * HYN;
    float* Hxob = out_base + hxo_off + b * HXN;
    float* Hyob = out_base + hyo_off + b * HYN;

    if (i < HXH && j < HXW) {
        float s3 = faraday_s3(Eb, i, j, m);
        Hxob[i * HXW + j] = Hxb[i * HXW + j] - CFLF * s3;
    }
    if (i < HYH && j < HYW) {
        float s4 = faraday_s4(Eb, i, j, m);
        Hyob[i * HYW + j] = Hyb[i * HYW + j] + CFLF * s4;
    }
}

// ---------------------------------------------------------------------------
// Faraday: main interior blocks (y < 256) + border blocks (y >= 256).
// ---------------------------------------------------------------------------
__global__ __launch_bounds__(128, 10)
void k_faraday(const float* __restrict__ e_base,  int e_off,
               const float* __restrict__ hx_base, int hx_off,
               const float* __restrict__ hy_base, int hy_off,
               float* __restrict__ out_base,      int hxo_off, int hyo_off)
{
    int b = blockIdx.z;
    if (blockIdx.y >= 256) {
        int idx = ((blockIdx.y - 256) * 16 + blockIdx.x) * 128
                + threadIdx.y * 32 + threadIdx.x;
        faraday_border_body(idx, b, e_base, e_off, hx_base, hx_off,
                            hy_base, hy_off, out_base, hxo_off, hyo_off);
        return;
    }

    int t  = blockIdx.x * 32 + threadIdx.x;
    int i0 = (blockIdx.y * 4 + threadIdx.y) * 2;
    if (i0 < 2 || i0 > NN - 5) return;        // warp-uniform

    const int sF = hxo_off & 3;
    const int j = 4 * t - sF;
    const bool fast = (j >= 2) && (j <= NN - 7);
    const unsigned bal = __ballot_sync(0xffffffffu, fast);
    if (!fast) return;

    MCoef m = load_M();
    const float cA = g_coef[11];
    const float cB = g_coef[12];
    const float cC = g_coef[13];

    const int eb = e_off + b * EN;
    const int xb = hx_off + b * HXN;
    const int yb = hy_off + b * HYN;

    float s3a[4] = {0, 0, 0, 0}, s3b[4] = {0, 0, 0, 0};
    float s4a[4] = {0, 0, 0, 0}, s4b[4] = {0, 0, 0, 0};

    const int ebase = eb + (i0 - 1) * EW + j;
    switch (ebase & 3) {
        case 0: faraday_e_sec<0>(e_base, ebase, m, cA, cB, cC, s3a, s3b, s4a, s4b); break;
        case 1: faraday_e_sec<1>(e_base, ebase, m, cA, cB, cC, s3a, s3b, s4a, s4b); break;
        case 2: faraday_e_sec<2>(e_base, ebase, m, cA, cB, cC, s3a, s3b, s4a, s4b); break;
        case 3: faraday_e_sec<3>(e_base, ebase, m, cA, cB, cC, s3a, s3b, s4a, s4b); break;
    }

    // H inputs loaded LATE to minimize live registers through the E section.
    float hx0[4], hx1[4], hy0[4], hy1[4];
    const int hxidx = xb + i0 * HXW + j;      // HXW == 0 mod 4
    switch (hxidx & 3) {
        case 0: load_win_k<4, 0>(hx_base, hxidx, hx0); load_win_k<4, 0>(hx_base, hxidx + HXW, hx1); break;
        case 1: load_win_k<4, 1>(hx_base, hxidx, hx0); load_win_k<4, 1>(hx_base, hxidx + HXW, hx1); break;
        case 2: load_win_k<4, 2>(hx_base, hxidx, hx0); load_win_k<4, 2>(hx_base, hxidx + HXW, hx1); break;
        case 3: load_win_k<4, 3>(hx_base, hxidx, hx0); load_win_k<4, 3>(hx_base, hxidx + HXW, hx1); break;
    }
    const int hyidx = yb + i0 * HYW + j;      // HYW == 3 mod 4
    switch (hyidx & 3) {
        case 0: load_win_k<4, 0>(hy_base, hyidx, hy0); load_win_k<4, 3>(hy_base, hyidx + HYW, hy1); break;
        case 1: load_win_k<4, 1>(hy_base, hyidx, hy0); load_win_k<4, 0>(hy_base, hyidx + HYW, hy1); break;
        case 2: load_win_k<4, 2>(hy_base, hyidx, hy0); load_win_k<4, 1>(hy_base, hyidx + HYW, hy1); break;
        case 3: load_win_k<4, 3>(hy_base, hyidx, hy0); load_win_k<4, 2>(hy_base, hyidx + HYW, hy1); break;
    }

    float4 w;
    w.x = hx0[0] - CFLF * s3a[0];
    w.y = hx0[1] - CFLF * s3a[1];
    w.z = hx0[2] - CFLF * s3a[2];
    w.w = hx0[3] - CFLF * s3a[3];
    *reinterpret_cast<float4*>(out_base + hxo_off + b * HXN + i0 * HXW + j) = w;
    w.x = hx1[0] - CFLF * s3b[0];
    w.y = hx1[1] - CFLF * s3b[1];
    w.z = hx1[2] - CFLF * s3b[2];
    w.w = hx1[3] - CFLF * s3b[3];
    *reinterpret_cast<float4*>(out_base + hxo_off + b * HXN + (i0 + 1) * HXW + j) = w;

    float wy00 = hy0[0] + CFLF * s4a[0];
    float wy01 = hy0[1] + CFLF * s4a[1];
    float wy02 = hy0[2] + CFLF * s4a[2];
    float wy03 = hy0[3] + CFLF * s4a[3];
    float wy10 = hy1[0] + CFLF * s4b[0];
    float wy11 = hy1[1] + CFLF * s4b[1];
    float wy12 = hy1[2] + CFLF * s4b[2];
    float wy13 = hy1[3] + CFLF * s4b[3];
    if (bal == 0xffffffffu) {
        warp_store128(out_base, hyo_off + b * HYN + i0 * HYW + j, wy00, wy01, wy02, wy03);
        warp_store128(out_base, hyo_off + b * HYN + (i0 + 1) * HYW + j, wy10, wy11, wy12, wy13);
    } else {
        float* p0 = out_base + hyo_off + b * HYN + i0 * HYW + j;
        float* p1 = p0 + HYW;
        p0[0] = wy00; p0[1] = wy01; p0[2] = wy02; p0[3] = wy03;
        p1[0] = wy10; p1[1] = wy11; p1[2] = wy12; p1[3] = wy13;
    }
}

// ---------------------------------------------------------------------------
extern "C" void kernel_launch(void* const* d_in, const int* in_sizes, int n_in,
                              void* d_out, int out_size)
{
    const float* sb = (const float*)d_in[3];
    const float* sd = (const float*)d_in[4];
    const float* sg = (const float*)d_in[5];
    float* out = (float*)d_out;

    const float* e_base  = (const float*)d_in[0]; int e_off  = 0;
    const float* hx_base = (const float*)d_in[1]; int hx_off = 0;
    const float* hy_base = (const float*)d_in[2]; int hy_off = 0;

    const int STEP = BB * (EN + HXN + HYN);

    k_setup<<<1, 1>>>(sb, sd, sg);

    dim3 blk(32, 4, 1);
    dim3 gA(16, 256 + AB_YBLKS, BB);          // main rows + amper border band
    dim3 gF(16, 256 + FB_YBLKS, BB);          // main rows + faraday border band

    for (int k = 0; k < 3; k++) {
        int eo_off  = k * STEP;
        int hxo_off = eo_off + BB * EN;
        int hyo_off = hxo_off + BB * HXN;

        k_amper<<<gA, blk>>>(e_base, e_off, hx_base, hx_off, hy_base, hy_off,
                             out, eo_off);
        k_faraday<<<gF, blk>>>(out, eo_off, hx_base, hx_off, hy_base, hy_off,
                               out, hxo_off, hyo_off);

        e_base = out;  e_off  = eo_off;
        hx_base = out; hx_off = hxo_off;
        hy_base = out; hy_off = hyo_off;
    }
}

// round 15
// speedup vs baseline: 1.4734x; 1.0088x over previous
#include <cuda_runtime.h>

// Problem constants (fixed: N=2048, B=2)
#define NN   2048
#define BB   2
#define EW   (NN + 1)            // 2049  (== 1 mod 4)
#define HXH  (NN - 1)            // 2047
#define HXW  (NN)                // 2048  (== 0 mod 4)
#define HYH  (NN)                // 2048
#define HYW  (NN - 1)            // 2047  (== 3 mod 4)
#define EN   (EW * EW)
#define HXN  (HXH * HXW)
#define HYN  (HYH * HYW)
#define CFLF 0.35f

#define KF0 (-11.0f / 6.0f)
#define KF1 (3.0f)
#define KF2 (-1.5f)
#define KF3 (1.0f / 3.0f)
#define KB0 (-1.0f / 3.0f)
#define KB1 (1.5f)
#define KB2 (-3.0f)
#define KB3 (11.0f / 6.0f)

struct MCoef {
    float M00, M01, M02, M03, M11, M20, M21, M22, M23;
};

// Precomputed coefficients, filled once by k_setup:
// [0..8]  M00..M23  [9] cM21KF0  [10] cM02KB3  [11] cA  [12] cB  [13] cC
__device__ float g_coef[16];

__global__ void k_setup(const float* __restrict__ sb,
                        const float* __restrict__ sd,
                        const float* __restrict__ sg)
{
    float beta = *sb, delta = *sd, gamma = *sg;
    float M00 = -0.25f * beta + 0.1f * gamma;
    float M01 =  0.25f * beta + delta - 0.5f - 0.1f * gamma;
    float M02 =  0.25f * beta - 0.1f * gamma;
    float M03 = -0.25f * beta + 0.1f * gamma;
    float M11 = -2.0f * delta;
    float M20 =  0.25f * beta - 0.1f * gamma;
    float M21 = -0.25f * beta + delta + 0.5f + 0.1f * gamma;
    float M22 = -0.25f * beta - 0.1f * gamma;
    float M23 =  0.25f * beta + 0.1f * gamma;
    g_coef[0] = M00;  g_coef[1] = M01;  g_coef[2] = M02;  g_coef[3] = M03;
    g_coef[4] = M11;  g_coef[5] = M20;  g_coef[6] = M21;  g_coef[7] = M22;
    g_coef[8] = M23;
    g_coef[9]  = M21 + KF0;
    g_coef[10] = M02 + KB3;
    g_coef[11] = M02 - 2.0f;
    g_coef[12] = M11 - 1.5f;
    g_coef[13] = M21 + 2.0f;
    g_coef[14] = 0.0f; g_coef[15] = 0.0f;
}

__device__ __forceinline__ MCoef load_M() {
    const float4* cp = reinterpret_cast<const float4*>(g_coef);
    float4 c0 = cp[0], c1 = cp[1], c2 = cp[2];
    MCoef m;
    m.M00 = c0.x; m.M01 = c0.y; m.M02 = c0.z; m.M03 = c0.w;
    m.M11 = c1.x; m.M20 = c1.y; m.M21 = c1.z; m.M22 = c1.w;
    m.M23 = c2.x;
    return m;
}

// ---------------------------------------------------------------------------
// Warp-coalesced store (whole warp must participate).
// ---------------------------------------------------------------------------
__device__ __forceinline__ void warp_store128(float* __restrict__ out, int gi,
                                              float v0, float v1, float v2, float v3)
{
    const unsigned FULL = 0xffffffffu;
    const int lane = threadIdx.x & 31;
    const int s = gi & 3;
    if (s == 0) {
        float4 w; w.x = v0; w.y = v1; w.z = v2; w.w = v3;
        *reinterpret_cast<float4*>(out + gi) = w;
        return;
    }
    float n0 = __shfl_down_sync(FULL, v0, 1);
    float n1 = __shfl_down_sync(FULL, v1, 1);
    float n2 = __shfl_down_sync(FULL, v2, 1);
    if (s == 1) {
        if (lane < 31) {
            float4 w; w.x = v3; w.y = n0; w.z = n1; w.w = n2;
            *reinterpret_cast<float4*>(out + gi + 3) = w;
        }
        if (lane == 0)  { out[gi] = v0; out[gi + 1] = v1; out[gi + 2] = v2; }
        else if (lane == 31) { out[gi + 3] = v3; }
    } else if (s == 2) {
        if (lane < 31) {
            float4 w; w.x = v2; w.y = v3; w.z = n0; w.w = n1;
            *reinterpret_cast<float4*>(out + gi + 2) = w;
        }
        if (lane == 0)  { out[gi] = v0; out[gi + 1] = v1; }
        else if (lane == 31) { out[gi + 2] = v2; out[gi + 3] = v3; }
    } else {
        if (lane < 31) {
            float4 w; w.x = v1; w.y = v2; w.z = v3; w.w = n0;
            *reinterpret_cast<float4*>(out + gi + 1) = w;
        }
        if (lane == 0)  { out[gi] = v0; }
        else if (lane == 31) { out[gi + 1] = v1; out[gi + 2] = v2; out[gi + 3] = v3; }
    }
}

// ---------------------------------------------------------------------------
// Compile-time-skew window load: out[t] = buf[idx+t], requires (idx&3)==K.
// ---------------------------------------------------------------------------
template<int W, int K>
__device__ __forceinline__ void load_win_k(const float* __restrict__ buf, int idx,
                                           float* __restrict__ out)
{
    constexpr int NV = (W + K + 3) / 4;
    const float4* p = reinterpret_cast<const float4*>(buf + (idx - K));
    float f[NV * 4];
    #pragma unroll
    for (int t = 0; t < NV; t++)
        *reinterpret_cast<float4*>(f + 4 * t) = p[t];
    #pragma unroll
    for (int t = 0; t < W; t++) out[t] = f[t + K];
}

// ---------------------------------------------------------------------------
// Generic (boundary) amper point.
// ---------------------------------------------------------------------------
__device__ float amper_point(const float* __restrict__ Hxb,
                             const float* __restrict__ Hyb,
                             int i, int j, const MCoef& m)
{
    float s1 = 0.0f, s2 = 0.0f;
    bool irow = (i >= 2 && i <= NN - 2);
    bool jcol = (j >= 2 && j <= NN - 2);

#define HYv(r, c) Hyb[(r) * HYW + (c)]
#define HXv(r, c) Hxb[(r) * HXW + (c)]
    if (irow && jcol) {
        s1 += m.M00 * HYv(i - 2, j - 2) + m.M20 * HYv(i - 2, j);
        s1 += m.M01 * HYv(i - 1, j - 2) + m.M11 * HYv(i - 1, j - 1) + m.M21 * HYv(i - 1, j);
        s1 += m.M02 * HYv(i,     j - 2) + m.M22 * HYv(i,     j);
        s1 += m.M03 * HYv(i + 1, j - 2) + m.M23 * HYv(i + 1, j);
        s2 += m.M00 * HXv(i - 2, j - 2) + m.M01 * HXv(i - 2, j - 1)
            + m.M02 * HXv(i - 2, j)     + m.M03 * HXv(i - 2, j + 1);
        s2 += m.M11 * HXv(i - 1, j - 1);
        s2 += m.M20 * HXv(i,     j - 2) + m.M21 * HXv(i,     j - 1)
            + m.M22 * HXv(i,     j)     + m.M23 * HXv(i,     j + 1);
    }
    if (i >= 1 && j <= NN - 5) {
        s1 += KF0 * HYv(i - 1, j)     + KF1 * HYv(i - 1, j + 1)
            + KF2 * HYv(i - 1, j + 2) + KF3 * HYv(i - 1, j + 3);
    }
    if (i <= NN - 1 && j >= 5) {
        s1 += KB0 * HYv(i, j - 5) + KB1 * HYv(i, j - 4)
            + KB2 * HYv(i, j - 3) + KB3 * HYv(i, j - 2);
    }
    if (irow && j >= 1 && j <= 2) {
        s1 += -HYv(i - 1, j - 1) + 3.0f * HYv(i - 1, j)
              - 3.0f * HYv(i - 1, j + 1) + HYv(i - 1, j + 2);
    }
    if (irow && j >= NN - 2 && j <= NN - 1) {
        s1 += HYv(i, j - 4) - 3.0f * HYv(i, j - 3)
            + 3.0f * HYv(i, j - 2) - HYv(i, j - 1);
    }
    if (j >= 1 && i <= NN - 5) {
        s2 += KF0 * HXv(i, j - 1)     + KF1 * HXv(i + 1, j - 1)
            + KF2 * HXv(i + 2, j - 1) + KF3 * HXv(i + 3, j - 1);
    }
    if (j <= NN - 1 && i >= 5) {
        s2 += KB0 * HXv(i - 5, j) + KB1 * HXv(i - 4, j)
            + KB2 * HXv(i - 3, j) + KB3 * HXv(i - 2, j);
    }
    if (jcol && i >= 1 && i <= 2) {
        s2 += -HXv(i - 1, j - 1) + 3.0f * HXv(i, j - 1)
              - 3.0f * HXv(i + 1, j - 1) + HXv(i + 2, j - 1);
    }
    if (jcol && i >= NN - 2 && i <= NN - 1) {
        s2 += HXv(i - 4, j) - 3.0f * HXv(i - 3, j)
            + 3.0f * HXv(i - 2, j) - HXv(i - 1, j);
    }
#undef HYv
#undef HXv
    return s1 - s2;
}

// ---------------------------------------------------------------------------
// Amper Hy section (rows i0-2 .. i0+2), 2 output rows. KY = skew of base.
// ---------------------------------------------------------------------------
template<int KY>
__device__ __forceinline__ void amper_hy_sec(const float* __restrict__ hy, int base,
                                             const MCoef& m, float cM21KF0, float cM02KB3,
                                             float* __restrict__ s1a, float* __restrict__ s1b)
{
    float Y0[6], Y1[9], Y2[12], Y3[9], Y4[6];
    load_win_k<6,  KY          >(hy, base, Y0);
    load_win_k<9,  (KY + 3) & 3>(hy, base + HYW, Y1);
    load_win_k<12, (KY + 3) & 3>(hy, base + 2 * HYW - 3, Y2);
    load_win_k<9,  (KY + 2) & 3>(hy, base + 3 * HYW - 3, Y3);
    load_win_k<6,  KY          >(hy, base + 4 * HYW, Y4);

    #pragma unroll
    for (int q = 0; q < 4; q++) {
        s1a[q] += m.M00 * Y0[q] + m.M20 * Y0[q + 2];
        s1a[q] += m.M01 * Y1[q] + m.M11 * Y1[q + 1] + cM21KF0 * Y1[q + 2]
                + KF1 * Y1[q + 3] + KF2 * Y1[q + 4] + KF3 * Y1[q + 5];
        s1b[q] += m.M00 * Y1[q] + m.M20 * Y1[q + 2];
        s1a[q] += KB0 * Y2[q] + KB1 * Y2[q + 1] + KB2 * Y2[q + 2]
                + cM02KB3 * Y2[q + 3] + m.M22 * Y2[q + 5];
        s1b[q] += m.M01 * Y2[q + 3] + m.M11 * Y2[q + 4] + cM21KF0 * Y2[q + 5]
                + KF1 * Y2[q + 6] + KF2 * Y2[q + 7] + KF3 * Y2[q + 8];
        s1a[q] += m.M03 * Y3[q + 3] + m.M23 * Y3[q + 5];
        s1b[q] += KB0 * Y3[q] + KB1 * Y3[q + 1] + KB2 * Y3[q + 2]
                + cM02KB3 * Y3[q + 3] + m.M22 * Y3[q + 5];
        s1b[q] += m.M03 * Y4[q] + m.M23 * Y4[q + 2];
    }
}

// ---------------------------------------------------------------------------
// Amper Hx section (rows i0-5 .. i0+4), 2 output rows. KX = skew of base.
// ---------------------------------------------------------------------------
template<int KX>
__device__ __forceinline__ void amper_hx_sec(const float* __restrict__ hx, int base,
                                             const MCoef& m, float cM21KF0, float cM02KB3,
                                             float* __restrict__ s2a, float* __restrict__ s2b)
{
    float X0[4], X1[4], X2[4], X3[7], X4[7], X5[7], X6[7], X7[4], X8[4], X9[4];
    load_win_k<4, KX          >(hx, base, X0);
    load_win_k<4, KX          >(hx, base + HXW, X1);
    load_win_k<4, KX          >(hx, base + 2 * HXW, X2);
    load_win_k<7, (KX + 2) & 3>(hx, base + 3 * HXW - 2, X3);
    load_win_k<7, (KX + 2) & 3>(hx, base + 4 * HXW - 2, X4);
    load_win_k<7, (KX + 2) & 3>(hx, base + 5 * HXW - 2, X5);
    load_win_k<7, (KX + 2) & 3>(hx, base + 6 * HXW - 2, X6);
    load_win_k<4, (KX + 3) & 3>(hx, base + 7 * HXW - 1, X7);
    load_win_k<4, (KX + 3) & 3>(hx, base + 8 * HXW - 1, X8);
    load_win_k<4, (KX + 3) & 3>(hx, base + 9 * HXW - 1, X9);

    #pragma unroll
    for (int q = 0; q < 4; q++) {
        s2a[q] += KB0 * X0[q] + KB1 * X1[q] + KB2 * X2[q];
        s2b[q] += KB0 * X1[q] + KB1 * X2[q];
        s2a[q] += m.M00 * X3[q] + m.M01 * X3[q + 1] + cM02KB3 * X3[q + 2] + m.M03 * X3[q + 3];
        s2b[q] += KB2 * X3[q + 2];
        s2a[q] += m.M11 * X4[q + 1];
        s2b[q] += m.M00 * X4[q] + m.M01 * X4[q + 1] + cM02KB3 * X4[q + 2] + m.M03 * X4[q + 3];
        s2a[q] += m.M20 * X5[q] + cM21KF0 * X5[q + 1] + m.M22 * X5[q + 2] + m.M23 * X5[q + 3];
        s2b[q] += m.M11 * X5[q + 1];
        s2a[q] += KF1 * X6[q + 1];
        s2b[q] += m.M20 * X6[q] + cM21KF0 * X6[q + 1] + m.M22 * X6[q + 2] + m.M23 * X6[q + 3];
        s2a[q] += KF2 * X7[q] + KF3 * X8[q];
        s2b[q] += KF1 * X7[q] + KF2 * X8[q] + KF3 * X9[q];
    }
}

// ---------------------------------------------------------------------------
// Amper border body (cold path, noinline; spills are fine).
// ---------------------------------------------------------------------------
#define AB_R0 12294               // 6*2049
#define AB_R1 10245               // 5*2049
#define AB_R2 16304               // 2038*8
#define AB_R3 22418               // 2038*11
#define AB_N  (AB_R0 + AB_R1 + AB_R2 + AB_R3)   // 61261
#define AB_YBLKS ((AB_N + 2047) / 2048)         // 30

__device__ __noinline__ void amper_border_body(
    int idx, int b,
    const float* __restrict__ e_base,  int e_off,
    const float* __restrict__ hx_base, int hx_off,
    const float* __restrict__ hy_base, int hy_off,
    float* __restrict__ out_base,      int eo_off)
{
    if (idx >= AB_N) return;
    int i, j;
    if (idx < AB_R0) { i = idx / EW; j = idx % EW; }
    else if (idx < AB_R0 + AB_R1) { int r = idx - AB_R0; i = 2044 + r / EW; j = r % EW; }
    else if (idx < AB_R0 + AB_R1 + AB_R2) { int r = idx - (AB_R0 + AB_R1); i = 6 + r / 8; j = r % 8; }
    else { int r = idx - (AB_R0 + AB_R1 + AB_R2); i = 6 + r / 11; j = 2038 + r % 11; }

    int i0 = i & ~1;
    int s = (eo_off + b * EN + i0 * EW) & 3;
    int js = j - ((j + s) & 3);
    if (i0 >= 5 && i0 <= NN - 6 && js >= 5 && js <= NN - 8) return;  // main covered it

    MCoef m = load_M();
    const float* Hxb = hx_base + hx_off + b * HXN;
    const float* Hyb = hy_base + hy_off + b * HYN;
    float d = amper_point(Hxb, Hyb, i, j, m);
    out_base[eo_off + b * EN + i * EW + j] =
        e_base[e_off + b * EN + i * EW + j] + CFLF * d;
}

// ---------------------------------------------------------------------------
// Amper: main interior blocks (y < 256) + border blocks (y >= 256).
// ---------------------------------------------------------------------------
__global__ __launch_bounds__(128, 10)
void k_amper(const float* __restrict__ e_base,  int e_off,
             const float* __restrict__ hx_base, int hx_off,
             const float* __restrict__ hy_base, int hy_off,
             float* __restrict__ out_base,      int eo_off)
{
    int b = blockIdx.z;
    if (blockIdx.y >= 256) {
        int idx = ((blockIdx.y - 256) * 16 + blockIdx.x) * 128
                + threadIdx.y * 32 + threadIdx.x;
        amper_border_body(idx, b, e_base, e_off, hx_base, hx_off,
                          hy_base, hy_off, out_base, eo_off);
        return;
    }

    int t  = blockIdx.x * 32 + threadIdx.x;
    int i0 = (blockIdx.y * 4 + threadIdx.y) * 2;
    if (i0 < 5 || i0 > NN - 6) return;        // warp-uniform

    const int erow0 = eo_off + b * EN + i0 * EW;
    const int s = erow0 & 3;
    const int j = 4 * t - s;
    const bool fast = (j >= 5) && (j <= NN - 8);
    const unsigned bal = __ballot_sync(0xffffffffu, fast);
    if (!fast) return;

    MCoef m = load_M();
    const float cM21KF0 = g_coef[9];
    const float cM02KB3 = g_coef[10];

    const int xb = hx_off + b * HXN;
    const int yb = hy_off + b * HYN;

    float s1a[4] = {0, 0, 0, 0}, s1b[4] = {0, 0, 0, 0};
    float s2a[4] = {0, 0, 0, 0}, s2b[4] = {0, 0, 0, 0};

    const int ybase = yb + (i0 - 2) * HYW + (j - 2);
    switch (ybase & 3) {
        case 0: amper_hy_sec<0>(hy_base, ybase, m, cM21KF0, cM02KB3, s1a, s1b); break;
        case 1: amper_hy_sec<1>(hy_base, ybase, m, cM21KF0, cM02KB3, s1a, s1b); break;
        case 2: amper_hy_sec<2>(hy_base, ybase, m, cM21KF0, cM02KB3, s1a, s1b); break;
        case 3: amper_hy_sec<3>(hy_base, ybase, m, cM21KF0, cM02KB3, s1a, s1b); break;
    }

    const int xbase = xb + (i0 - 5) * HXW + j;
    switch (xbase & 3) {
        case 0: amper_hx_sec<0>(hx_base, xbase, m, cM21KF0, cM02KB3, s2a, s2b); break;
        case 1: amper_hx_sec<1>(hx_base, xbase, m, cM21KF0, cM02KB3, s2a, s2b); break;
        case 2: amper_hx_sec<2>(hx_base, xbase, m, cM21KF0, cM02KB3, s2a, s2b); break;
        case 3: amper_hx_sec<3>(hx_base, xbase, m, cM21KF0, cM02KB3, s2a, s2b); break;
    }

    // E input loaded LATE to minimize live registers through the stencil body.
    float E0[4], E1[4];
    const int eidx = e_off + b * EN + i0 * EW + j;
    switch (eidx & 3) {
        case 0: load_win_k<4, 0>(e_base, eidx, E0); load_win_k<4, 1>(e_base, eidx + EW, E1); break;
        case 1: load_win_k<4, 1>(e_base, eidx, E0); load_win_k<4, 2>(e_base, eidx + EW, E1); break;
        case 2: load_win_k<4, 2>(e_base, eidx, E0); load_win_k<4, 3>(e_base, eidx + EW, E1); break;
        case 3: load_win_k<4, 3>(e_base, eidx, E0); load_win_k<4, 0>(e_base, eidx + EW, E1); break;
    }

    float4 w;
    w.x = E0[0] + CFLF * (s1a[0] - s2a[0]);
    w.y = E0[1] + CFLF * (s1a[1] - s2a[1]);
    w.z = E0[2] + CFLF * (s1a[2] - s2a[2]);
    w.w = E0[3] + CFLF * (s1a[3] - s2a[3]);
    *reinterpret_cast<float4*>(out_base + erow0 + j) = w;   // aligned by construction

    float r1_0 = E1[0] + CFLF * (s1b[0] - s2b[0]);
    float r1_1 = E1[1] + CFLF * (s1b[1] - s2b[1]);
    float r1_2 = E1[2] + CFLF * (s1b[2] - s2b[2]);
    float r1_3 = E1[3] + CFLF * (s1b[3] - s2b[3]);
    if (bal == 0xffffffffu) {
        warp_store128(out_base, erow0 + EW + j, r1_0, r1_1, r1_2, r1_3);
    } else {
        float* p1 = out_base + erow0 + EW + j;
        p1[0] = r1_0; p1[1] = r1_1; p1[2] = r1_2; p1[3] = r1_3;
    }
}

// ---------------------------------------------------------------------------
// Generic faraday point helpers
// ---------------------------------------------------------------------------
__device__ float faraday_s3(const float* __restrict__ Eb, int i, int j, const MCoef& m)
{
#define Ev(r, c) Eb[(r) * EW + (c)]
    float s3 = 0.0f;
    if (j >= 1 && j <= NN - 2) {
        s3 += m.M00 * Ev(i,     j - 1) + m.M01 * Ev(i,     j)
            + m.M02 * Ev(i,     j + 1) + m.M03 * Ev(i,     j + 2);
        s3 += m.M11 * Ev(i + 1, j);
        s3 += m.M20 * Ev(i + 2, j - 1) + m.M21 * Ev(i + 2, j)
            + m.M22 * Ev(i + 2, j + 1) + m.M23 * Ev(i + 2, j + 2);
    }
    if (i <= NN - 4)
        s3 += -1.5f * Ev(i + 1, j) + 2.0f * Ev(i + 2, j) - 0.5f * Ev(i + 3, j);
    if (i >= 2)
        s3 += 0.5f * Ev(i - 1, j + 1) - 2.0f * Ev(i, j + 1) + 1.5f * Ev(i + 1, j + 1);
#undef Ev
    return s3;
}

__device__ float faraday_s4(const float* __restrict__ Eb, int i, int j, const MCoef& m)
{
#define Ev(r, c) Eb[(r) * EW + (c)]
    float s4 = 0.0f;
    if (i >= 1 && i <= NN - 2) {
        s4 += m.M00 * Ev(i - 1, j) + m.M20 * Ev(i - 1, j + 2);
        s4 += m.M01 * Ev(i,     j) + m.M11 * Ev(i, j + 1) + m.M21 * Ev(i, j + 2);
        s4 += m.M02 * Ev(i + 1, j) + m.M22 * Ev(i + 1, j + 2);
        s4 += m.M03 * Ev(i + 2, j) + m.M23 * Ev(i + 2, j + 2);
    }
    if (j <= NN - 4)
        s4 += -1.5f * Ev(i, j + 1) + 2.0f * Ev(i, j + 2) - 0.5f * Ev(i, j + 3);
    if (j >= 2)
        s4 += 0.5f * Ev(i + 1, j - 1) - 2.0f * Ev(i + 1, j) + 1.5f * Ev(i + 1, j + 1);
#undef Ev
    return s4;
}

// ---------------------------------------------------------------------------
// Faraday E section (rows i0-1 .. i0+4), 2 output rows. KE = skew of base.
// ---------------------------------------------------------------------------
template<int KE>
__device__ __forceinline__ void faraday_e_sec(const float* __restrict__ e, int base,
                                              const MCoef& m, float cA, float cB, float cC,
                                              float* __restrict__ s3a, float* __restrict__ s3b,
                                              float* __restrict__ s4a, float* __restrict__ s4b)
{
    float W0[6], W1[8], W2[8], W3[7], W4[7], W5[4];
    load_win_k<6, KE          >(e, base, W0);
    load_win_k<8, KE          >(e, base + EW - 1, W1);
    load_win_k<8, (KE + 1) & 3>(e, base + 2 * EW - 1, W2);
    load_win_k<7, (KE + 2) & 3>(e, base + 3 * EW - 1, W3);
    load_win_k<7, (KE + 3) & 3>(e, base + 4 * EW - 1, W4);
    load_win_k<4, (KE + 1) & 3>(e, base + 5 * EW, W5);

    #pragma unroll
    for (int q = 0; q < 4; q++) {
        s3a[q] += 0.5f * W0[q + 1];
        s4a[q] += m.M00 * W0[q] + m.M20 * W0[q + 2];
        s3a[q] += m.M00 * W1[q] + m.M01 * W1[q + 1] + cA * W1[q + 2] + m.M03 * W1[q + 3];
        s4a[q] += m.M01 * W1[q + 1] + cB * W1[q + 2] + cC * W1[q + 3] - 0.5f * W1[q + 4];
        s3b[q] += 0.5f * W1[q + 2];
        s4b[q] += m.M00 * W1[q + 1] + m.M20 * W1[q + 3];
        s3a[q] += cB * W2[q + 1] + 1.5f * W2[q + 2];
        s4a[q] += 0.5f * W2[q] + cA * W2[q + 1] + 1.5f * W2[q + 2] + m.M22 * W2[q + 3];
        s3b[q] += m.M00 * W2[q] + m.M01 * W2[q + 1] + cA * W2[q + 2] + m.M03 * W2[q + 3];
        s4b[q] += m.M01 * W2[q + 1] + cB * W2[q + 2] + cC * W2[q + 3] - 0.5f * W2[q + 4];
        s3a[q] += m.M20 * W3[q] + cC * W3[q + 1] + m.M22 * W3[q + 2] + m.M23 * W3[q + 3];
        s4a[q] += m.M03 * W3[q + 1] + m.M23 * W3[q + 3];
        s3b[q] += cB * W3[q + 1] + 1.5f * W3[q + 2];
        s4b[q] += 0.5f * W3[q] + cA * W3[q + 1] + 1.5f * W3[q + 2] + m.M22 * W3[q + 3];
        s3a[q] += -0.5f * W4[q + 1];
        s3b[q] += m.M20 * W4[q] + cC * W4[q + 1] + m.M22 * W4[q + 2] + m.M23 * W4[q + 3];
        s4b[q] += m.M03 * W4[q + 1] + m.M23 * W4[q + 3];
        s3b[q] += -0.5f * W5[q];
    }
}

// ---------------------------------------------------------------------------
// Faraday border body (cold path, noinline).
// ---------------------------------------------------------------------------
#define FB_R0 4096                // 2*2048
#define FB_R1 8192                // 4*2048
#define FB_R2 10210               // 2042*5
#define FB_R3 18378               // 2042*9
#define FB_N  (FB_R0 + FB_R1 + FB_R2 + FB_R3)   // 40876
#define FB_YBLKS ((FB_N + 2047) / 2048)         // 20

__device__ __noinline__ void faraday_border_body(
    int idx, int b,
    const float* __restrict__ e_base,  int e_off,
    const float* __restrict__ hx_base, int hx_off,
    const float* __restrict__ hy_base, int hy_off,
    float* __restrict__ out_base,      int hxo_off, int hyo_off)
{
    if (idx >= FB_N) return;
    int i, j;
    if (idx < FB_R0) { i = idx / NN; j = idx % NN; }
    else if (idx < FB_R0 + FB_R1) { int r = idx - FB_R0; i = 2044 + r / NN; j = r % NN; }
    else if (idx < FB_R0 + FB_R1 + FB_R2) { int r = idx - (FB_R0 + FB_R1); i = 2 + r / 5; j = r % 5; }
    else { int r = idx - (FB_R0 + FB_R1 + FB_R2); i = 2 + r / 9; j = 2039 + r % 9; }

    int i0 = i & ~1;
    int sF = hxo_off & 3;
    int js = j - ((j + sF) & 3);
    if (i0 >= 2 && i0 <= NN - 5 && js >= 2 && js <= NN - 7) return;  // main covered it

    MCoef m = load_M();
    const float* Eb  = e_base + e_off + b * EN;
    const float* Hxb = hx_base + hx_off + b * HXN;
    const float* Hyb = hy_base + hy_off + b * HYN;
    float* Hxob = out_base + hxo_off + b * HXN;
    float* Hyob = out_base + hyo_off + b * HYN;

    if (i < HXH && j < HXW) {
        float s3 = faraday_s3(Eb, i, j, m);
        Hxob[i * HXW + j] = Hxb[i * HXW + j] - CFLF * s3;
    }
    if (i < HYH && j < HYW) {
        float s4 = faraday_s4(Eb, i, j, m);
        Hyob[i * HYW + j] = Hyb[i * HYW + j] + CFLF * s4;
    }
}

// ---------------------------------------------------------------------------
// Faraday: main interior blocks (y < 256) + border blocks (y >= 256).
// ---------------------------------------------------------------------------
__global__ __launch_bounds__(128, 10)
void k_faraday(const float* __restrict__ e_base,  int e_off,
               const float* __restrict__ hx_base, int hx_off,
               const float* __restrict__ hy_base, int hy_off,
               float* __restrict__ out_base,      int hxo_off, int hyo_off)
{
    int b = blockIdx.z;
    if (blockIdx.y >= 256) {
        int idx = ((blockIdx.y - 256) * 16 + blockIdx.x) * 128
                + threadIdx.y * 32 + threadIdx.x;
        faraday_border_body(idx, b, e_base, e_off, hx_base, hx_off,
                            hy_base, hy_off, out_base, hxo_off, hyo_off);
        return;
    }

    int t  = blockIdx.x * 32 + threadIdx.x;
    int i0 = (blockIdx.y * 4 + threadIdx.y) * 2;
    if (i0 < 2 || i0 > NN - 5) return;        // warp-uniform

    const int sF = hxo_off & 3;
    const int j = 4 * t - sF;
    const bool fast = (j >= 2) && (j <= NN - 7);
    const unsigned bal = __ballot_sync(0xffffffffu, fast);
    if (!fast) return;

    MCoef m = load_M();
    const float cA = g_coef[11];
    const float cB = g_coef[12];
    const float cC = g_coef[13];

    const int eb = e_off + b * EN;
    const int xb = hx_off + b * HXN;
    const int yb = hy_off + b * HYN;

    float s3a[4] = {0, 0, 0, 0}, s3b[4] = {0, 0, 0, 0};
    float s4a[4] = {0, 0, 0, 0}, s4b[4] = {0, 0, 0, 0};

    const int ebase = eb + (i0 - 1) * EW + j;
    switch (ebase & 3) {
        case 0: faraday_e_sec<0>(e_base, ebase, m, cA, cB, cC, s3a, s3b, s4a, s4b); break;
        case 1: faraday_e_sec<1>(e_base, ebase, m, cA, cB, cC, s3a, s3b, s4a, s4b); break;
        case 2: faraday_e_sec<2>(e_base, ebase, m, cA, cB, cC, s3a, s3b, s4a, s4b); break;
        case 3: faraday_e_sec<3>(e_base, ebase, m, cA, cB, cC, s3a, s3b, s4a, s4b); break;
    }

    // H inputs loaded LATE to minimize live registers through the E section.
    float hx0[4], hx1[4], hy0[4], hy1[4];
    const int hxidx = xb + i0 * HXW + j;      // HXW == 0 mod 4
    switch (hxidx & 3) {
        case 0: load_win_k<4, 0>(hx_base, hxidx, hx0); load_win_k<4, 0>(hx_base, hxidx + HXW, hx1); break;
        case 1: load_win_k<4, 1>(hx_base, hxidx, hx0); load_win_k<4, 1>(hx_base, hxidx + HXW, hx1); break;
        case 2: load_win_k<4, 2>(hx_base, hxidx, hx0); load_win_k<4, 2>(hx_base, hxidx + HXW, hx1); break;
        case 3: load_win_k<4, 3>(hx_base, hxidx, hx0); load_win_k<4, 3>(hx_base, hxidx + HXW, hx1); break;
    }
    const int hyidx = yb + i0 * HYW + j;      // HYW == 3 mod 4
    switch (hyidx & 3) {
        case 0: load_win_k<4, 0>(hy_base, hyidx, hy0); load_win_k<4, 3>(hy_base, hyidx + HYW, hy1); break;
        case 1: load_win_k<4, 1>(hy_base, hyidx, hy0); load_win_k<4, 0>(hy_base, hyidx + HYW, hy1); break;
        case 2: load_win_k<4, 2>(hy_base, hyidx, hy0); load_win_k<4, 1>(hy_base, hyidx + HYW, hy1); break;
        case 3: load_win_k<4, 3>(hy_base, hyidx, hy0); load_win_k<4, 2>(hy_base, hyidx + HYW, hy1); break;
    }

    float4 w;
    w.x = hx0[0] - CFLF * s3a[0];
    w.y = hx0[1] - CFLF * s3a[1];
    w.z = hx0[2] - CFLF * s3a[2];
    w.w = hx0[3] - CFLF * s3a[3];
    *reinterpret_cast<float4*>(out_base + hxo_off + b * HXN + i0 * HXW + j) = w;
    w.x = hx1[0] - CFLF * s3b[0];
    w.y = hx1[1] - CFLF * s3b[1];
    w.z = hx1[2] - CFLF * s3b[2];
    w.w = hx1[3] - CFLF * s3b[3];
    *reinterpret_cast<float4*>(out_base + hxo_off + b * HXN + (i0 + 1) * HXW + j) = w;

    float wy00 = hy0[0] + CFLF * s4a[0];
    float wy01 = hy0[1] + CFLF * s4a[1];
    float wy02 = hy0[2] + CFLF * s4a[2];
    float wy03 = hy0[3] + CFLF * s4a[3];
    float wy10 = hy1[0] + CFLF * s4b[0];
    float wy11 = hy1[1] + CFLF * s4b[1];
    float wy12 = hy1[2] + CFLF * s4b[2];
    float wy13 = hy1[3] + CFLF * s4b[3];
    if (bal == 0xffffffffu) {
        warp_store128(out_base, hyo_off + b * HYN + i0 * HYW + j, wy00, wy01, wy02, wy03);
        warp_store128(out_base, hyo_off + b * HYN + (i0 + 1) * HYW + j, wy10, wy11, wy12, wy13);
    } else {
        float* p0 = out_base + hyo_off + b * HYN + i0 * HYW + j;
        float* p1 = p0 + HYW;
        p0[0] = wy00; p0[1] = wy01; p0[2] = wy02; p0[3] = wy03;
        p1[0] = wy10; p1[1] = wy11; p1[2] = wy12; p1[3] = wy13;
    }
}

// ---------------------------------------------------------------------------
extern "C" void kernel_launch(void* const* d_in, const int* in_sizes, int n_in,
                              void* d_out, int out_size)
{
    const float* sb = (const float*)d_in[3];
    const float* sd = (const float*)d_in[4];
    const float* sg = (const float*)d_in[5];
    float* out = (float*)d_out;

    const float* e_base  = (const float*)d_in[0]; int e_off  = 0;
    const float* hx_base = (const float*)d_in[1]; int hx_off = 0;
    const float* hy_base = (const float*)d_in[2]; int hy_off = 0;

    const int STEP = BB * (EN + HXN + HYN);

    k_setup<<<1, 1>>>(sb, sd, sg);

    dim3 blk(32, 4, 1);
    dim3 gA(16, 256 + AB_YBLKS, BB);          // main rows + amper border band
    dim3 gF(16, 256 + FB_YBLKS, BB);          // main rows + faraday border band

    for (int k = 0; k < 3; k++) {
        int eo_off  = k * STEP;
        int hxo_off = eo_off + BB * EN;
        int hyo_off = hxo_off + BB * HXN;

        k_amper<<<gA, blk>>>(e_base, e_off, hx_base, hx_off, hy_base, hy_off,
                             out, eo_off);
        k_faraday<<<gF, blk>>>(out, eo_off, hx_base, hx_off, hy_base, hy_off,
                               out, hxo_off, hyo_off);

        e_base = out;  e_off  = eo_off;
        hx_base = out; hx_off = hxo_off;
        hy_base = out; hy_off = hyo_off;
    }
}

// round 16
// speedup vs baseline: 1.4749x; 1.0010x over previous
#include <cuda_runtime.h>

// Problem constants (fixed: N=2048, B=2)
#define NN   2048
#define BB   2
#define EW   (NN + 1)            // 2049  (== 1 mod 4)
#define HXH  (NN - 1)            // 2047
#define HXW  (NN)                // 2048  (== 0 mod 4)
#define HYH  (NN)                // 2048
#define HYW  (NN - 1)            // 2047  (== 3 mod 4)
#define EN   (EW * EW)
#define HXN  (HXH * HXW)
#define HYN  (HYH * HYW)
#define CFLF 0.35f

#define KF0 (-11.0f / 6.0f)
#define KF1 (3.0f)
#define KF2 (-1.5f)
#define KF3 (1.0f / 3.0f)
#define KB0 (-1.0f / 3.0f)
#define KB1 (1.5f)
#define KB2 (-3.0f)
#define KB3 (11.0f / 6.0f)

struct MCoef {
    float M00, M01, M02, M03, M11, M20, M21, M22, M23;
};

// Precomputed coefficients, filled once by k_setup:
// [0..8]  M00..M23  [9] cM21KF0  [10] cM02KB3  [11] cA  [12] cB  [13] cC
__device__ float g_coef[16];

__global__ void k_setup(const float* __restrict__ sb,
                        const float* __restrict__ sd,
                        const float* __restrict__ sg)
{
    float beta = *sb, delta = *sd, gamma = *sg;
    float M00 = -0.25f * beta + 0.1f * gamma;
    float M01 =  0.25f * beta + delta - 0.5f - 0.1f * gamma;
    float M02 =  0.25f * beta - 0.1f * gamma;
    float M03 = -0.25f * beta + 0.1f * gamma;
    float M11 = -2.0f * delta;
    float M20 =  0.25f * beta - 0.1f * gamma;
    float M21 = -0.25f * beta + delta + 0.5f + 0.1f * gamma;
    float M22 = -0.25f * beta - 0.1f * gamma;
    float M23 =  0.25f * beta + 0.1f * gamma;
    g_coef[0] = M00;  g_coef[1] = M01;  g_coef[2] = M02;  g_coef[3] = M03;
    g_coef[4] = M11;  g_coef[5] = M20;  g_coef[6] = M21;  g_coef[7] = M22;
    g_coef[8] = M23;
    g_coef[9]  = M21 + KF0;
    g_coef[10] = M02 + KB3;
    g_coef[11] = M02 - 2.0f;
    g_coef[12] = M11 - 1.5f;
    g_coef[13] = M21 + 2.0f;
    g_coef[14] = 0.0f; g_coef[15] = 0.0f;
}

__device__ __forceinline__ MCoef load_M() {
    const float4* cp = reinterpret_cast<const float4*>(g_coef);
    float4 c0 = cp[0], c1 = cp[1], c2 = cp[2];
    MCoef m;
    m.M00 = c0.x; m.M01 = c0.y; m.M02 = c0.z; m.M03 = c0.w;
    m.M11 = c1.x; m.M20 = c1.y; m.M21 = c1.z; m.M22 = c1.w;
    m.M23 = c2.x;
    return m;
}

// ---------------------------------------------------------------------------
// Warp-coalesced store (whole warp must participate).
// ---------------------------------------------------------------------------
__device__ __forceinline__ void warp_store128(float* __restrict__ out, int gi,
                                              float v0, float v1, float v2, float v3)
{
    const unsigned FULL = 0xffffffffu;
    const int lane = threadIdx.x & 31;
    const int s = gi & 3;
    if (s == 0) {
        float4 w; w.x = v0; w.y = v1; w.z = v2; w.w = v3;
        *reinterpret_cast<float4*>(out + gi) = w;
        return;
    }
    float n0 = __shfl_down_sync(FULL, v0, 1);
    float n1 = __shfl_down_sync(FULL, v1, 1);
    float n2 = __shfl_down_sync(FULL, v2, 1);
    if (s == 1) {
        if (lane < 31) {
            float4 w; w.x = v3; w.y = n0; w.z = n1; w.w = n2;
            *reinterpret_cast<float4*>(out + gi + 3) = w;
        }
        if (lane == 0)  { out[gi] = v0; out[gi + 1] = v1; out[gi + 2] = v2; }
        else if (lane == 31) { out[gi + 3] = v3; }
    } else if (s == 2) {
        if (lane < 31) {
            float4 w; w.x = v2; w.y = v3; w.z = n0; w.w = n1;
            *reinterpret_cast<float4*>(out + gi + 2) = w;
        }
        if (lane == 0)  { out[gi] = v0; out[gi + 1] = v1; }
        else if (lane == 31) { out[gi + 2] = v2; out[gi + 3] = v3; }
    } else {
        if (lane < 31) {
            float4 w; w.x = v1; w.y = v2; w.z = v3; w.w = n0;
            *reinterpret_cast<float4*>(out + gi + 1) = w;
        }
        if (lane == 0)  { out[gi] = v0; }
        else if (lane == 31) { out[gi + 1] = v1; out[gi + 2] = v2; out[gi + 3] = v3; }
    }
}

// ---------------------------------------------------------------------------
// Compile-time-skew window load: out[t] = buf[idx+t], requires (idx&3)==K.
// ---------------------------------------------------------------------------
template<int W, int K>
__device__ __forceinline__ void load_win_k(const float* __restrict__ buf, int idx,
                                           float* __restrict__ out)
{
    constexpr int NV = (W + K + 3) / 4;
    const float4* p = reinterpret_cast<const float4*>(buf + (idx - K));
    float f[NV * 4];
    #pragma unroll
    for (int t = 0; t < NV; t++)
        *reinterpret_cast<float4*>(f + 4 * t) = p[t];
    #pragma unroll
    for (int t = 0; t < W; t++) out[t] = f[t + K];
}

// ---------------------------------------------------------------------------
// Generic (boundary) amper point.
// ---------------------------------------------------------------------------
__device__ float amper_point(const float* __restrict__ Hxb,
                             const float* __restrict__ Hyb,
                             int i, int j, const MCoef& m)
{
    float s1 = 0.0f, s2 = 0.0f;
    bool irow = (i >= 2 && i <= NN - 2);
    bool jcol = (j >= 2 && j <= NN - 2);

#define HYv(r, c) Hyb[(r) * HYW + (c)]
#define HXv(r, c) Hxb[(r) * HXW + (c)]
    if (irow && jcol) {
        s1 += m.M00 * HYv(i - 2, j - 2) + m.M20 * HYv(i - 2, j);
        s1 += m.M01 * HYv(i - 1, j - 2) + m.M11 * HYv(i - 1, j - 1) + m.M21 * HYv(i - 1, j);
        s1 += m.M02 * HYv(i,     j - 2) + m.M22 * HYv(i,     j);
        s1 += m.M03 * HYv(i + 1, j - 2) + m.M23 * HYv(i + 1, j);
        s2 += m.M00 * HXv(i - 2, j - 2) + m.M01 * HXv(i - 2, j - 1)
            + m.M02 * HXv(i - 2, j)     + m.M03 * HXv(i - 2, j + 1);
        s2 += m.M11 * HXv(i - 1, j - 1);
        s2 += m.M20 * HXv(i,     j - 2) + m.M21 * HXv(i,     j - 1)
            + m.M22 * HXv(i,     j)     + m.M23 * HXv(i,     j + 1);
    }
    if (i >= 1 && j <= NN - 5) {
        s1 += KF0 * HYv(i - 1, j)     + KF1 * HYv(i - 1, j + 1)
            + KF2 * HYv(i - 1, j + 2) + KF3 * HYv(i - 1, j + 3);
    }
    if (i <= NN - 1 && j >= 5) {
        s1 += KB0 * HYv(i, j - 5) + KB1 * HYv(i, j - 4)
            + KB2 * HYv(i, j - 3) + KB3 * HYv(i, j - 2);
    }
    if (irow && j >= 1 && j <= 2) {
        s1 += -HYv(i - 1, j - 1) + 3.0f * HYv(i - 1, j)
              - 3.0f * HYv(i - 1, j + 1) + HYv(i - 1, j + 2);
    }
    if (irow && j >= NN - 2 && j <= NN - 1) {
        s1 += HYv(i, j - 4) - 3.0f * HYv(i, j - 3)
            + 3.0f * HYv(i, j - 2) - HYv(i, j - 1);
    }
    if (j >= 1 && i <= NN - 5) {
        s2 += KF0 * HXv(i, j - 1)     + KF1 * HXv(i + 1, j - 1)
            + KF2 * HXv(i + 2, j - 1) + KF3 * HXv(i + 3, j - 1);
    }
    if (j <= NN - 1 && i >= 5) {
        s2 += KB0 * HXv(i - 5, j) + KB1 * HXv(i - 4, j)
            + KB2 * HXv(i - 3, j) + KB3 * HXv(i - 2, j);
    }
    if (jcol && i >= 1 && i <= 2) {
        s2 += -HXv(i - 1, j - 1) + 3.0f * HXv(i, j - 1)
              - 3.0f * HXv(i + 1, j - 1) + HXv(i + 2, j - 1);
    }
    if (jcol && i >= NN - 2 && i <= NN - 1) {
        s2 += HXv(i - 4, j) - 3.0f * HXv(i - 3, j)
            + 3.0f * HXv(i - 2, j) - HXv(i - 1, j);
    }
#undef HYv
#undef HXv
    return s1 - s2;
}

// ---------------------------------------------------------------------------
// Amper Hy section (rows i0-2 .. i0+2), 2 output rows. KY = skew of base.
// ---------------------------------------------------------------------------
template<int KY>
__device__ __forceinline__ void amper_hy_sec(const float* __restrict__ hy, int base,
                                             const MCoef& m, float cM21KF0, float cM02KB3,
                                             float* __restrict__ s1a, float* __restrict__ s1b)
{
    float Y0[6], Y1[9], Y2[12], Y3[9], Y4[6];
    load_win_k<6,  KY          >(hy, base, Y0);
    load_win_k<9,  (KY + 3) & 3>(hy, base + HYW, Y1);
    load_win_k<12, (KY + 3) & 3>(hy, base + 2 * HYW - 3, Y2);
    load_win_k<9,  (KY + 2) & 3>(hy, base + 3 * HYW - 3, Y3);
    load_win_k<6,  KY          >(hy, base + 4 * HYW, Y4);

    #pragma unroll
    for (int q = 0; q < 4; q++) {
        s1a[q] += m.M00 * Y0[q] + m.M20 * Y0[q + 2];
        s1a[q] += m.M01 * Y1[q] + m.M11 * Y1[q + 1] + cM21KF0 * Y1[q + 2]
                + KF1 * Y1[q + 3] + KF2 * Y1[q + 4] + KF3 * Y1[q + 5];
        s1b[q] += m.M00 * Y1[q] + m.M20 * Y1[q + 2];
        s1a[q] += KB0 * Y2[q] + KB1 * Y2[q + 1] + KB2 * Y2[q + 2]
                + cM02KB3 * Y2[q + 3] + m.M22 * Y2[q + 5];
        s1b[q] += m.M01 * Y2[q + 3] + m.M11 * Y2[q + 4] + cM21KF0 * Y2[q + 5]
                + KF1 * Y2[q + 6] + KF2 * Y2[q + 7] + KF3 * Y2[q + 8];
        s1a[q] += m.M03 * Y3[q + 3] + m.M23 * Y3[q + 5];
        s1b[q] += KB0 * Y3[q] + KB1 * Y3[q + 1] + KB2 * Y3[q + 2]
                + cM02KB3 * Y3[q + 3] + m.M22 * Y3[q + 5];
        s1b[q] += m.M03 * Y4[q] + m.M23 * Y4[q + 2];
    }
}

// ---------------------------------------------------------------------------
// Amper Hx section (rows i0-5 .. i0+4), 2 output rows. KX = skew of base.
// ---------------------------------------------------------------------------
template<int KX>
__device__ __forceinline__ void amper_hx_sec(const float* __restrict__ hx, int base,
                                             const MCoef& m, float cM21KF0, float cM02KB3,
                                             float* __restrict__ s2a, float* __restrict__ s2b)
{
    float X0[4], X1[4], X2[4], X3[7], X4[7], X5[7], X6[7], X7[4], X8[4], X9[4];
    load_win_k<4, KX          >(hx, base, X0);
    load_win_k<4, KX          >(hx, base + HXW, X1);
    load_win_k<4, KX          >(hx, base + 2 * HXW, X2);
    load_win_k<7, (KX + 2) & 3>(hx, base + 3 * HXW - 2, X3);
    load_win_k<7, (KX + 2) & 3>(hx, base + 4 * HXW - 2, X4);
    load_win_k<7, (KX + 2) & 3>(hx, base + 5 * HXW - 2, X5);
    load_win_k<7, (KX + 2) & 3>(hx, base + 6 * HXW - 2, X6);
    load_win_k<4, (KX + 3) & 3>(hx, base + 7 * HXW - 1, X7);
    load_win_k<4, (KX + 3) & 3>(hx, base + 8 * HXW - 1, X8);
    load_win_k<4, (KX + 3) & 3>(hx, base + 9 * HXW - 1, X9);

    #pragma unroll
    for (int q = 0; q < 4; q++) {
        s2a[q] += KB0 * X0[q] + KB1 * X1[q] + KB2 * X2[q];
        s2b[q] += KB0 * X1[q] + KB1 * X2[q];
        s2a[q] += m.M00 * X3[q] + m.M01 * X3[q + 1] + cM02KB3 * X3[q + 2] + m.M03 * X3[q + 3];
        s2b[q] += KB2 * X3[q + 2];
        s2a[q] += m.M11 * X4[q + 1];
        s2b[q] += m.M00 * X4[q] + m.M01 * X4[q + 1] + cM02KB3 * X4[q + 2] + m.M03 * X4[q + 3];
        s2a[q] += m.M20 * X5[q] + cM21KF0 * X5[q + 1] + m.M22 * X5[q + 2] + m.M23 * X5[q + 3];
        s2b[q] += m.M11 * X5[q + 1];
        s2a[q] += KF1 * X6[q + 1];
        s2b[q] += m.M20 * X6[q] + cM21KF0 * X6[q + 1] + m.M22 * X6[q + 2] + m.M23 * X6[q + 3];
        s2a[q] += KF2 * X7[q] + KF3 * X8[q];
        s2b[q] += KF1 * X7[q] + KF2 * X8[q] + KF3 * X9[q];
    }
}

// ---------------------------------------------------------------------------
// Amper border body (cold path, noinline; spills are fine).
// ---------------------------------------------------------------------------
#define AB_R0 12294               // 6*2049
#define AB_R1 10245               // 5*2049
#define AB_R2 16304               // 2038*8
#define AB_R3 22418               // 2038*11
#define AB_N  (AB_R0 + AB_R1 + AB_R2 + AB_R3)   // 61261
#define AB_YBLKS ((AB_N + 2047) / 2048)         // 30

__device__ __noinline__ void amper_border_body(
    int idx, int b,
    const float* __restrict__ e_base,  int e_off,
    const float* __restrict__ hx_base, int hx_off,
    const float* __restrict__ hy_base, int hy_off,
    float* __restrict__ out_base,      int eo_off)
{
    if (idx >= AB_N) return;
    int i, j;
    if (idx < AB_R0) { i = idx / EW; j = idx % EW; }
    else if (idx < AB_R0 + AB_R1) { int r = idx - AB_R0; i = 2044 + r / EW; j = r % EW; }
    else if (idx < AB_R0 + AB_R1 + AB_R2) { int r = idx - (AB_R0 + AB_R1); i = 6 + r / 8; j = r % 8; }
    else { int r = idx - (AB_R0 + AB_R1 + AB_R2); i = 6 + r / 11; j = 2038 + r % 11; }

    int i0 = i & ~1;
    int s = (eo_off + b * EN + i0 * EW) & 3;
    int js = j - ((j + s) & 3);
    if (i0 >= 5 && i0 <= NN - 6 && js >= 5 && js <= NN - 8) return;  // main covered it

    MCoef m = load_M();
    const float* Hxb = hx_base + hx_off + b * HXN;
    const float* Hyb = hy_base + hy_off + b * HYN;
    float d = amper_point(Hxb, Hyb, i, j, m);
    out_base[eo_off + b * EN + i * EW + j] =
        e_base[e_off + b * EN + i * EW + j] + CFLF * d;
}

// ---------------------------------------------------------------------------
// Amper: main interior blocks (y < 256) + border blocks (y >= 256).
// ---------------------------------------------------------------------------
__global__ __launch_bounds__(128, 10)
void k_amper(const float* __restrict__ e_base,  int e_off,
             const float* __restrict__ hx_base, int hx_off,
             const float* __restrict__ hy_base, int hy_off,
             float* __restrict__ out_base,      int eo_off)
{
    int b = blockIdx.z;
    if (blockIdx.y >= 256) {
        int idx = ((blockIdx.y - 256) * 16 + blockIdx.x) * 128
                + threadIdx.y * 32 + threadIdx.x;
        amper_border_body(idx, b, e_base, e_off, hx_base, hx_off,
                          hy_base, hy_off, out_base, eo_off);
        return;
    }

    int t  = blockIdx.x * 32 + threadIdx.x;
    int i0 = (blockIdx.y * 4 + threadIdx.y) * 2;
    if (i0 < 5 || i0 > NN - 6) return;        // warp-uniform

    const int erow0 = eo_off + b * EN + i0 * EW;
    const int s = erow0 & 3;
    const int j = 4 * t - s;
    const bool fast = (j >= 5) && (j <= NN - 8);
    const unsigned bal = __ballot_sync(0xffffffffu, fast);
    if (!fast) return;

    MCoef m = load_M();
    const float cM21KF0 = g_coef[9];
    const float cM02KB3 = g_coef[10];

    const int xb = hx_off + b * HXN;
    const int yb = hy_off + b * HYN;

    float s1a[4] = {0, 0, 0, 0}, s1b[4] = {0, 0, 0, 0};
    float s2a[4] = {0, 0, 0, 0}, s2b[4] = {0, 0, 0, 0};

    const int ybase = yb + (i0 - 2) * HYW + (j - 2);
    switch (ybase & 3) {
        case 0: amper_hy_sec<0>(hy_base, ybase, m, cM21KF0, cM02KB3, s1a, s1b); break;
        case 1: amper_hy_sec<1>(hy_base, ybase, m, cM21KF0, cM02KB3, s1a, s1b); break;
        case 2: amper_hy_sec<2>(hy_base, ybase, m, cM21KF0, cM02KB3, s1a, s1b); break;
        case 3: amper_hy_sec<3>(hy_base, ybase, m, cM21KF0, cM02KB3, s1a, s1b); break;
    }

    const int xbase = xb + (i0 - 5) * HXW + j;
    switch (xbase & 3) {
        case 0: amper_hx_sec<0>(hx_base, xbase, m, cM21KF0, cM02KB3, s2a, s2b); break;
        case 1: amper_hx_sec<1>(hx_base, xbase, m, cM21KF0, cM02KB3, s2a, s2b); break;
        case 2: amper_hx_sec<2>(hx_base, xbase, m, cM21KF0, cM02KB3, s2a, s2b); break;
        case 3: amper_hx_sec<3>(hx_base, xbase, m, cM21KF0, cM02KB3, s2a, s2b); break;
    }

    // E input loaded LATE to minimize live registers through the stencil body.
    float E0[4], E1[4];
    const int eidx = e_off + b * EN + i0 * EW + j;
    switch (eidx & 3) {
        case 0: load_win_k<4, 0>(e_base, eidx, E0); load_win_k<4, 1>(e_base, eidx + EW, E1); break;
        case 1: load_win_k<4, 1>(e_base, eidx, E0); load_win_k<4, 2>(e_base, eidx + EW, E1); break;
        case 2: load_win_k<4, 2>(e_base, eidx, E0); load_win_k<4, 3>(e_base, eidx + EW, E1); break;
        case 3: load_win_k<4, 3>(e_base, eidx, E0); load_win_k<4, 0>(e_base, eidx + EW, E1); break;
    }

    float4 w;
    w.x = E0[0] + CFLF * (s1a[0] - s2a[0]);
    w.y = E0[1] + CFLF * (s1a[1] - s2a[1]);
    w.z = E0[2] + CFLF * (s1a[2] - s2a[2]);
    w.w = E0[3] + CFLF * (s1a[3] - s2a[3]);
    *reinterpret_cast<float4*>(out_base + erow0 + j) = w;   // aligned by construction

    float r1_0 = E1[0] + CFLF * (s1b[0] - s2b[0]);
    float r1_1 = E1[1] + CFLF * (s1b[1] - s2b[1]);
    float r1_2 = E1[2] + CFLF * (s1b[2] - s2b[2]);
    float r1_3 = E1[3] + CFLF * (s1b[3] - s2b[3]);
    if (bal == 0xffffffffu) {
        warp_store128(out_base, erow0 + EW + j, r1_0, r1_1, r1_2, r1_3);
    } else {
        float* p1 = out_base + erow0 + EW + j;
        p1[0] = r1_0; p1[1] = r1_1; p1[2] = r1_2; p1[3] = r1_3;
    }
}

// ---------------------------------------------------------------------------
// Generic faraday point helpers
// ---------------------------------------------------------------------------
__device__ float faraday_s3(const float* __restrict__ Eb, int i, int j, const MCoef& m)
{
#define Ev(r, c) Eb[(r) * EW + (c)]
    float s3 = 0.0f;
    if (j >= 1 && j <= NN - 2) {
        s3 += m.M00 * Ev(i,     j - 1) + m.M01 * Ev(i,     j)
            + m.M02 * Ev(i,     j + 1) + m.M03 * Ev(i,     j + 2);
        s3 += m.M11 * Ev(i + 1, j);
        s3 += m.M20 * Ev(i + 2, j - 1) + m.M21 * Ev(i + 2, j)
            + m.M22 * Ev(i + 2, j + 1) + m.M23 * Ev(i + 2, j + 2);
    }
    if (i <= NN - 4)
        s3 += -1.5f * Ev(i + 1, j) + 2.0f * Ev(i + 2, j) - 0.5f * Ev(i + 3, j);
    if (i >= 2)
        s3 += 0.5f * Ev(i - 1, j + 1) - 2.0f * Ev(i, j + 1) + 1.5f * Ev(i + 1, j + 1);
#undef Ev
    return s3;
}

__device__ float faraday_s4(const float* __restrict__ Eb, int i, int j, const MCoef& m)
{
#define Ev(r, c) Eb[(r) * EW + (c)]
    float s4 = 0.0f;
    if (i >= 1 && i <= NN - 2) {
        s4 += m.M00 * Ev(i - 1, j) + m.M20 * Ev(i - 1, j + 2);
        s4 += m.M01 * Ev(i,     j) + m.M11 * Ev(i, j + 1) + m.M21 * Ev(i, j + 2);
        s4 += m.M02 * Ev(i + 1, j) + m.M22 * Ev(i + 1, j + 2);
        s4 += m.M03 * Ev(i + 2, j) + m.M23 * Ev(i + 2, j + 2);
    }
    if (j <= NN - 4)
        s4 += -1.5f * Ev(i, j + 1) + 2.0f * Ev(i, j + 2) - 0.5f * Ev(i, j + 3);
    if (j >= 2)
        s4 += 0.5f * Ev(i + 1, j - 1) - 2.0f * Ev(i + 1, j) + 1.5f * Ev(i + 1, j + 1);
#undef Ev
    return s4;
}

// ---------------------------------------------------------------------------
// Faraday E section (rows i0-1 .. i0+4), 2 output rows. KE = skew of base.
// ---------------------------------------------------------------------------
template<int KE>
__device__ __forceinline__ void faraday_e_sec(const float* __restrict__ e, int base,
                                              const MCoef& m, float cA, float cB, float cC,
                                              float* __restrict__ s3a, float* __restrict__ s3b,
                                              float* __restrict__ s4a, float* __restrict__ s4b)
{
    float W0[6], W1[8], W2[8], W3[7], W4[7], W5[4];
    load_win_k<6, KE          >(e, base, W0);
    load_win_k<8, KE          >(e, base + EW - 1, W1);
    load_win_k<8, (KE + 1) & 3>(e, base + 2 * EW - 1, W2);
    load_win_k<7, (KE + 2) & 3>(e, base + 3 * EW - 1, W3);
    load_win_k<7, (KE + 3) & 3>(e, base + 4 * EW - 1, W4);
    load_win_k<4, (KE + 1) & 3>(e, base + 5 * EW, W5);

    #pragma unroll
    for (int q = 0; q < 4; q++) {
        s3a[q] += 0.5f * W0[q + 1];
        s4a[q] += m.M00 * W0[q] + m.M20 * W0[q + 2];
        s3a[q] += m.M00 * W1[q] + m.M01 * W1[q + 1] + cA * W1[q + 2] + m.M03 * W1[q + 3];
        s4a[q] += m.M01 * W1[q + 1] + cB * W1[q + 2] + cC * W1[q + 3] - 0.5f * W1[q + 4];
        s3b[q] += 0.5f * W1[q + 2];
        s4b[q] += m.M00 * W1[q + 1] + m.M20 * W1[q + 3];
        s3a[q] += cB * W2[q + 1] + 1.5f * W2[q + 2];
        s4a[q] += 0.5f * W2[q] + cA * W2[q + 1] + 1.5f * W2[q + 2] + m.M22 * W2[q + 3];
        s3b[q] += m.M00 * W2[q] + m.M01 * W2[q + 1] + cA * W2[q + 2] + m.M03 * W2[q + 3];
        s4b[q] += m.M01 * W2[q + 1] + cB * W2[q + 2] + cC * W2[q + 3] - 0.5f * W2[q + 4];
        s3a[q] += m.M20 * W3[q] + cC * W3[q + 1] + m.M22 * W3[q + 2] + m.M23 * W3[q + 3];
        s4a[q] += m.M03 * W3[q + 1] + m.M23 * W3[q + 3];
        s3b[q] += cB * W3[q + 1] + 1.5f * W3[q + 2];
        s4b[q] += 0.5f * W3[q] + cA * W3[q + 1] + 1.5f * W3[q + 2] + m.M22 * W3[q + 3];
        s3a[q] += -0.5f * W4[q + 1];
        s3b[q] += m.M20 * W4[q] + cC * W4[q + 1] + m.M22 * W4[q + 2] + m.M23 * W4[q + 3];
        s4b[q] += m.M03 * W4[q + 1] + m.M23 * W4[q + 3];
        s3b[q] += -0.5f * W5[q];
    }
}

// ---------------------------------------------------------------------------
// Faraday border body (cold path, noinline).
// ---------------------------------------------------------------------------
#define FB_R0 4096                // 2*2048
#define FB_R1 8192                // 4*2048
#define FB_R2 10210               // 2042*5
#define FB_R3 18378               // 2042*9
#define FB_N  (FB_R0 + FB_R1 + FB_R2 + FB_R3)   // 40876
#define FB_YBLKS ((FB_N + 2047) / 2048)         // 20

__device__ __noinline__ void faraday_border_body(
    int idx, int b,
    const float* __restrict__ e_base,  int e_off,
    const float* __restrict__ hx_base, int hx_off,
    const float* __restrict__ hy_base, int hy_off,
    float* __restrict__ out_base,      int hxo_off, int hyo_off)
{
    if (idx >= FB_N) return;
    int i, j;
    if (idx < FB_R0) { i = idx / NN; j = idx % NN; }
    else if (idx < FB_R0 + FB_R1) { int r = idx - FB_R0; i = 2044 + r / NN; j = r % NN; }
    else if (idx < FB_R0 + FB_R1 + FB_R2) { int r = idx - (FB_R0 + FB_R1); i = 2 + r / 5; j = r % 5; }
    else { int r = idx - (FB_R0 + FB_R1 + FB_R2); i = 2 + r / 9; j = 2039 + r % 9; }

    int i0 = i & ~1;
    int sF = hxo_off & 3;
    int js = j - ((j + sF) & 3);
    if (i0 >= 2 && i0 <= NN - 5 && js >= 2 && js <= NN - 7) return;  // main covered it

    MCoef m = load_M();
    const float* Eb  = e_base + e_off + b * EN;
    const float* Hxb = hx_base + hx_off + b * HXN;
    const float* Hyb = hy_base + hy_off + b * HYN;
    float* Hxob = out_base + hxo_off + b * HXN;
    float* Hyob = out_base + hyo_off + b * HYN;

    if (i < HXH && j < HXW) {
        float s3 = faraday_s3(Eb, i, j, m);
        Hxob[i * HXW + j] = Hxb[i * HXW + j] - CFLF * s3;
    }
    if (i < HYH && j < HYW) {
        float s4 = faraday_s4(Eb, i, j, m);
        Hyob[i * HYW + j] = Hyb[i * HYW + j] + CFLF * s4;
    }
}

// ---------------------------------------------------------------------------
// Faraday: main interior blocks (y < 256) + border blocks (y >= 256).
// ---------------------------------------------------------------------------
__global__ __launch_bounds__(128, 10)
void k_faraday(const float* __restrict__ e_base,  int e_off,
               const float* __restrict__ hx_base, int hx_off,
               const float* __restrict__ hy_base, int hy_off,
               float* __restrict__ out_base,      int hxo_off, int hyo_off)
{
    int b = blockIdx.z;
    if (blockIdx.y >= 256) {
        int idx = ((blockIdx.y - 256) * 16 + blockIdx.x) * 128
                + threadIdx.y * 32 + threadIdx.x;
        faraday_border_body(idx, b, e_base, e_off, hx_base, hx_off,
                            hy_base, hy_off, out_base, hxo_off, hyo_off);
        return;
    }

    int t  = blockIdx.x * 32 + threadIdx.x;
    int i0 = (blockIdx.y * 4 + threadIdx.y) * 2;
    if (i0 < 2 || i0 > NN - 5) return;        // warp-uniform

    const int sF = hxo_off & 3;
    const int j = 4 * t - sF;
    const bool fast = (j >= 2) && (j <= NN - 7);
    const unsigned bal = __ballot_sync(0xffffffffu, fast);
    if (!fast) return;

    MCoef m = load_M();
    const float cA = g_coef[11];
    const float cB = g_coef[12];
    const float cC = g_coef[13];

    const int eb = e_off + b * EN;
    const int xb = hx_off + b * HXN;
    const int yb = hy_off + b * HYN;

    float s3a[4] = {0, 0, 0, 0}, s3b[4] = {0, 0, 0, 0};
    float s4a[4] = {0, 0, 0, 0}, s4b[4] = {0, 0, 0, 0};

    const int ebase = eb + (i0 - 1) * EW + j;
    switch (ebase & 3) {
        case 0: faraday_e_sec<0>(e_base, ebase, m, cA, cB, cC, s3a, s3b, s4a, s4b); break;
        case 1: faraday_e_sec<1>(e_base, ebase, m, cA, cB, cC, s3a, s3b, s4a, s4b); break;
        case 2: faraday_e_sec<2>(e_base, ebase, m, cA, cB, cC, s3a, s3b, s4a, s4b); break;
        case 3: faraday_e_sec<3>(e_base, ebase, m, cA, cB, cC, s3a, s3b, s4a, s4b); break;
    }

    // H inputs loaded LATE to minimize live registers through the E section.
    float hx0[4], hx1[4], hy0[4], hy1[4];
    const int hxidx = xb + i0 * HXW + j;      // HXW == 0 mod 4
    switch (hxidx & 3) {
        case 0: load_win_k<4, 0>(hx_base, hxidx, hx0); load_win_k<4, 0>(hx_base, hxidx + HXW, hx1); break;
        case 1: load_win_k<4, 1>(hx_base, hxidx, hx0); load_win_k<4, 1>(hx_base, hxidx + HXW, hx1); break;
        case 2: load_win_k<4, 2>(hx_base, hxidx, hx0); load_win_k<4, 2>(hx_base, hxidx + HXW, hx1); break;
        case 3: load_win_k<4, 3>(hx_base, hxidx, hx0); load_win_k<4, 3>(hx_base, hxidx + HXW, hx1); break;
    }
    const int hyidx = yb + i0 * HYW + j;      // HYW == 3 mod 4
    switch (hyidx & 3) {
        case 0: load_win_k<4, 0>(hy_base, hyidx, hy0); load_win_k<4, 3>(hy_base, hyidx + HYW, hy1); break;
        case 1: load_win_k<4, 1>(hy_base, hyidx, hy0); load_win_k<4, 0>(hy_base, hyidx + HYW, hy1); break;
        case 2: load_win_k<4, 2>(hy_base, hyidx, hy0); load_win_k<4, 1>(hy_base, hyidx + HYW, hy1); break;
        case 3: load_win_k<4, 3>(hy_base, hyidx, hy0); load_win_k<4, 2>(hy_base, hyidx + HYW, hy1); break;
    }

    float4 w;
    w.x = hx0[0] - CFLF * s3a[0];
    w.y = hx0[1] - CFLF * s3a[1];
    w.z = hx0[2] - CFLF * s3a[2];
    w.w = hx0[3] - CFLF * s3a[3];
    *reinterpret_cast<float4*>(out_base + hxo_off + b * HXN + i0 * HXW + j) = w;
    w.x = hx1[0] - CFLF * s3b[0];
    w.y = hx1[1] - CFLF * s3b[1];
    w.z = hx1[2] - CFLF * s3b[2];
    w.w = hx1[3] - CFLF * s3b[3];
    *reinterpret_cast<float4*>(out_base + hxo_off + b * HXN + (i0 + 1) * HXW + j) = w;

    float wy00 = hy0[0] + CFLF * s4a[0];
    float wy01 = hy0[1] + CFLF * s4a[1];
    float wy02 = hy0[2] + CFLF * s4a[2];
    float wy03 = hy0[3] + CFLF * s4a[3];
    float wy10 = hy1[0] + CFLF * s4b[0];
    float wy11 = hy1[1] + CFLF * s4b[1];
    float wy12 = hy1[2] + CFLF * s4b[2];
    float wy13 = hy1[3] + CFLF * s4b[3];
    if (bal == 0xffffffffu) {
        warp_store128(out_base, hyo_off + b * HYN + i0 * HYW + j, wy00, wy01, wy02, wy03);
        warp_store128(out_base, hyo_off + b * HYN + (i0 + 1) * HYW + j, wy10, wy11, wy12, wy13);
    } else {
        float* p0 = out_base + hyo_off + b * HYN + i0 * HYW + j;
        float* p1 = p0 + HYW;
        p0[0] = wy00; p0[1] = wy01; p0[2] = wy02; p0[3] = wy03;
        p1[0] = wy10; p1[1] = wy11; p1[2] = wy12; p1[3] = wy13;
    }
}

// ---------------------------------------------------------------------------
extern "C" void kernel_launch(void* const* d_in, const int* in_sizes, int n_in,
                              void* d_out, int out_size)
{
    const float* sb = (const float*)d_in[3];
    const float* sd = (const float*)d_in[4];
    const float* sg = (const float*)d_in[5];
    float* out = (float*)d_out;

    const float* e_base  = (const float*)d_in[0]; int e_off  = 0;
    const float* hx_base = (const float*)d_in[1]; int hx_off = 0;
    const float* hy_base = (const float*)d_in[2]; int hy_off = 0;

    const int STEP = BB * (EN + HXN + HYN);

    k_setup<<<1, 1>>>(sb, sd, sg);

    dim3 blk(32, 4, 1);
    dim3 gA(16, 256 + AB_YBLKS, BB);          // main rows + amper border band
    dim3 gF(16, 256 + FB_YBLKS, BB);          // main rows + faraday border band

    for (int k = 0; k < 3; k++) {
        int eo_off  = k * STEP;
        int hxo_off = eo_off + BB * EN;
        int hyo_off = hxo_off + BB * HXN;

        k_amper<<<gA, blk>>>(e_base, e_off, hx_base, hx_off, hy_base, hy_off,
                             out, eo_off);
        k_faraday<<<gF, blk>>>(out, eo_off, hx_base, hx_off, hy_base, hy_off,
                               out, hxo_off, hyo_off);

        e_base = out;  e_off  = eo_off;
        hx_base = out; hx_off = hxo_off;
        hy_base = out; hy_off = hyo_off;
    }
}